// round 3
// baseline (speedup 1.0000x reference)
#include <cuda_runtime.h>
#include <cstdint>
#include <cstdio>

// ---------------- problem dims ----------------
#define E_    1152
#define H_    1280
#define O_    2432
#define DL    4
#define HD_   64
#define NH_   20
#define NQ_   64
#define TIN_  320
#define FF_   5120
#define B_    32
#define N_    577
#define NKV   641              // N_ + NQ_
#define MH    (B_*N_)          // 18464
#define MC    (B_*NKV)         // 20512
#define ML    (B_*NQ_)         // 2048

// ---------------- scratch (device globals; no allocation) ----------------
__device__ float g_tproj[B_*TIN_];
__device__ float g_t1[B_*H_];
__device__ float g_temb[B_*H_];
__device__ float g_tsilu[B_*H_];
__device__ float g_h[(size_t)MH*H_];
__device__ float g_cat[(size_t)MC*H_];
__device__ float g_kv[(size_t)MC*2*H_];
__device__ float g_lat[(size_t)ML*H_];
__device__ float g_lm[(size_t)ML*H_];
__device__ float g_q[(size_t)ML*H_];
__device__ float g_att[(size_t)ML*H_];
__device__ float g_ff[(size_t)ML*FF_];
__device__ float g_emb[B_*4*H_];
__device__ float g_obuf[(size_t)ML*O_];

// ---------------- epilogue modes ----------------
#define MODE_NONE      0
#define MODE_BIAS      1
#define MODE_BIAS_TEMB 2   // + bias[c] + extra[(r/577)*N + c]
#define MODE_BIAS_SILU 3
#define MODE_GELU      4
#define MODE_RES       5   // + extra[r*N + c]

// ---------------- generic fp32 SGEMM: C[M,N] = A[M,K] @ B[K,N] (+epilogue) ---
// Requirements: K % 8 == 0, N % 128 == 0. M arbitrary (guarded).
__global__ __launch_bounds__(256, 2)
void sgemm_kernel(const float* __restrict__ A, const float* __restrict__ Bm,
                  float* __restrict__ C, int M, int N, int K,
                  const float* __restrict__ bias, const float* __restrict__ extra,
                  int mode)
{
    __shared__ float As[2][8][128];
    __shared__ float Bs[2][8][128];

    const int tid  = threadIdx.x;
    const int row0 = blockIdx.y * 128;
    const int col0 = blockIdx.x * 128;

    const int ar = tid >> 1;            // 0..127
    const int ac = (tid & 1) << 2;      // 0 or 4
    const int br = tid >> 5;            // 0..7
    const int bc = (tid & 31) << 2;     // 0..124

    const int ty = tid >> 4;            // 0..15
    const int tx = tid & 15;            // 0..15

    float acc[8][8];
    #pragma unroll
    for (int i = 0; i < 8; i++)
        #pragma unroll
        for (int j = 0; j < 8; j++) acc[i][j] = 0.f;

    const bool arow_ok = (row0 + ar) < M;
    const float* Aptr = A + (size_t)(row0 + ar) * K + ac;
    const float* Bptr = Bm + (size_t)br * N + col0 + bc;

    // load tile 0
    {
        float4 a = arow_ok ? *(const float4*)Aptr : make_float4(0.f,0.f,0.f,0.f);
        float4 b = *(const float4*)Bptr;
        As[0][ac+0][ar] = a.x; As[0][ac+1][ar] = a.y;
        As[0][ac+2][ar] = a.z; As[0][ac+3][ar] = a.w;
        *(float4*)&Bs[0][br][bc] = b;
    }
    __syncthreads();

    int cur = 0;
    for (int kt = 0; kt < K; kt += 8) {
        const bool has_next = (kt + 8) < K;
        float4 an, bn;
        if (has_next) {
            an = arow_ok ? *(const float4*)(Aptr + kt + 8) : make_float4(0.f,0.f,0.f,0.f);
            bn = *(const float4*)(Bptr + (size_t)(kt + 8) * N);
        }
        #pragma unroll
        for (int k = 0; k < 8; k++) {
            float ra[8], rb[8];
            float4 t0 = *(const float4*)&As[cur][k][ty*8];
            float4 t1 = *(const float4*)&As[cur][k][ty*8+4];
            float4 u0 = *(const float4*)&Bs[cur][k][tx*8];
            float4 u1 = *(const float4*)&Bs[cur][k][tx*8+4];
            ra[0]=t0.x; ra[1]=t0.y; ra[2]=t0.z; ra[3]=t0.w;
            ra[4]=t1.x; ra[5]=t1.y; ra[6]=t1.z; ra[7]=t1.w;
            rb[0]=u0.x; rb[1]=u0.y; rb[2]=u0.z; rb[3]=u0.w;
            rb[4]=u1.x; rb[5]=u1.y; rb[6]=u1.z; rb[7]=u1.w;
            #pragma unroll
            for (int i = 0; i < 8; i++)
                #pragma unroll
                for (int j = 0; j < 8; j++)
                    acc[i][j] = fmaf(ra[i], rb[j], acc[i][j]);
        }
        if (has_next) {
            As[cur^1][ac+0][ar] = an.x; As[cur^1][ac+1][ar] = an.y;
            As[cur^1][ac+2][ar] = an.z; As[cur^1][ac+3][ar] = an.w;
            *(float4*)&Bs[cur^1][br][bc] = bn;
            __syncthreads();
            cur ^= 1;
        }
    }

    // epilogue
    #pragma unroll
    for (int i = 0; i < 8; i++) {
        const int r = row0 + ty*8 + i;
        if (r >= M) continue;
        #pragma unroll
        for (int j = 0; j < 8; j++) {
            const int c = col0 + tx*8 + j;
            float v = acc[i][j];
            if (mode == MODE_BIAS) {
                v += bias[c];
            } else if (mode == MODE_BIAS_TEMB) {
                v += bias[c] + extra[(size_t)(r / N_) * N + c];
            } else if (mode == MODE_BIAS_SILU) {
                float s = v + bias[c];
                v = s / (1.0f + expf(-s));
            } else if (mode == MODE_GELU) {
                v = 0.5f * v * (1.0f + erff(v * 0.70710678118654752f));
            } else if (mode == MODE_RES) {
                v += extra[(size_t)r * N + c];
            }
            C[(size_t)r * N + c] = v;
        }
    }
}

// ---------------- fused attention: one block per (b, head) ----------------
// Q[b,l,h*64+d] from g_q, K/V from g_kv (K = cols [0,1280), V = cols [1280,2560)).
// scores (64x704 padded) + softmax + AV, output to g_att.
#define JPAD   704               // 11 tiles of 64
#define SSTR   68                // padded row stride (floats), 16B-aligned units
#define SMEM_ATTN ((JPAD*SSTR + 64*SSTR + 64*SSTR + 64) * 4)

__global__ __launch_bounds__(256, 1)
void attn_kernel(const float* __restrict__ Q, const float* __restrict__ KV,
                 float* __restrict__ Ot)
{
    extern __shared__ float sm[];
    float* S    = sm;                        // [JPAD][SSTR]  scores^T : S[j][l]
    float* Qs   = S  + JPAD*SSTR;            // [64][SSTR]    q^T : Qs[d][l]
    float* Ts   = Qs + 64*SSTR;              // [64][SSTR]    K^T tile / V tile
    float* rinv = Ts + 64*SSTR;              // [64] 1/rowsum

    const int tid = threadIdx.x;
    const int b   = blockIdx.x / NH_;
    const int h   = blockIdx.x % NH_;

    const float* qbase = Q  + ((size_t)b * NQ_) * H_ + h * HD_;
    const float* kbase = KV + ((size_t)b * NKV) * (2*H_) + h * HD_;
    const float* vbase = kbase + H_;

    // load Q transposed: Qs[d][l]
    #pragma unroll
    for (int r = 0; r < 16; r++) {
        int idx = tid + r * 256;             // 0..4095
        int l = idx >> 6, d = idx & 63;
        Qs[d*SSTR + l] = qbase[(size_t)l * H_ + d];
    }

    const int lt = tid >> 4;   // 0..15 (l groups of 4)
    const int c4 = tid & 15;   // 0..15 (j or d groups of 4)

    // ---- phase 1: scores ----
    for (int t = 0; t < 11; t++) {
        const int jbase = t * 64;
        #pragma unroll
        for (int r = 0; r < 16; r++) {
            int idx = tid + r * 256;
            int jj = idx >> 6, d = idx & 63;
            int j = jbase + jj;
            Ts[d*SSTR + jj] = (j < NKV) ? kbase[(size_t)j * (2*H_) + d] : 0.f;
        }
        __syncthreads();

        float acc[4][4];
        #pragma unroll
        for (int i = 0; i < 4; i++)
            #pragma unroll
            for (int j = 0; j < 4; j++) acc[i][j] = 0.f;

        #pragma unroll 8
        for (int d = 0; d < 64; d++) {
            float4 q4 = *(const float4*)&Qs[d*SSTR + lt*4];
            float4 k4 = *(const float4*)&Ts[d*SSTR + c4*4];
            float qa[4] = {q4.x, q4.y, q4.z, q4.w};
            float ka[4] = {k4.x, k4.y, k4.z, k4.w};
            #pragma unroll
            for (int i = 0; i < 4; i++)
                #pragma unroll
                for (int j = 0; j < 4; j++)
                    acc[i][j] = fmaf(qa[i], ka[j], acc[i][j]);
        }
        #pragma unroll
        for (int jj = 0; jj < 4; jj++) {
            const int j = jbase + c4*4 + jj;
            float4 w;
            if (j < NKV) {
                w.x = acc[0][jj] * 0.125f; w.y = acc[1][jj] * 0.125f;
                w.z = acc[2][jj] * 0.125f; w.w = acc[3][jj] * 0.125f;
            } else {
                w.x = w.y = w.z = w.w = -1e30f;
            }
            *(float4*)&S[(size_t)j*SSTR + lt*4] = w;
        }
        __syncthreads();
    }

    // ---- phase 2: softmax over j per row l (4 lanes per row) ----
    {
        const int l   = tid >> 2;
        const int sub = tid & 3;
        float m = -1e30f;
        for (int j = sub; j < JPAD; j += 4) m = fmaxf(m, S[j*SSTR + l]);
        m = fmaxf(m, __shfl_xor_sync(0xffffffffu, m, 1));
        m = fmaxf(m, __shfl_xor_sync(0xffffffffu, m, 2));
        float ssum = 0.f;
        for (int j = sub; j < JPAD; j += 4) {
            float e = __expf(S[j*SSTR + l] - m);
            S[j*SSTR + l] = e;
            ssum += e;
        }
        ssum += __shfl_xor_sync(0xffffffffu, ssum, 1);
        ssum += __shfl_xor_sync(0xffffffffu, ssum, 2);
        if (sub == 0) rinv[l] = 1.0f / ssum;
    }
    __syncthreads();

    // ---- phase 3: att = P @ V ----
    float oacc[4][4];
    #pragma unroll
    for (int i = 0; i < 4; i++)
        #pragma unroll
        for (int j = 0; j < 4; j++) oacc[i][j] = 0.f;

    for (int t = 0; t < 11; t++) {
        const int jbase = t * 64;
        #pragma unroll
        for (int r = 0; r < 16; r++) {
            int idx = tid + r * 256;
            int jj = idx >> 6, d = idx & 63;
            int j = jbase + jj;
            Ts[jj*SSTR + d] = (j < NKV) ? vbase[(size_t)j * (2*H_) + d] : 0.f;
        }
        __syncthreads();
        #pragma unroll 8
        for (int jj = 0; jj < 64; jj++) {
            float4 p4 = *(const float4*)&S[(size_t)(jbase + jj)*SSTR + lt*4];
            float4 v4 = *(const float4*)&Ts[jj*SSTR + c4*4];
            float pa[4] = {p4.x, p4.y, p4.z, p4.w};
            float va[4] = {v4.x, v4.y, v4.z, v4.w};
            #pragma unroll
            for (int i = 0; i < 4; i++)
                #pragma unroll
                for (int j = 0; j < 4; j++)
                    oacc[i][j] = fmaf(pa[i], va[j], oacc[i][j]);
        }
        __syncthreads();
    }

    #pragma unroll
    for (int i = 0; i < 4; i++) {
        const int l = lt*4 + i;
        const float sc = rinv[l];
        #pragma unroll
        for (int j = 0; j < 4; j++) {
            const int d = c4*4 + j;
            Ot[((size_t)(b*NQ_ + l)) * H_ + h*HD_ + d] = oacc[i][j] * sc;
        }
    }
}

// ---------------- LayerNorm helpers ----------------
__device__ inline void block_reduce_2(float& s, float& s2) {
    __shared__ float red[16];
    const int lane = threadIdx.x & 31;
    const int w    = threadIdx.x >> 5;
    #pragma unroll
    for (int o = 16; o > 0; o >>= 1) {
        s  += __shfl_xor_sync(0xffffffffu, s,  o);
        s2 += __shfl_xor_sync(0xffffffffu, s2, o);
    }
    if (lane == 0) { red[w] = s; red[8 + w] = s2; }
    __syncthreads();
    if (threadIdx.x < 32) {
        s  = (lane < 8) ? red[lane]     : 0.f;
        s2 = (lane < 8) ? red[8 + lane] : 0.f;
        #pragma unroll
        for (int o = 4; o > 0; o >>= 1) {
            s  += __shfl_xor_sync(0xffffffffu, s,  o);
            s2 += __shfl_xor_sync(0xffffffffu, s2, o);
        }
        if (lane == 0) { red[0] = s; red[8] = s2; }
    }
    __syncthreads();
    s = red[0]; s2 = red[8];
}

// LN(h) rows -> cat rows [b*641 + n]
__global__ __launch_bounds__(256)
void ln_h_kernel(const float* __restrict__ in, const float* __restrict__ g,
                 const float* __restrict__ beta, float* __restrict__ cat)
{
    const int r = blockIdx.x;                 // 0..MH-1
    const int b = r / N_, n = r % N_;
    const float* x = in + (size_t)r * H_;
    float* out = cat + ((size_t)b * NKV + n) * H_;
    float s = 0.f, s2 = 0.f;
    for (int i = threadIdx.x; i < H_; i += 256) { float v = x[i]; s += v; s2 += v*v; }
    block_reduce_2(s, s2);
    const float mean = s * (1.0f / H_);
    const float var  = s2 * (1.0f / H_) - mean * mean;
    const float inv  = rsqrtf(var + 1e-5f);
    for (int i = threadIdx.x; i < H_; i += 256)
        out[i] = (x[i] - mean) * inv * g[i] + beta[i];
}

// LN(lat) with adaLN modulation: v = LN(v)*(1+sc)+sh -> out1 (+ optional cat rows)
__global__ __launch_bounds__(256)
void ln_mod_kernel(const float* __restrict__ in, const float* __restrict__ g,
                   const float* __restrict__ beta, const float* __restrict__ emb,
                   int shOff, int scOff, float* __restrict__ out1,
                   float* __restrict__ out2)
{
    const int r = blockIdx.x;                 // 0..ML-1
    const int b = r >> 6, qrow = r & 63;
    const float* x  = in + (size_t)r * H_;
    const float* sh = emb + (size_t)b * (4*H_) + shOff;
    const float* sc = emb + (size_t)b * (4*H_) + scOff;
    float s = 0.f, s2 = 0.f;
    for (int i = threadIdx.x; i < H_; i += 256) { float v = x[i]; s += v; s2 += v*v; }
    block_reduce_2(s, s2);
    const float mean = s * (1.0f / H_);
    const float var  = s2 * (1.0f / H_) - mean * mean;
    const float inv  = rsqrtf(var + 1e-5f);
    float* o1 = out1 + (size_t)r * H_;
    float* o2 = out2 ? out2 + ((size_t)b * NKV + N_ + qrow) * H_ : nullptr;
    for (int i = threadIdx.x; i < H_; i += 256) {
        float v = (x[i] - mean) * inv * g[i] + beta[i];
        v = v * (1.0f + sc[i]) + sh[i];
        o1[i] = v;
        if (o2) o2[i] = v;
    }
}

// final LN (rows of length O_)
__global__ __launch_bounds__(256)
void ln_out_kernel(const float* __restrict__ in, const float* __restrict__ g,
                   const float* __restrict__ beta, float* __restrict__ out)
{
    const int r = blockIdx.x;                 // 0..ML-1
    const float* x = in + (size_t)r * O_;
    float s = 0.f, s2 = 0.f;
    for (int i = threadIdx.x; i < O_; i += 256) { float v = x[i]; s += v; s2 += v*v; }
    block_reduce_2(s, s2);
    const float mean = s * (1.0f / O_);
    const float var  = s2 * (1.0f / O_) - mean * mean;
    const float inv  = rsqrtf(var + 1e-5f);
    float* o = out + (size_t)r * O_;
    for (int i = threadIdx.x; i < O_; i += 256)
        o[i] = (x[i] - mean) * inv * g[i] + beta[i];
}

// ---------------- small kernels ----------------
__global__ void time_proj_kernel(const float* __restrict__ t, float* __restrict__ tp)
{
    const int b = blockIdx.x;      // 0..31
    const int k = threadIdx.x;     // 0..159
    const float f = expf(-9.210340371976184f * (float)k / 160.0f);   // ln(10000)
    const float ang = t[b] * f;
    tp[b*TIN_ + k]        = cosf(ang);
    tp[b*TIN_ + 160 + k]  = sinf(ang);
}

__global__ void silu_kernel(const float* __restrict__ in, float* __restrict__ out, int n)
{
    int i = blockIdx.x * blockDim.x + threadIdx.x;
    if (i < n) { float v = in[i]; out[i] = v / (1.0f + expf(-v)); }
}

__global__ void lat_init_kernel(const float* __restrict__ l0, float* __restrict__ lat)
{
    int i = blockIdx.x * blockDim.x + threadIdx.x;
    if (i < ML * H_) lat[i] = l0[i % (NQ_ * H_)];
}

__global__ void copy_kernel(const float* __restrict__ in, float* __restrict__ out, int n)
{
    int i = blockIdx.x * blockDim.x + threadIdx.x;
    if (i < n) out[i] = in[i];
}

// ---------------- host driver ----------------
static inline void run_gemm(const float* A, const float* B, float* C,
                            int M, int N, int K,
                            const float* bias, const float* extra, int mode)
{
    dim3 grid(N / 128, (M + 127) / 128);
    sgemm_kernel<<<grid, 256>>>(A, B, C, M, N, K, bias, extra, mode);
}

extern "C" void kernel_launch(void* const* d_in, const int* in_sizes, int n_in,
                              void* d_out, int out_size)
{
    const float* x          = (const float*)d_in[0];
    const float* timestep   = (const float*)d_in[1];
    const float* latents0   = (const float*)d_in[2];
    const float* proj_in_W  = (const float*)d_in[3];
    const float* proj_in_b  = (const float*)d_in[4];
    const float* te1_W      = (const float*)d_in[5];
    const float* te1_b      = (const float*)d_in[6];
    const float* te2_W      = (const float*)d_in[7];
    const float* te2_b      = (const float*)d_in[8];
    const float* ln0_g      = (const float*)d_in[9];
    const float* ln0_b      = (const float*)d_in[10];
    const float* ln1_g      = (const float*)d_in[11];
    const float* ln1_b      = (const float*)d_in[12];
    const float* Wq         = (const float*)d_in[13];
    const float* Wkv        = (const float*)d_in[14];
    const float* Wo         = (const float*)d_in[15];
    const float* ada_W      = (const float*)d_in[16];
    const float* ada_b      = (const float*)d_in[17];
    const float* lnada_g    = (const float*)d_in[18];
    const float* lnada_b    = (const float*)d_in[19];
    const float* Wff1       = (const float*)d_in[20];
    const float* Wff2       = (const float*)d_in[21];
    const float* proj_out_W = (const float*)d_in[22];
    const float* proj_out_b = (const float*)d_in[23];
    const float* norm_out_g = (const float*)d_in[24];
    const float* norm_out_b = (const float*)d_in[25];

    float *tproj, *t1, *temb, *tsilu, *h, *cat, *kv, *lat, *lm, *q, *att, *ff, *emb, *obuf;
    cudaGetSymbolAddress((void**)&tproj, g_tproj);
    cudaGetSymbolAddress((void**)&t1,    g_t1);
    cudaGetSymbolAddress((void**)&temb,  g_temb);
    cudaGetSymbolAddress((void**)&tsilu, g_tsilu);
    cudaGetSymbolAddress((void**)&h,     g_h);
    cudaGetSymbolAddress((void**)&cat,   g_cat);
    cudaGetSymbolAddress((void**)&kv,    g_kv);
    cudaGetSymbolAddress((void**)&lat,   g_lat);
    cudaGetSymbolAddress((void**)&lm,    g_lm);
    cudaGetSymbolAddress((void**)&q,     g_q);
    cudaGetSymbolAddress((void**)&att,   g_att);
    cudaGetSymbolAddress((void**)&ff,    g_ff);
    cudaGetSymbolAddress((void**)&emb,   g_emb);
    cudaGetSymbolAddress((void**)&obuf,  g_obuf);

    cudaFuncSetAttribute(attn_kernel, cudaFuncAttributeMaxDynamicSharedMemorySize,
                         SMEM_ATTN);

    // time embedding
    time_proj_kernel<<<B_, 160>>>(timestep, tproj);
    run_gemm(tproj, te1_W, t1, B_, H_, TIN_, te1_b, nullptr, MODE_BIAS_SILU);
    run_gemm(t1, te2_W, temb, B_, H_, H_, te2_b, nullptr, MODE_BIAS);
    silu_kernel<<<(B_*H_ + 255)/256, 256>>>(temb, tsilu, B_*H_);

    // h = x @ proj_in_W + b + temb[batch]
    run_gemm(x, proj_in_W, h, MH, H_, E_, proj_in_b, temb, MODE_BIAS_TEMB);

    // latents broadcast
    lat_init_kernel<<<(ML*H_ + 255)/256, 256>>>(latents0, lat);

    for (int i = 0; i < DL; i++) {
        const float* WqL   = Wq     + (size_t)i * H_ * H_;
        const float* WkvL  = Wkv    + (size_t)i * H_ * 2 * H_;
        const float* WoL   = Wo     + (size_t)i * H_ * H_;
        const float* adaWL = ada_W  + (size_t)i * H_ * 4 * H_;
        const float* adabL = ada_b  + (size_t)i * 4 * H_;
        const float* Wff1L = Wff1   + (size_t)i * H_ * FF_;
        const float* Wff2L = Wff2   + (size_t)i * FF_ * H_;

        // adaLN params: emb[B,4H] = silu(temb) @ ada_W + ada_b
        run_gemm(tsilu, adaWL, emb, B_, 4*H_, H_, adabL, nullptr, MODE_BIAS);

        // cat[:, :577] = LN(h); cat[:, 577:] = lm = LN(lat)*(1+sc_msa)+sh_msa
        ln_h_kernel<<<MH, 256>>>(h, ln0_g + i*H_, ln0_b + i*H_, cat);
        ln_mod_kernel<<<ML, 256>>>(lat, ln1_g + i*H_, ln1_b + i*H_,
                                   emb, 0, H_, lm, cat);

        run_gemm(lm,  WqL,  q,  ML, H_,   H_, nullptr, nullptr, MODE_NONE);
        run_gemm(cat, WkvL, kv, MC, 2*H_, H_, nullptr, nullptr, MODE_NONE);

        attn_kernel<<<B_*NH_, 256, SMEM_ATTN>>>(q, kv, att);

        // lat = att @ Wo + lat
        run_gemm(att, WoL, lat, ML, H_, H_, nullptr, lat, MODE_RES);

        // lm2 = LN(lat)*(1+sc_mlp)+sh_mlp
        ln_mod_kernel<<<ML, 256>>>(lat, lnada_g + i*H_, lnada_b + i*H_,
                                   emb, 2*H_, 3*H_, lm, nullptr);

        // ff = gelu(lm2 @ Wff1); lat = ff @ Wff2 + lat
        run_gemm(lm, Wff1L, ff, ML, FF_, H_, nullptr, nullptr, MODE_GELU);
        run_gemm(ff, Wff2L, lat, ML, H_, FF_, nullptr, lat, MODE_RES);
    }

    // out = LN(lat @ proj_out_W + b)
    run_gemm(lat, proj_out_W, obuf, ML, O_, H_, proj_out_b, nullptr, MODE_BIAS);
    ln_out_kernel<<<ML, 256>>>(obuf, norm_out_g, norm_out_b, (float*)d_out);

    // second output: t_emb
    const int out0 = ML * O_;
    if (out_size >= out0 + B_*H_)
        copy_kernel<<<(B_*H_ + 255)/256, 256>>>(temb, (float*)d_out + out0, B_*H_);
}

// round 8
// speedup vs baseline: 1.0009x; 1.0009x over previous
#include <cuda_runtime.h>
#include <cstdint>
#include <cstdio>

// ---------------- problem dims ----------------
#define E_    1152
#define H_    1280
#define O_    2432
#define DL    4
#define HD_   64
#define NH_   20
#define NQ_   64
#define TIN_  320
#define FF_   5120
#define B_    32
#define N_    577
#define NKV   641              // N_ + NQ_
#define MH    (B_*N_)          // 18464
#define MC    (B_*NKV)         // 20512
#define ML    (B_*NQ_)         // 2048

// ---------------- scratch (device globals; no allocation) ----------------
__device__ float g_tproj[B_*TIN_];
__device__ float g_t1[B_*H_];
__device__ float g_temb[B_*H_];
__device__ float g_tsilu[B_*H_];
__device__ float g_h[(size_t)MH*H_];
__device__ float g_cat[(size_t)MC*H_];
__device__ float g_kv[(size_t)MC*2*H_];
__device__ float g_lat[(size_t)ML*H_];
__device__ float g_lm[(size_t)ML*H_];
__device__ float g_q[(size_t)ML*H_];
__device__ float g_att[(size_t)ML*H_];
__device__ float g_ff[(size_t)ML*FF_];
__device__ float g_emb[B_*4*H_];
__device__ float g_obuf[(size_t)ML*O_];

// ---------------- epilogue modes ----------------
#define MODE_NONE      0
#define MODE_BIAS      1
#define MODE_BIAS_TEMB 2   // + bias[c] + extra[(r/577)*N + c]
#define MODE_BIAS_SILU 3
#define MODE_GELU      4
#define MODE_RES       5   // + extra[r*N + c]

// ---------------- generic fp32 SGEMM: C[M,N] = A[M,K] @ B[K,N] (+epilogue) ---
// Requirements: K % 8 == 0, N % 128 == 0. M arbitrary (guarded).
__global__ __launch_bounds__(256, 2)
void sgemm_kernel(const float* __restrict__ A, const float* __restrict__ Bm,
                  float* __restrict__ C, int M, int N, int K,
                  const float* __restrict__ bias, const float* __restrict__ extra,
                  int mode)
{
    __shared__ float As[2][8][128];
    __shared__ float Bs[2][8][128];

    const int tid  = threadIdx.x;
    const int row0 = blockIdx.y * 128;
    const int col0 = blockIdx.x * 128;

    const int ar = tid >> 1;            // 0..127
    const int ac = (tid & 1) << 2;      // 0 or 4
    const int br = tid >> 5;            // 0..7
    const int bc = (tid & 31) << 2;     // 0..124

    const int ty = tid >> 4;            // 0..15
    const int tx = tid & 15;            // 0..15

    float acc[8][8];
    #pragma unroll
    for (int i = 0; i < 8; i++)
        #pragma unroll
        for (int j = 0; j < 8; j++) acc[i][j] = 0.f;

    const bool arow_ok = (row0 + ar) < M;
    const float* Aptr = A + (size_t)(row0 + ar) * K + ac;
    const float* Bptr = Bm + (size_t)br * N + col0 + bc;

    // load tile 0
    {
        float4 a = arow_ok ? *(const float4*)Aptr : make_float4(0.f,0.f,0.f,0.f);
        float4 b = *(const float4*)Bptr;
        As[0][ac+0][ar] = a.x; As[0][ac+1][ar] = a.y;
        As[0][ac+2][ar] = a.z; As[0][ac+3][ar] = a.w;
        *(float4*)&Bs[0][br][bc] = b;
    }
    __syncthreads();

    int cur = 0;
    for (int kt = 0; kt < K; kt += 8) {
        const bool has_next = (kt + 8) < K;
        float4 an, bn;
        if (has_next) {
            an = arow_ok ? *(const float4*)(Aptr + kt + 8) : make_float4(0.f,0.f,0.f,0.f);
            bn = *(const float4*)(Bptr + (size_t)(kt + 8) * N);
        }
        #pragma unroll
        for (int k = 0; k < 8; k++) {
            float ra[8], rb[8];
            float4 t0 = *(const float4*)&As[cur][k][ty*8];
            float4 t1 = *(const float4*)&As[cur][k][ty*8+4];
            float4 u0 = *(const float4*)&Bs[cur][k][tx*8];
            float4 u1 = *(const float4*)&Bs[cur][k][tx*8+4];
            ra[0]=t0.x; ra[1]=t0.y; ra[2]=t0.z; ra[3]=t0.w;
            ra[4]=t1.x; ra[5]=t1.y; ra[6]=t1.z; ra[7]=t1.w;
            rb[0]=u0.x; rb[1]=u0.y; rb[2]=u0.z; rb[3]=u0.w;
            rb[4]=u1.x; rb[5]=u1.y; rb[6]=u1.z; rb[7]=u1.w;
            #pragma unroll
            for (int i = 0; i < 8; i++)
                #pragma unroll
                for (int j = 0; j < 8; j++)
                    acc[i][j] = fmaf(ra[i], rb[j], acc[i][j]);
        }
        if (has_next) {
            As[cur^1][ac+0][ar] = an.x; As[cur^1][ac+1][ar] = an.y;
            As[cur^1][ac+2][ar] = an.z; As[cur^1][ac+3][ar] = an.w;
            *(float4*)&Bs[cur^1][br][bc] = bn;
            __syncthreads();
            cur ^= 1;
        }
    }

    // epilogue
    #pragma unroll
    for (int i = 0; i < 8; i++) {
        const int r = row0 + ty*8 + i;
        if (r >= M) continue;
        #pragma unroll
        for (int j = 0; j < 8; j++) {
            const int c = col0 + tx*8 + j;
            float v = acc[i][j];
            if (mode == MODE_BIAS) {
                v += bias[c];
            } else if (mode == MODE_BIAS_TEMB) {
                v += bias[c] + extra[(size_t)(r / N_) * N + c];
            } else if (mode == MODE_BIAS_SILU) {
                float s = v + bias[c];
                v = s / (1.0f + expf(-s));
            } else if (mode == MODE_GELU) {
                v = 0.5f * v * (1.0f + erff(v * 0.70710678118654752f));
            } else if (mode == MODE_RES) {
                v += extra[(size_t)r * N + c];
            }
            C[(size_t)r * N + c] = v;
        }
    }
}

// ---------------- fused attention: one block per (b, head) ----------------
// Q[b,l,h*64+d] from g_q, K/V from g_kv (K = cols [0,1280), V = cols [1280,2560)).
// scores (64x704 padded) + softmax + AV, output to g_att.
#define JPAD   704               // 11 tiles of 64
#define SSTR   68                // padded row stride (floats), 16B-aligned units
#define SMEM_ATTN ((JPAD*SSTR + 64*SSTR + 64*SSTR + 64) * 4)

__global__ __launch_bounds__(256, 1)
void attn_kernel(const float* __restrict__ Q, const float* __restrict__ KV,
                 float* __restrict__ Ot)
{
    extern __shared__ float sm[];
    float* S    = sm;                        // [JPAD][SSTR]  scores^T : S[j][l]
    float* Qs   = S  + JPAD*SSTR;            // [64][SSTR]    q^T : Qs[d][l]
    float* Ts   = Qs + 64*SSTR;              // [64][SSTR]    K^T tile / V tile
    float* rinv = Ts + 64*SSTR;              // [64] 1/rowsum

    const int tid = threadIdx.x;
    const int b   = blockIdx.x / NH_;
    const int h   = blockIdx.x % NH_;

    const float* qbase = Q  + ((size_t)b * NQ_) * H_ + h * HD_;
    const float* kbase = KV + ((size_t)b * NKV) * (2*H_) + h * HD_;
    const float* vbase = kbase + H_;

    // load Q transposed: Qs[d][l]
    #pragma unroll
    for (int r = 0; r < 16; r++) {
        int idx = tid + r * 256;             // 0..4095
        int l = idx >> 6, d = idx & 63;
        Qs[d*SSTR + l] = qbase[(size_t)l * H_ + d];
    }

    const int lt = tid >> 4;   // 0..15 (l groups of 4)
    const int c4 = tid & 15;   // 0..15 (j or d groups of 4)

    // ---- phase 1: scores ----
    for (int t = 0; t < 11; t++) {
        const int jbase = t * 64;
        #pragma unroll
        for (int r = 0; r < 16; r++) {
            int idx = tid + r * 256;
            int jj = idx >> 6, d = idx & 63;
            int j = jbase + jj;
            Ts[d*SSTR + jj] = (j < NKV) ? kbase[(size_t)j * (2*H_) + d] : 0.f;
        }
        __syncthreads();

        float acc[4][4];
        #pragma unroll
        for (int i = 0; i < 4; i++)
            #pragma unroll
            for (int j = 0; j < 4; j++) acc[i][j] = 0.f;

        #pragma unroll 8
        for (int d = 0; d < 64; d++) {
            float4 q4 = *(const float4*)&Qs[d*SSTR + lt*4];
            float4 k4 = *(const float4*)&Ts[d*SSTR + c4*4];
            float qa[4] = {q4.x, q4.y, q4.z, q4.w};
            float ka[4] = {k4.x, k4.y, k4.z, k4.w};
            #pragma unroll
            for (int i = 0; i < 4; i++)
                #pragma unroll
                for (int j = 0; j < 4; j++)
                    acc[i][j] = fmaf(qa[i], ka[j], acc[i][j]);
        }
        #pragma unroll
        for (int jj = 0; jj < 4; jj++) {
            const int j = jbase + c4*4 + jj;
            float4 w;
            if (j < NKV) {
                w.x = acc[0][jj] * 0.125f; w.y = acc[1][jj] * 0.125f;
                w.z = acc[2][jj] * 0.125f; w.w = acc[3][jj] * 0.125f;
            } else {
                w.x = w.y = w.z = w.w = -1e30f;
            }
            *(float4*)&S[(size_t)j*SSTR + lt*4] = w;
        }
        __syncthreads();
    }

    // ---- phase 2: softmax over j per row l (4 lanes per row) ----
    {
        const int l   = tid >> 2;
        const int sub = tid & 3;
        float m = -1e30f;
        for (int j = sub; j < JPAD; j += 4) m = fmaxf(m, S[j*SSTR + l]);
        m = fmaxf(m, __shfl_xor_sync(0xffffffffu, m, 1));
        m = fmaxf(m, __shfl_xor_sync(0xffffffffu, m, 2));
        float ssum = 0.f;
        for (int j = sub; j < JPAD; j += 4) {
            float e = __expf(S[j*SSTR + l] - m);
            S[j*SSTR + l] = e;
            ssum += e;
        }
        ssum += __shfl_xor_sync(0xffffffffu, ssum, 1);
        ssum += __shfl_xor_sync(0xffffffffu, ssum, 2);
        if (sub == 0) rinv[l] = 1.0f / ssum;
    }
    __syncthreads();

    // ---- phase 3: att = P @ V ----
    float oacc[4][4];
    #pragma unroll
    for (int i = 0; i < 4; i++)
        #pragma unroll
        for (int j = 0; j < 4; j++) oacc[i][j] = 0.f;

    for (int t = 0; t < 11; t++) {
        const int jbase = t * 64;
        #pragma unroll
        for (int r = 0; r < 16; r++) {
            int idx = tid + r * 256;
            int jj = idx >> 6, d = idx & 63;
            int j = jbase + jj;
            Ts[jj*SSTR + d] = (j < NKV) ? vbase[(size_t)j * (2*H_) + d] : 0.f;
        }
        __syncthreads();
        #pragma unroll 8
        for (int jj = 0; jj < 64; jj++) {
            float4 p4 = *(const float4*)&S[(size_t)(jbase + jj)*SSTR + lt*4];
            float4 v4 = *(const float4*)&Ts[jj*SSTR + c4*4];
            float pa[4] = {p4.x, p4.y, p4.z, p4.w};
            float va[4] = {v4.x, v4.y, v4.z, v4.w};
            #pragma unroll
            for (int i = 0; i < 4; i++)
                #pragma unroll
                for (int j = 0; j < 4; j++)
                    oacc[i][j] = fmaf(pa[i], va[j], oacc[i][j]);
        }
        __syncthreads();
    }

    #pragma unroll
    for (int i = 0; i < 4; i++) {
        const int l = lt*4 + i;
        const float sc = rinv[l];
        #pragma unroll
        for (int j = 0; j < 4; j++) {
            const int d = c4*4 + j;
            Ot[((size_t)(b*NQ_ + l)) * H_ + h*HD_ + d] = oacc[i][j] * sc;
        }
    }
}

// ---------------- LayerNorm helpers ----------------
__device__ inline void block_reduce_2(float& s, float& s2) {
    __shared__ float red[16];
    const int lane = threadIdx.x & 31;
    const int w    = threadIdx.x >> 5;
    #pragma unroll
    for (int o = 16; o > 0; o >>= 1) {
        s  += __shfl_xor_sync(0xffffffffu, s,  o);
        s2 += __shfl_xor_sync(0xffffffffu, s2, o);
    }
    if (lane == 0) { red[w] = s; red[8 + w] = s2; }
    __syncthreads();
    if (threadIdx.x < 32) {
        s  = (lane < 8) ? red[lane]     : 0.f;
        s2 = (lane < 8) ? red[8 + lane] : 0.f;
        #pragma unroll
        for (int o = 4; o > 0; o >>= 1) {
            s  += __shfl_xor_sync(0xffffffffu, s,  o);
            s2 += __shfl_xor_sync(0xffffffffu, s2, o);
        }
        if (lane == 0) { red[0] = s; red[8] = s2; }
    }
    __syncthreads();
    s = red[0]; s2 = red[8];
}

// LN(h) rows -> cat rows [b*641 + n]
__global__ __launch_bounds__(256)
void ln_h_kernel(const float* __restrict__ in, const float* __restrict__ g,
                 const float* __restrict__ beta, float* __restrict__ cat)
{
    const int r = blockIdx.x;                 // 0..MH-1
    const int b = r / N_, n = r % N_;
    const float* x = in + (size_t)r * H_;
    float* out = cat + ((size_t)b * NKV + n) * H_;
    float s = 0.f, s2 = 0.f;
    for (int i = threadIdx.x; i < H_; i += 256) { float v = x[i]; s += v; s2 += v*v; }
    block_reduce_2(s, s2);
    const float mean = s * (1.0f / H_);
    const float var  = s2 * (1.0f / H_) - mean * mean;
    const float inv  = rsqrtf(var + 1e-5f);
    for (int i = threadIdx.x; i < H_; i += 256)
        out[i] = (x[i] - mean) * inv * g[i] + beta[i];
}

// LN(lat) with adaLN modulation: v = LN(v)*(1+sc)+sh -> out1 (+ optional cat rows)
__global__ __launch_bounds__(256)
void ln_mod_kernel(const float* __restrict__ in, const float* __restrict__ g,
                   const float* __restrict__ beta, const float* __restrict__ emb,
                   int shOff, int scOff, float* __restrict__ out1,
                   float* __restrict__ out2)
{
    const int r = blockIdx.x;                 // 0..ML-1
    const int b = r >> 6, qrow = r & 63;
    const float* x  = in + (size_t)r * H_;
    const float* sh = emb + (size_t)b * (4*H_) + shOff;
    const float* sc = emb + (size_t)b * (4*H_) + scOff;
    float s = 0.f, s2 = 0.f;
    for (int i = threadIdx.x; i < H_; i += 256) { float v = x[i]; s += v; s2 += v*v; }
    block_reduce_2(s, s2);
    const float mean = s * (1.0f / H_);
    const float var  = s2 * (1.0f / H_) - mean * mean;
    const float inv  = rsqrtf(var + 1e-5f);
    float* o1 = out1 + (size_t)r * H_;
    float* o2 = out2 ? out2 + ((size_t)b * NKV + N_ + qrow) * H_ : nullptr;
    for (int i = threadIdx.x; i < H_; i += 256) {
        float v = (x[i] - mean) * inv * g[i] + beta[i];
        v = v * (1.0f + sc[i]) + sh[i];
        o1[i] = v;
        if (o2) o2[i] = v;
    }
}

// final LN (rows of length O_)
__global__ __launch_bounds__(256)
void ln_out_kernel(const float* __restrict__ in, const float* __restrict__ g,
                   const float* __restrict__ beta, float* __restrict__ out)
{
    const int r = blockIdx.x;                 // 0..ML-1
    const float* x = in + (size_t)r * O_;
    float s = 0.f, s2 = 0.f;
    for (int i = threadIdx.x; i < O_; i += 256) { float v = x[i]; s += v; s2 += v*v; }
    block_reduce_2(s, s2);
    const float mean = s * (1.0f / O_);
    const float var  = s2 * (1.0f / O_) - mean * mean;
    const float inv  = rsqrtf(var + 1e-5f);
    float* o = out + (size_t)r * O_;
    for (int i = threadIdx.x; i < O_; i += 256)
        o[i] = (x[i] - mean) * inv * g[i] + beta[i];
}

// ---------------- small kernels ----------------
__global__ void time_proj_kernel(const float* __restrict__ t, float* __restrict__ tp)
{
    const int b = blockIdx.x;      // 0..31
    const int k = threadIdx.x;     // 0..159
    const float f = expf(-9.210340371976184f * (float)k / 160.0f);   // ln(10000)
    const float ang = t[b] * f;
    tp[b*TIN_ + k]        = cosf(ang);
    tp[b*TIN_ + 160 + k]  = sinf(ang);
}

__global__ void silu_kernel(const float* __restrict__ in, float* __restrict__ out, int n)
{
    int i = blockIdx.x * blockDim.x + threadIdx.x;
    if (i < n) { float v = in[i]; out[i] = v / (1.0f + expf(-v)); }
}

__global__ void lat_init_kernel(const float* __restrict__ l0, float* __restrict__ lat)
{
    int i = blockIdx.x * blockDim.x + threadIdx.x;
    if (i < ML * H_) lat[i] = l0[i % (NQ_ * H_)];
}

__global__ void copy_kernel(const float* __restrict__ in, float* __restrict__ out, int n)
{
    int i = blockIdx.x * blockDim.x + threadIdx.x;
    if (i < n) out[i] = in[i];
}

// ---------------- host driver ----------------
static inline void run_gemm(const float* A, const float* B, float* C,
                            int M, int N, int K,
                            const float* bias, const float* extra, int mode)
{
    dim3 grid(N / 128, (M + 127) / 128);
    sgemm_kernel<<<grid, 256>>>(A, B, C, M, N, K, bias, extra, mode);
}

extern "C" void kernel_launch(void* const* d_in, const int* in_sizes, int n_in,
                              void* d_out, int out_size)
{
    const float* x          = (const float*)d_in[0];
    const float* timestep   = (const float*)d_in[1];
    const float* latents0   = (const float*)d_in[2];
    const float* proj_in_W  = (const float*)d_in[3];
    const float* proj_in_b  = (const float*)d_in[4];
    const float* te1_W      = (const float*)d_in[5];
    const float* te1_b      = (const float*)d_in[6];
    const float* te2_W      = (const float*)d_in[7];
    const float* te2_b      = (const float*)d_in[8];
    const float* ln0_g      = (const float*)d_in[9];
    const float* ln0_b      = (const float*)d_in[10];
    const float* ln1_g      = (const float*)d_in[11];
    const float* ln1_b      = (const float*)d_in[12];
    const float* Wq         = (const float*)d_in[13];
    const float* Wkv        = (const float*)d_in[14];
    const float* Wo         = (const float*)d_in[15];
    const float* ada_W      = (const float*)d_in[16];
    const float* ada_b      = (const float*)d_in[17];
    const float* lnada_g    = (const float*)d_in[18];
    const float* lnada_b    = (const float*)d_in[19];
    const float* Wff1       = (const float*)d_in[20];
    const float* Wff2       = (const float*)d_in[21];
    const float* proj_out_W = (const float*)d_in[22];
    const float* proj_out_b = (const float*)d_in[23];
    const float* norm_out_g = (const float*)d_in[24];
    const float* norm_out_b = (const float*)d_in[25];

    float *tproj, *t1, *temb, *tsilu, *h, *cat, *kv, *lat, *lm, *q, *att, *ff, *emb, *obuf;
    cudaGetSymbolAddress((void**)&tproj, g_tproj);
    cudaGetSymbolAddress((void**)&t1,    g_t1);
    cudaGetSymbolAddress((void**)&temb,  g_temb);
    cudaGetSymbolAddress((void**)&tsilu, g_tsilu);
    cudaGetSymbolAddress((void**)&h,     g_h);
    cudaGetSymbolAddress((void**)&cat,   g_cat);
    cudaGetSymbolAddress((void**)&kv,    g_kv);
    cudaGetSymbolAddress((void**)&lat,   g_lat);
    cudaGetSymbolAddress((void**)&lm,    g_lm);
    cudaGetSymbolAddress((void**)&q,     g_q);
    cudaGetSymbolAddress((void**)&att,   g_att);
    cudaGetSymbolAddress((void**)&ff,    g_ff);
    cudaGetSymbolAddress((void**)&emb,   g_emb);
    cudaGetSymbolAddress((void**)&obuf,  g_obuf);

    cudaFuncSetAttribute(attn_kernel, cudaFuncAttributeMaxDynamicSharedMemorySize,
                         SMEM_ATTN);

    // time embedding
    time_proj_kernel<<<B_, 160>>>(timestep, tproj);
    run_gemm(tproj, te1_W, t1, B_, H_, TIN_, te1_b, nullptr, MODE_BIAS_SILU);
    run_gemm(t1, te2_W, temb, B_, H_, H_, te2_b, nullptr, MODE_BIAS);
    silu_kernel<<<(B_*H_ + 255)/256, 256>>>(temb, tsilu, B_*H_);

    // h = x @ proj_in_W + b + temb[batch]
    run_gemm(x, proj_in_W, h, MH, H_, E_, proj_in_b, temb, MODE_BIAS_TEMB);

    // latents broadcast
    lat_init_kernel<<<(ML*H_ + 255)/256, 256>>>(latents0, lat);

    for (int i = 0; i < DL; i++) {
        const float* WqL   = Wq     + (size_t)i * H_ * H_;
        const float* WkvL  = Wkv    + (size_t)i * H_ * 2 * H_;
        const float* WoL   = Wo     + (size_t)i * H_ * H_;
        const float* adaWL = ada_W  + (size_t)i * H_ * 4 * H_;
        const float* adabL = ada_b  + (size_t)i * 4 * H_;
        const float* Wff1L = Wff1   + (size_t)i * H_ * FF_;
        const float* Wff2L = Wff2   + (size_t)i * FF_ * H_;

        // adaLN params: emb[B,4H] = silu(temb) @ ada_W + ada_b
        run_gemm(tsilu, adaWL, emb, B_, 4*H_, H_, adabL, nullptr, MODE_BIAS);

        // cat[:, :577] = LN(h); cat[:, 577:] = lm = LN(lat)*(1+sc_msa)+sh_msa
        ln_h_kernel<<<MH, 256>>>(h, ln0_g + i*H_, ln0_b + i*H_, cat);
        ln_mod_kernel<<<ML, 256>>>(lat, ln1_g + i*H_, ln1_b + i*H_,
                                   emb, 0, H_, lm, cat);

        run_gemm(lm,  WqL,  q,  ML, H_,   H_, nullptr, nullptr, MODE_NONE);
        run_gemm(cat, WkvL, kv, MC, 2*H_, H_, nullptr, nullptr, MODE_NONE);

        attn_kernel<<<B_*NH_, 256, SMEM_ATTN>>>(q, kv, att);

        // lat = att @ Wo + lat
        run_gemm(att, WoL, lat, ML, H_, H_, nullptr, lat, MODE_RES);

        // lm2 = LN(lat)*(1+sc_mlp)+sh_mlp
        ln_mod_kernel<<<ML, 256>>>(lat, lnada_g + i*H_, lnada_b + i*H_,
                                   emb, 2*H_, 3*H_, lm, nullptr);

        // ff = gelu(lm2 @ Wff1); lat = ff @ Wff2 + lat
        run_gemm(lm, Wff1L, ff, ML, FF_, H_, nullptr, nullptr, MODE_GELU);
        run_gemm(ff, Wff2L, lat, ML, H_, FF_, nullptr, lat, MODE_RES);
    }

    // out = LN(lat @ proj_out_W + b)
    run_gemm(lat, proj_out_W, obuf, ML, O_, H_, proj_out_b, nullptr, MODE_BIAS);
    ln_out_kernel<<<ML, 256>>>(obuf, norm_out_g, norm_out_b, (float*)d_out);

    // second output: t_emb
    const int out0 = ML * O_;
    if (out_size >= out0 + B_*H_)
        copy_kernel<<<(B_*H_ + 255)/256, 256>>>(temb, (float*)d_out + out0, B_*H_);
}

// round 10
// speedup vs baseline: 2.6861x; 2.6836x over previous
#include <cuda_runtime.h>
#include <cuda_bf16.h>
#include <cstdint>

using bf16 = __nv_bfloat16;

#define E_    1152
#define H_    1280
#define O_    2432
#define DL    4
#define HD_   64
#define NH_   20
#define NQ_   64
#define TIN_  320
#define FF_   5120
#define B_    32
#define N_    577
#define NKV   641
#define MH    (B_*N_)
#define MC    (B_*NKV)
#define ML    (B_*NQ_)

// fp32 scratch
__device__ float g_tproj[B_*TIN_];
__device__ float g_t1[B_*H_];
__device__ float g_temb[B_*H_];
__device__ float g_tsilu[B_*H_];
__device__ float g_h[(size_t)MH*H_];
__device__ float g_cat[(size_t)MC*H_];
__device__ float g_kv[(size_t)MC*2*H_];
__device__ float g_lat[(size_t)ML*H_];
__device__ float g_lm[(size_t)ML*H_];
__device__ float g_q[(size_t)ML*H_];
__device__ float g_att[(size_t)ML*H_];
__device__ float g_ff[(size_t)ML*FF_];
__device__ float g_emb[B_*4*H_];
__device__ float g_obuf[(size_t)ML*O_];

// bf16 weights transposed to [N,K], hi/lo
__device__ bf16 g_wpin_h[(size_t)H_*E_],      g_wpin_l[(size_t)H_*E_];
__device__ bf16 g_wte1_h[(size_t)H_*TIN_],    g_wte1_l[(size_t)H_*TIN_];
__device__ bf16 g_wte2_h[(size_t)H_*H_],      g_wte2_l[(size_t)H_*H_];
__device__ bf16 g_wq_h[(size_t)DL*H_*H_],     g_wq_l[(size_t)DL*H_*H_];
__device__ bf16 g_wkv_h[(size_t)DL*2*H_*H_],  g_wkv_l[(size_t)DL*2*H_*H_];
__device__ bf16 g_wo_h[(size_t)DL*H_*H_],     g_wo_l[(size_t)DL*H_*H_];
__device__ bf16 g_wada_h[(size_t)DL*4*H_*H_], g_wada_l[(size_t)DL*4*H_*H_];
__device__ bf16 g_wff1_h[(size_t)DL*FF_*H_],  g_wff1_l[(size_t)DL*FF_*H_];
__device__ bf16 g_wff2_h[(size_t)DL*H_*FF_],  g_wff2_l[(size_t)DL*H_*FF_];
__device__ bf16 g_wpo_h[(size_t)O_*H_],       g_wpo_l[(size_t)O_*H_];

// bf16 activations hi/lo
__device__ bf16 g_tp_h[B_*TIN_],        g_tp_l[B_*TIN_];
__device__ bf16 g_t1_h[B_*H_],          g_t1_l[B_*H_];
__device__ bf16 g_ts_h[B_*H_],          g_ts_l[B_*H_];
__device__ bf16 g_x_h[(size_t)MH*E_],   g_x_l[(size_t)MH*E_];
__device__ bf16 g_cat_h[(size_t)MC*H_], g_cat_l[(size_t)MC*H_];
__device__ bf16 g_lm_h[(size_t)ML*H_],  g_lm_l[(size_t)ML*H_];
__device__ bf16 g_att_h[(size_t)ML*H_], g_att_l[(size_t)ML*H_];
__device__ bf16 g_ff_h[(size_t)ML*FF_], g_ff_l[(size_t)ML*FF_];

#define MODE_NONE      0
#define MODE_BIAS      1
#define MODE_BIAS_TEMB 2
#define MODE_BIAS_SILU 3
#define MODE_GELU      4
#define MODE_RES       5

// ---------- PTX helpers (sm_80-portable only; NO tcgen05) ----------
__device__ __forceinline__ uint32_t smem_u32(const void* p) {
    uint32_t a;
    asm("{ .reg .u64 t; cvta.to.shared.u64 t, %1; cvt.u32.u64 %0, t; }" : "=r"(a) : "l"(p));
    return a;
}
__device__ __forceinline__ void cp16(uint32_t dst, const void* src, int sz) {
    asm volatile("cp.async.cg.shared.global [%0], [%1], 16, %2;" :: "r"(dst), "l"(src), "r"(sz));
}
#define CP_COMMIT() asm volatile("cp.async.commit_group;" ::: "memory")

#define LDSM4(r, a) asm volatile( \
    "ldmatrix.sync.aligned.m8n8.x4.shared.b16 {%0,%1,%2,%3}, [%4];" \
    : "=r"((r)[0]), "=r"((r)[1]), "=r"((r)[2]), "=r"((r)[3]) : "r"(a))

#define MMA16816(d, a, b) asm volatile( \
    "mma.sync.aligned.m16n8k16.row.col.f32.bf16.bf16.f32 " \
    "{%0,%1,%2,%3}, {%4,%5,%6,%7}, {%8,%9}, {%0,%1,%2,%3};" \
    : "+f"((d)[0]), "+f"((d)[1]), "+f"((d)[2]), "+f"((d)[3]) \
    : "r"((a)[0]), "r"((a)[1]), "r"((a)[2]), "r"((a)[3]), "r"((b)[0]), "r"((b)[1]))

// ---------- bf16 3-split GEMM via mma.sync ----------
// C[M,N] = Ah@Bh^T + Ah@Bl^T + Al@Bh^T (+epilogue)
// A*: [M,K] bf16 row-major.  B*: [N,K] bf16 row-major (weights pre-transposed).
// CTA tile 128x128, BK=64, 8 warps (2x4), warp tile 64x32, 3-stage cp.async.
#define STAGE_BYTES 65536
#define GEMM_SMEM   (3*STAGE_BYTES)

__device__ __forceinline__ float epi(float v, int r, int c, int N,
                                     const float* __restrict__ bias,
                                     const float* __restrict__ extra, int mode)
{
    if (mode == MODE_BIAS) v += bias[c];
    else if (mode == MODE_BIAS_TEMB) v += bias[c] + extra[(size_t)(r / N_) * N + c];
    else if (mode == MODE_BIAS_SILU) { float s = v + bias[c]; v = s / (1.0f + expf(-s)); }
    else if (mode == MODE_GELU) v = 0.5f * v * (1.0f + erff(v * 0.70710678118654752f));
    else if (mode == MODE_RES) v += extra[(size_t)r * N + c];
    return v;
}

// Fill one 4-tile stage (Ah/Al/Bh/Bl, each 128 rows x 64 bf16, XOR-swizzled 16B chunks)
__device__ __forceinline__ void g_load_stage(
    uint32_t base, const bf16* __restrict__ Ah, const bf16* __restrict__ Al,
    const bf16* __restrict__ Bh, const bf16* __restrict__ Bl,
    int row0, int col0, int M, int K, int kc, int tid)
{
    #pragma unroll
    for (int p = 0; p < 4; p++) {
        const int idx = tid + p * 256;
        const int r = idx >> 3, ch = idx & 7;
        const uint32_t dsw = (uint32_t)(r * 128 + ((ch ^ (r & 7)) << 4));
        const int ar = row0 + r, br = col0 + r;
        const size_t ao = (size_t)ar * K + kc + ch * 8;
        const size_t bo = (size_t)br * K + kc + ch * 8;
        const int asz = (ar < M) ? 16 : 0;
        cp16(base + dsw,         Ah + ao, asz);
        cp16(base + 16384 + dsw, Al + ao, asz);
        cp16(base + 32768 + dsw, Bh + bo, 16);
        cp16(base + 49152 + dsw, Bl + bo, 16);
    }
    CP_COMMIT();
}

__global__ __launch_bounds__(256)
void gemm_mma_kernel(const bf16* __restrict__ Ah, const bf16* __restrict__ Al,
                     const bf16* __restrict__ Bh, const bf16* __restrict__ Bl,
                     float* __restrict__ C, int M, int N, int K,
                     const float* __restrict__ bias, const float* __restrict__ extra,
                     int mode)
{
    extern __shared__ char smem[];
    const int tid = threadIdx.x;
    const int lane = tid & 31, wid = tid >> 5;
    const int wm = wid & 1, wn = wid >> 1;          // 2 x 4 warps
    const int row0 = blockIdx.y * 128, col0 = blockIdx.x * 128;
    const uint32_t sb = smem_u32(smem);

    float acc[4][4][4];
    #pragma unroll
    for (int a = 0; a < 4; a++)
        #pragma unroll
        for (int b = 0; b < 4; b++)
            #pragma unroll
            for (int c = 0; c < 4; c++) acc[a][b][c] = 0.f;

    const int NIT = K >> 6;   // K % 64 == 0 for all call sites; NIT >= 2 always

    g_load_stage(sb,               Ah, Al, Bh, Bl, row0, col0, M, K, 0,  tid);
    g_load_stage(sb + STAGE_BYTES, Ah, Al, Bh, Bl, row0, col0, M, K, 64, tid);

    int sidx = 0;
    for (int it = 0; it < NIT; it++) {
        if (it + 2 < NIT) {
            const int s2 = (it + 2) % 3;
            g_load_stage(sb + s2 * STAGE_BYTES, Ah, Al, Bh, Bl,
                         row0, col0, M, K, (it + 2) * 64, tid);
            asm volatile("cp.async.wait_group 2;" ::: "memory");
        } else if (it + 1 < NIT) {
            asm volatile("cp.async.wait_group 1;" ::: "memory");
        } else {
            asm volatile("cp.async.wait_group 0;" ::: "memory");
        }
        __syncthreads();

        const uint32_t aTh = sb + sidx * STAGE_BYTES;
        const uint32_t bTh = aTh + 32768;

        #pragma unroll
        for (int ks = 0; ks < 4; ks++) {
            uint32_t ahf[4][4], alf[4][4], bhf[2][4], blf[2][4];
            #pragma unroll
            for (int mt = 0; mt < 4; mt++) {
                const int r = wm * 64 + mt * 16 + (lane & 15);
                const int cch = ks * 2 + (lane >> 4);          // 16B-chunk index
                const uint32_t ad = aTh + r * 128 + ((cch ^ (r & 7)) << 4);
                LDSM4(ahf[mt], ad);
                LDSM4(alf[mt], ad + 16384);
            }
            #pragma unroll
            for (int n2 = 0; n2 < 2; n2++) {
                const int r = wn * 32 + n2 * 16 + (lane & 7) + ((lane >> 4) << 3);
                const int cch = ks * 2 + ((lane >> 3) & 1);
                const uint32_t ad = bTh + r * 128 + ((cch ^ (r & 7)) << 4);
                LDSM4(bhf[n2], ad);
                LDSM4(blf[n2], ad + 16384);
            }
            #pragma unroll
            for (int mt = 0; mt < 4; mt++)
                #pragma unroll
                for (int nt = 0; nt < 4; nt++) {
                    uint32_t* b2h = &bhf[nt >> 1][(nt & 1) << 1];
                    uint32_t* b2l = &blf[nt >> 1][(nt & 1) << 1];
                    MMA16816(acc[mt][nt], ahf[mt], b2h);
                    MMA16816(acc[mt][nt], ahf[mt], b2l);
                    MMA16816(acc[mt][nt], alf[mt], b2h);
                }
        }
        __syncthreads();
        if (++sidx == 3) sidx = 0;
    }

    // epilogue: acc c0,c1 -> (row g, col 2tg..+1); c2,c3 -> (row g+8)
    const int g = lane >> 2, tg = lane & 3;
    #pragma unroll
    for (int mt = 0; mt < 4; mt++) {
        const int r0 = row0 + wm * 64 + mt * 16 + g;
        #pragma unroll
        for (int nt = 0; nt < 4; nt++) {
            const int c = col0 + wn * 32 + nt * 8 + tg * 2;
            float* cc = acc[mt][nt];
            if (r0 < M) {
                float2 v;
                v.x = epi(cc[0], r0, c,     N, bias, extra, mode);
                v.y = epi(cc[1], r0, c + 1, N, bias, extra, mode);
                *(float2*)&C[(size_t)r0 * N + c] = v;
            }
            const int r1 = r0 + 8;
            if (r1 < M) {
                float2 v;
                v.x = epi(cc[2], r1, c,     N, bias, extra, mode);
                v.y = epi(cc[3], r1, c + 1, N, bias, extra, mode);
                *(float2*)&C[(size_t)r1 * N + c] = v;
            }
        }
    }
}

// ---------- split / transpose-split ----------
__global__ __launch_bounds__(256)
void split_kernel(const float* __restrict__ in, bf16* __restrict__ hi,
                  bf16* __restrict__ lo, int n)
{
    const int i = (blockIdx.x * blockDim.x + threadIdx.x) * 4;
    if (i >= n) return;
    float4 v = *(const float4*)(in + i);
    float a[4] = {v.x, v.y, v.z, v.w};
    bf16 hh[4], ll[4];
    #pragma unroll
    for (int j = 0; j < 4; j++) {
        bf16 h = __float2bfloat16(a[j]);
        hh[j] = h;
        ll[j] = __float2bfloat16(a[j] - __bfloat162float(h));
    }
    __nv_bfloat162 h01, h23, l01, l23;
    h01.x = hh[0]; h01.y = hh[1]; h23.x = hh[2]; h23.y = hh[3];
    l01.x = ll[0]; l01.y = ll[1]; l23.x = ll[2]; l23.y = ll[3];
    ((__nv_bfloat162*)(hi + i))[0] = h01;
    ((__nv_bfloat162*)(hi + i))[1] = h23;
    ((__nv_bfloat162*)(lo + i))[0] = l01;
    ((__nv_bfloat162*)(lo + i))[1] = l23;
}

__global__ __launch_bounds__(256)
void tsplit_kernel(const float* __restrict__ W, bf16* __restrict__ Th,
                   bf16* __restrict__ Tl, int K, int N)
{
    __shared__ float t[32][33];
    const int nb = blockIdx.x * 32, kb = blockIdx.y * 32;
    const int tx = threadIdx.x, ty = threadIdx.y;
    #pragma unroll
    for (int j = 0; j < 4; j++)
        t[ty + 8*j][tx] = W[(size_t)(kb + ty + 8*j) * N + nb + tx];
    __syncthreads();
    #pragma unroll
    for (int j = 0; j < 4; j++) {
        const int n = nb + ty + 8*j, k = kb + tx;
        const float v = t[tx][ty + 8*j];
        const bf16 h = __float2bfloat16(v);
        Th[(size_t)n * K + k] = h;
        Tl[(size_t)n * K + k] = __float2bfloat16(v - __bfloat162float(h));
    }
}

// ---------- attention (fp32) ----------
#define JPAD 704
#define SSTR 68
#define SMEM_ATTN ((JPAD*SSTR + 64*SSTR + 64*SSTR + 64) * 4)

__global__ __launch_bounds__(256, 1)
void attn_kernel(const float* __restrict__ Q, const float* __restrict__ KV,
                 float* __restrict__ Ot)
{
    extern __shared__ float sm[];
    float* S    = sm;
    float* Qs   = S  + JPAD*SSTR;
    float* Ts   = Qs + 64*SSTR;
    float* rinv = Ts + 64*SSTR;

    const int tid = threadIdx.x;
    const int b   = blockIdx.x / NH_;
    const int h   = blockIdx.x % NH_;

    const float* qbase = Q  + ((size_t)b * NQ_) * H_ + h * HD_;
    const float* kbase = KV + ((size_t)b * NKV) * (2*H_) + h * HD_;
    const float* vbase = kbase + H_;

    #pragma unroll
    for (int r = 0; r < 16; r++) {
        int idx = tid + r * 256;
        int l = idx >> 6, d = idx & 63;
        Qs[d*SSTR + l] = qbase[(size_t)l * H_ + d];
    }
    const int lt = tid >> 4, c4 = tid & 15;

    for (int t = 0; t < 11; t++) {
        const int jbase = t * 64;
        #pragma unroll
        for (int r = 0; r < 16; r++) {
            int idx = tid + r * 256;
            int jj = idx >> 6, d = idx & 63;
            int j = jbase + jj;
            Ts[d*SSTR + jj] = (j < NKV) ? kbase[(size_t)j * (2*H_) + d] : 0.f;
        }
        __syncthreads();
        float acc[4][4];
        #pragma unroll
        for (int i = 0; i < 4; i++)
            #pragma unroll
            for (int j = 0; j < 4; j++) acc[i][j] = 0.f;
        #pragma unroll 8
        for (int d = 0; d < 64; d++) {
            float4 q4 = *(const float4*)&Qs[d*SSTR + lt*4];
            float4 k4 = *(const float4*)&Ts[d*SSTR + c4*4];
            float qa[4] = {q4.x, q4.y, q4.z, q4.w};
            float ka[4] = {k4.x, k4.y, k4.z, k4.w};
            #pragma unroll
            for (int i = 0; i < 4; i++)
                #pragma unroll
                for (int j = 0; j < 4; j++)
                    acc[i][j] = fmaf(qa[i], ka[j], acc[i][j]);
        }
        #pragma unroll
        for (int jj = 0; jj < 4; jj++) {
            const int j = jbase + c4*4 + jj;
            float4 w;
            if (j < NKV) {
                w.x = acc[0][jj]*0.125f; w.y = acc[1][jj]*0.125f;
                w.z = acc[2][jj]*0.125f; w.w = acc[3][jj]*0.125f;
            } else { w.x = w.y = w.z = w.w = -1e30f; }
            *(float4*)&S[(size_t)j*SSTR + lt*4] = w;
        }
        __syncthreads();
    }
    {
        const int l = tid >> 2, sub = tid & 3;
        float m = -1e30f;
        for (int j = sub; j < JPAD; j += 4) m = fmaxf(m, S[j*SSTR + l]);
        m = fmaxf(m, __shfl_xor_sync(0xffffffffu, m, 1));
        m = fmaxf(m, __shfl_xor_sync(0xffffffffu, m, 2));
        float ssum = 0.f;
        for (int j = sub; j < JPAD; j += 4) {
            float e = __expf(S[j*SSTR + l] - m);
            S[j*SSTR + l] = e;
            ssum += e;
        }
        ssum += __shfl_xor_sync(0xffffffffu, ssum, 1);
        ssum += __shfl_xor_sync(0xffffffffu, ssum, 2);
        if (sub == 0) rinv[l] = 1.0f / ssum;
    }
    __syncthreads();

    float oacc[4][4];
    #pragma unroll
    for (int i = 0; i < 4; i++)
        #pragma unroll
        for (int j = 0; j < 4; j++) oacc[i][j] = 0.f;
    for (int t = 0; t < 11; t++) {
        const int jbase = t * 64;
        #pragma unroll
        for (int r = 0; r < 16; r++) {
            int idx = tid + r * 256;
            int jj = idx >> 6, d = idx & 63;
            int j = jbase + jj;
            Ts[jj*SSTR + d] = (j < NKV) ? vbase[(size_t)j * (2*H_) + d] : 0.f;
        }
        __syncthreads();
        #pragma unroll 8
        for (int jj = 0; jj < 64; jj++) {
            float4 p4 = *(const float4*)&S[(size_t)(jbase + jj)*SSTR + lt*4];
            float4 v4 = *(const float4*)&Ts[jj*SSTR + c4*4];
            float pa[4] = {p4.x, p4.y, p4.z, p4.w};
            float va[4] = {v4.x, v4.y, v4.z, v4.w};
            #pragma unroll
            for (int i = 0; i < 4; i++)
                #pragma unroll
                for (int j = 0; j < 4; j++)
                    oacc[i][j] = fmaf(pa[i], va[j], oacc[i][j]);
        }
        __syncthreads();
    }
    #pragma unroll
    for (int i = 0; i < 4; i++) {
        const int l = lt*4 + i;
        const float sc = rinv[l];
        #pragma unroll
        for (int j = 0; j < 4; j++) {
            const int d = c4*4 + j;
            Ot[((size_t)(b*NQ_ + l)) * H_ + h*HD_ + d] = oacc[i][j] * sc;
        }
    }
}

// ---------- LayerNorm ----------
__device__ inline void block_reduce_2(float& s, float& s2) {
    __shared__ float red[16];
    const int lane = threadIdx.x & 31, w = threadIdx.x >> 5;
    #pragma unroll
    for (int o = 16; o > 0; o >>= 1) {
        s  += __shfl_xor_sync(0xffffffffu, s,  o);
        s2 += __shfl_xor_sync(0xffffffffu, s2, o);
    }
    if (lane == 0) { red[w] = s; red[8 + w] = s2; }
    __syncthreads();
    if (threadIdx.x < 32) {
        s  = (lane < 8) ? red[lane]     : 0.f;
        s2 = (lane < 8) ? red[8 + lane] : 0.f;
        #pragma unroll
        for (int o = 4; o > 0; o >>= 1) {
            s  += __shfl_xor_sync(0xffffffffu, s,  o);
            s2 += __shfl_xor_sync(0xffffffffu, s2, o);
        }
        if (lane == 0) { red[0] = s; red[8] = s2; }
    }
    __syncthreads();
    s = red[0]; s2 = red[8];
}

__global__ __launch_bounds__(256)
void ln_h_kernel(const float* __restrict__ in, const float* __restrict__ g,
                 const float* __restrict__ beta, float* __restrict__ cat)
{
    const int r = blockIdx.x;
    const int b = r / N_, n = r % N_;
    const float* x = in + (size_t)r * H_;
    float* out = cat + ((size_t)b * NKV + n) * H_;
    float s = 0.f, s2 = 0.f;
    for (int i = threadIdx.x; i < H_; i += 256) { float v = x[i]; s += v; s2 += v*v; }
    block_reduce_2(s, s2);
    const float mean = s * (1.0f / H_);
    const float inv  = rsqrtf(s2 * (1.0f / H_) - mean * mean + 1e-5f);
    for (int i = threadIdx.x; i < H_; i += 256)
        out[i] = (x[i] - mean) * inv * g[i] + beta[i];
}

__global__ __launch_bounds__(256)
void ln_mod_kernel(const float* __restrict__ in, const float* __restrict__ g,
                   const float* __restrict__ beta, const float* __restrict__ emb,
                   int shOff, int scOff, float* __restrict__ out1,
                   float* __restrict__ out2)
{
    const int r = blockIdx.x;
    const int b = r >> 6, qrow = r & 63;
    const float* x  = in + (size_t)r * H_;
    const float* sh = emb + (size_t)b * (4*H_) + shOff;
    const float* sc = emb + (size_t)b * (4*H_) + scOff;
    float s = 0.f, s2 = 0.f;
    for (int i = threadIdx.x; i < H_; i += 256) { float v = x[i]; s += v; s2 += v*v; }
    block_reduce_2(s, s2);
    const float mean = s * (1.0f / H_);
    const float inv  = rsqrtf(s2 * (1.0f / H_) - mean * mean + 1e-5f);
    float* o1 = out1 + (size_t)r * H_;
    float* o2 = out2 ? out2 + ((size_t)b * NKV + N_ + qrow) * H_ : nullptr;
    for (int i = threadIdx.x; i < H_; i += 256) {
        float v = (x[i] - mean) * inv * g[i] + beta[i];
        v = v * (1.0f + sc[i]) + sh[i];
        o1[i] = v;
        if (o2) o2[i] = v;
    }
}

__global__ __launch_bounds__(256)
void ln_out_kernel(const float* __restrict__ in, const float* __restrict__ g,
                   const float* __restrict__ beta, float* __restrict__ out)
{
    const int r = blockIdx.x;
    const float* x = in + (size_t)r * O_;
    float s = 0.f, s2 = 0.f;
    for (int i = threadIdx.x; i < O_; i += 256) { float v = x[i]; s += v; s2 += v*v; }
    block_reduce_2(s, s2);
    const float mean = s * (1.0f / O_);
    const float inv  = rsqrtf(s2 * (1.0f / O_) - mean * mean + 1e-5f);
    float* o = out + (size_t)r * O_;
    for (int i = threadIdx.x; i < O_; i += 256)
        o[i] = (x[i] - mean) * inv * g[i] + beta[i];
}

// ---------- small kernels ----------
__global__ void time_proj_kernel(const float* __restrict__ t, float* __restrict__ tp)
{
    const int b = blockIdx.x, k = threadIdx.x;
    const float f = expf(-9.210340371976184f * (float)k / 160.0f);
    const float ang = t[b] * f;
    tp[b*TIN_ + k]       = cosf(ang);
    tp[b*TIN_ + 160 + k] = sinf(ang);
}
__global__ void silu_kernel(const float* __restrict__ in, float* __restrict__ out, int n)
{
    int i = blockIdx.x * blockDim.x + threadIdx.x;
    if (i < n) { float v = in[i]; out[i] = v / (1.0f + expf(-v)); }
}
__global__ void lat_init_kernel(const float* __restrict__ l0, float* __restrict__ lat)
{
    int i = blockIdx.x * blockDim.x + threadIdx.x;
    if (i < ML * H_) lat[i] = l0[i % (NQ_ * H_)];
}
__global__ void copy_kernel(const float* __restrict__ in, float* __restrict__ out, int n)
{
    int i = blockIdx.x * blockDim.x + threadIdx.x;
    if (i < n) out[i] = in[i];
}

// ---------- host driver ----------
static inline void run_mma(const bf16* Ah, const bf16* Al, const bf16* Bh, const bf16* Bl,
                           float* C, int M, int N, int K,
                           const float* bias, const float* extra, int mode)
{
    dim3 grid(N / 128, (M + 127) / 128);
    gemm_mma_kernel<<<grid, 256, GEMM_SMEM>>>(Ah, Al, Bh, Bl, C, M, N, K, bias, extra, mode);
}
static inline void run_split(const float* in, bf16* hi, bf16* lo, size_t n)
{
    split_kernel<<<(unsigned)((n/4 + 255)/256), 256>>>(in, hi, lo, (int)n);
}
static inline void run_tsplit(const float* W, bf16* Th, bf16* Tl, int K, int N)
{
    tsplit_kernel<<<dim3(N/32, K/32), dim3(32, 8)>>>(W, Th, Tl, K, N);
}

#define GSA(p, sym) cudaGetSymbolAddress((void**)&(p), sym)

extern "C" void kernel_launch(void* const* d_in, const int* in_sizes, int n_in,
                              void* d_out, int out_size)
{
    const float* x          = (const float*)d_in[0];
    const float* timestep   = (const float*)d_in[1];
    const float* latents0   = (const float*)d_in[2];
    const float* proj_in_W  = (const float*)d_in[3];
    const float* proj_in_b  = (const float*)d_in[4];
    const float* te1_W      = (const float*)d_in[5];
    const float* te1_b      = (const float*)d_in[6];
    const float* te2_W      = (const float*)d_in[7];
    const float* te2_b      = (const float*)d_in[8];
    const float* ln0_g      = (const float*)d_in[9];
    const float* ln0_b      = (const float*)d_in[10];
    const float* ln1_g      = (const float*)d_in[11];
    const float* ln1_b      = (const float*)d_in[12];
    const float* Wq         = (const float*)d_in[13];
    const float* Wkv        = (const float*)d_in[14];
    const float* Wo         = (const float*)d_in[15];
    const float* ada_W      = (const float*)d_in[16];
    const float* ada_b      = (const float*)d_in[17];
    const float* lnada_g    = (const float*)d_in[18];
    const float* lnada_b    = (const float*)d_in[19];
    const float* Wff1       = (const float*)d_in[20];
    const float* Wff2       = (const float*)d_in[21];
    const float* proj_out_W = (const float*)d_in[22];
    const float* proj_out_b = (const float*)d_in[23];
    const float* norm_out_g = (const float*)d_in[24];
    const float* norm_out_b = (const float*)d_in[25];

    float *tproj, *t1, *temb, *tsilu, *h, *cat, *kv, *lat, *lm, *q, *att, *ff, *emb, *obuf;
    GSA(tproj, g_tproj); GSA(t1, g_t1); GSA(temb, g_temb); GSA(tsilu, g_tsilu);
    GSA(h, g_h); GSA(cat, g_cat); GSA(kv, g_kv); GSA(lat, g_lat); GSA(lm, g_lm);
    GSA(q, g_q); GSA(att, g_att); GSA(ff, g_ff); GSA(emb, g_emb); GSA(obuf, g_obuf);

    bf16 *wpin_h,*wpin_l,*wte1_h,*wte1_l,*wte2_h,*wte2_l,*wq_h,*wq_l,*wkv_h,*wkv_l,
         *wo_h,*wo_l,*wada_h,*wada_l,*wff1_h,*wff1_l,*wff2_h,*wff2_l,*wpo_h,*wpo_l;
    GSA(wpin_h, g_wpin_h); GSA(wpin_l, g_wpin_l);
    GSA(wte1_h, g_wte1_h); GSA(wte1_l, g_wte1_l);
    GSA(wte2_h, g_wte2_h); GSA(wte2_l, g_wte2_l);
    GSA(wq_h, g_wq_h);     GSA(wq_l, g_wq_l);
    GSA(wkv_h, g_wkv_h);   GSA(wkv_l, g_wkv_l);
    GSA(wo_h, g_wo_h);     GSA(wo_l, g_wo_l);
    GSA(wada_h, g_wada_h); GSA(wada_l, g_wada_l);
    GSA(wff1_h, g_wff1_h); GSA(wff1_l, g_wff1_l);
    GSA(wff2_h, g_wff2_h); GSA(wff2_l, g_wff2_l);
    GSA(wpo_h, g_wpo_h);   GSA(wpo_l, g_wpo_l);

    bf16 *tph,*tpl,*t1h,*t1l,*tsh,*tsl,*xh,*xl,*cath,*catl,*lmh,*lml,*atth,*attl,*ffh,*ffl;
    GSA(tph, g_tp_h);   GSA(tpl, g_tp_l);
    GSA(t1h, g_t1_h);   GSA(t1l, g_t1_l);
    GSA(tsh, g_ts_h);   GSA(tsl, g_ts_l);
    GSA(xh, g_x_h);     GSA(xl, g_x_l);
    GSA(cath, g_cat_h); GSA(catl, g_cat_l);
    GSA(lmh, g_lm_h);   GSA(lml, g_lm_l);
    GSA(atth, g_att_h); GSA(attl, g_att_l);
    GSA(ffh, g_ff_h);   GSA(ffl, g_ff_l);

    cudaFuncSetAttribute(attn_kernel, cudaFuncAttributeMaxDynamicSharedMemorySize, SMEM_ATTN);
    cudaFuncSetAttribute(gemm_mma_kernel, cudaFuncAttributeMaxDynamicSharedMemorySize, GEMM_SMEM);

    // weight transpose+split
    run_tsplit(proj_in_W, wpin_h, wpin_l, E_, H_);
    run_tsplit(te1_W, wte1_h, wte1_l, TIN_, H_);
    run_tsplit(te2_W, wte2_h, wte2_l, H_, H_);
    for (int i = 0; i < DL; i++) {
        run_tsplit(Wq    + (size_t)i*H_*H_,    wq_h   + (size_t)i*H_*H_,   wq_l   + (size_t)i*H_*H_,   H_, H_);
        run_tsplit(Wkv   + (size_t)i*H_*2*H_,  wkv_h  + (size_t)i*2*H_*H_, wkv_l  + (size_t)i*2*H_*H_, H_, 2*H_);
        run_tsplit(Wo    + (size_t)i*H_*H_,    wo_h   + (size_t)i*H_*H_,   wo_l   + (size_t)i*H_*H_,   H_, H_);
        run_tsplit(ada_W + (size_t)i*H_*4*H_,  wada_h + (size_t)i*4*H_*H_, wada_l + (size_t)i*4*H_*H_, H_, 4*H_);
        run_tsplit(Wff1  + (size_t)i*H_*FF_,   wff1_h + (size_t)i*FF_*H_,  wff1_l + (size_t)i*FF_*H_,  H_, FF_);
        run_tsplit(Wff2  + (size_t)i*FF_*H_,   wff2_h + (size_t)i*H_*FF_,  wff2_l + (size_t)i*H_*FF_,  FF_, H_);
    }
    run_tsplit(proj_out_W, wpo_h, wpo_l, H_, O_);

    // time embedding
    time_proj_kernel<<<B_, 160>>>(timestep, tproj);
    run_split(tproj, tph, tpl, (size_t)B_*TIN_);
    run_mma(tph, tpl, wte1_h, wte1_l, t1, B_, H_, TIN_, te1_b, nullptr, MODE_BIAS_SILU);
    run_split(t1, t1h, t1l, (size_t)B_*H_);
    run_mma(t1h, t1l, wte2_h, wte2_l, temb, B_, H_, H_, te2_b, nullptr, MODE_BIAS);
    silu_kernel<<<(B_*H_ + 255)/256, 256>>>(temb, tsilu, B_*H_);
    run_split(tsilu, tsh, tsl, (size_t)B_*H_);

    // h = x @ proj_in_W + b + temb[batch]
    run_split(x, xh, xl, (size_t)MH*E_);
    run_mma(xh, xl, wpin_h, wpin_l, h, MH, H_, E_, proj_in_b, temb, MODE_BIAS_TEMB);

    lat_init_kernel<<<(ML*H_ + 255)/256, 256>>>(latents0, lat);

    for (int i = 0; i < DL; i++) {
        run_mma(tsh, tsl, wada_h + (size_t)i*4*H_*H_, wada_l + (size_t)i*4*H_*H_,
                emb, B_, 4*H_, H_, ada_b + (size_t)i*4*H_, nullptr, MODE_BIAS);

        ln_h_kernel<<<MH, 256>>>(h, ln0_g + i*H_, ln0_b + i*H_, cat);
        ln_mod_kernel<<<ML, 256>>>(lat, ln1_g + i*H_, ln1_b + i*H_, emb, 0, H_, lm, cat);
        run_split(cat, cath, catl, (size_t)MC*H_);
        run_split(lm, lmh, lml, (size_t)ML*H_);

        run_mma(lmh, lml, wq_h + (size_t)i*H_*H_, wq_l + (size_t)i*H_*H_,
                q, ML, H_, H_, nullptr, nullptr, MODE_NONE);
        run_mma(cath, catl, wkv_h + (size_t)i*2*H_*H_, wkv_l + (size_t)i*2*H_*H_,
                kv, MC, 2*H_, H_, nullptr, nullptr, MODE_NONE);

        attn_kernel<<<B_*NH_, 256, SMEM_ATTN>>>(q, kv, att);

        run_split(att, atth, attl, (size_t)ML*H_);
        run_mma(atth, attl, wo_h + (size_t)i*H_*H_, wo_l + (size_t)i*H_*H_,
                lat, ML, H_, H_, nullptr, lat, MODE_RES);

        ln_mod_kernel<<<ML, 256>>>(lat, lnada_g + i*H_, lnada_b + i*H_, emb, 2*H_, 3*H_, lm, nullptr);
        run_split(lm, lmh, lml, (size_t)ML*H_);
        run_mma(lmh, lml, wff1_h + (size_t)i*FF_*H_, wff1_l + (size_t)i*FF_*H_,
                ff, ML, FF_, H_, nullptr, nullptr, MODE_GELU);
        run_split(ff, ffh, ffl, (size_t)ML*FF_);
        run_mma(ffh, ffl, wff2_h + (size_t)i*H_*FF_, wff2_l + (size_t)i*H_*FF_,
                lat, ML, H_, FF_, nullptr, lat, MODE_RES);
    }

    run_split(lat, lmh, lml, (size_t)ML*H_);
    run_mma(lmh, lml, wpo_h, wpo_l, obuf, ML, O_, H_, proj_out_b, nullptr, MODE_BIAS);
    ln_out_kernel<<<ML, 256>>>(obuf, norm_out_g, norm_out_b, (float*)d_out);

    const int out0 = ML * O_;
    if (out_size >= out0 + B_*H_)
        copy_kernel<<<(B_*H_ + 255)/256, 256>>>(temb, (float*)d_out + out0, B_*H_);
}

// round 11
// speedup vs baseline: 2.8417x; 1.0579x over previous
#include <cuda_runtime.h>
#include <cuda_bf16.h>
#include <cstdint>

using bf16 = __nv_bfloat16;

#define E_    1152
#define H_    1280
#define O_    2432
#define DL    4
#define HD_   64
#define NH_   20
#define NQ_   64
#define TIN_  320
#define FF_   5120
#define B_    32
#define N_    577
#define NKV   641
#define MH    (B_*N_)
#define MC    (B_*NKV)
#define ML    (B_*NQ_)

// fp32 scratch (only where fp32 is actually consumed downstream)
__device__ float g_temb[B_*H_];
__device__ float g_h[(size_t)MH*H_];
__device__ float g_kv[(size_t)MC*2*H_];
__device__ float g_lat[(size_t)ML*H_];
__device__ float g_q[(size_t)ML*H_];
__device__ float g_emb[B_*4*H_];
__device__ float g_obuf[(size_t)ML*O_];

// bf16 weights transposed to [N,K], hi/lo
__device__ bf16 g_wpin_h[(size_t)H_*E_],      g_wpin_l[(size_t)H_*E_];
__device__ bf16 g_wte1_h[(size_t)H_*TIN_],    g_wte1_l[(size_t)H_*TIN_];
__device__ bf16 g_wte2_h[(size_t)H_*H_],      g_wte2_l[(size_t)H_*H_];
__device__ bf16 g_wq_h[(size_t)DL*H_*H_],     g_wq_l[(size_t)DL*H_*H_];
__device__ bf16 g_wkv_h[(size_t)DL*2*H_*H_],  g_wkv_l[(size_t)DL*2*H_*H_];
__device__ bf16 g_wo_h[(size_t)DL*H_*H_],     g_wo_l[(size_t)DL*H_*H_];
__device__ bf16 g_wada_h[(size_t)DL*4*H_*H_], g_wada_l[(size_t)DL*4*H_*H_];
__device__ bf16 g_wff1_h[(size_t)DL*FF_*H_],  g_wff1_l[(size_t)DL*FF_*H_];
__device__ bf16 g_wff2_h[(size_t)DL*H_*FF_],  g_wff2_l[(size_t)DL*H_*FF_];
__device__ bf16 g_wpo_h[(size_t)O_*H_],       g_wpo_l[(size_t)O_*H_];

// bf16 activations hi/lo
__device__ bf16 g_tp_h[B_*TIN_],        g_tp_l[B_*TIN_];
__device__ bf16 g_t1_h[B_*H_],          g_t1_l[B_*H_];
__device__ bf16 g_ts_h[B_*H_],          g_ts_l[B_*H_];
__device__ bf16 g_x_h[(size_t)MH*E_],   g_x_l[(size_t)MH*E_];
__device__ bf16 g_cat_h[(size_t)MC*H_], g_cat_l[(size_t)MC*H_];
__device__ bf16 g_lm_h[(size_t)ML*H_],  g_lm_l[(size_t)ML*H_];
__device__ bf16 g_att_h[(size_t)ML*H_], g_att_l[(size_t)ML*H_];
__device__ bf16 g_ff_h[(size_t)ML*FF_], g_ff_l[(size_t)ML*FF_];

#define MODE_NONE      0
#define MODE_BIAS      1
#define MODE_BIAS_SILU 3
#define MODE_GELU      4
#define MODE_RES       5

// ---------- PTX helpers (sm_80-portable; NO tcgen05 — ptxas targets sm_103) ----------
__device__ __forceinline__ uint32_t smem_u32(const void* p) {
    uint32_t a;
    asm("{ .reg .u64 t; cvta.to.shared.u64 t, %1; cvt.u32.u64 %0, t; }" : "=r"(a) : "l"(p));
    return a;
}
__device__ __forceinline__ void cp16(uint32_t dst, const void* src, int sz) {
    asm volatile("cp.async.cg.shared.global [%0], [%1], 16, %2;" :: "r"(dst), "l"(src), "r"(sz));
}
#define CP_COMMIT() asm volatile("cp.async.commit_group;" ::: "memory")

#define LDSM4(r, a) asm volatile( \
    "ldmatrix.sync.aligned.m8n8.x4.shared.b16 {%0,%1,%2,%3}, [%4];" \
    : "=r"((r)[0]), "=r"((r)[1]), "=r"((r)[2]), "=r"((r)[3]) : "r"(a))

#define MMA16816(d, a, b) asm volatile( \
    "mma.sync.aligned.m16n8k16.row.col.f32.bf16.bf16.f32 " \
    "{%0,%1,%2,%3}, {%4,%5,%6,%7}, {%8,%9}, {%0,%1,%2,%3};" \
    : "+f"((d)[0]), "+f"((d)[1]), "+f"((d)[2]), "+f"((d)[3]) \
    : "r"((a)[0]), "r"((a)[1]), "r"((a)[2]), "r"((a)[3]), "r"((b)[0]), "r"((b)[1]))

__device__ __forceinline__ void split2(float a, float b, __nv_bfloat162& hp, __nv_bfloat162& lp)
{
    bf16 h0 = __float2bfloat16(a), h1 = __float2bfloat16(b);
    hp.x = h0; hp.y = h1;
    lp.x = __float2bfloat16(a - __bfloat162float(h0));
    lp.y = __float2bfloat16(b - __bfloat162float(h1));
}

// ---------- bf16 3-split GEMM via mma.sync ----------
// C[M,N] = Ah@Bh^T + Ah@Bl^T + Al@Bh^T (+epilogue)
// A*: [M,K] bf16 row-major.  B*: [N,K] bf16 row-major (weights pre-transposed).
// CTA tile 128x128, BK=64, 8 warps (2x4), warp tile 64x32, 3-stage cp.async.
// osplit!=0: write hi/lo bf16 to Oh/Ol instead of fp32 C.
#define STAGE_BYTES 65536
#define GEMM_SMEM   (3*STAGE_BYTES)

__device__ __forceinline__ float epi(float v, int r, int c, int N,
                                     const float* __restrict__ bias,
                                     const float* __restrict__ extra, int mode)
{
    if (mode == MODE_BIAS) v += bias[c];
    else if (mode == MODE_BIAS_SILU) { float s = v + bias[c]; v = s / (1.0f + expf(-s)); }
    else if (mode == MODE_GELU) v = 0.5f * v * (1.0f + erff(v * 0.70710678118654752f));
    else if (mode == MODE_RES) v += extra[(size_t)r * N + c];
    return v;
}

__device__ __forceinline__ void g_load_stage(
    uint32_t base, const bf16* __restrict__ Ah, const bf16* __restrict__ Al,
    const bf16* __restrict__ Bh, const bf16* __restrict__ Bl,
    int row0, int col0, int M, int K, int kc, int tid)
{
    #pragma unroll
    for (int p = 0; p < 4; p++) {
        const int idx = tid + p * 256;
        const int r = idx >> 3, ch = idx & 7;
        const uint32_t dsw = (uint32_t)(r * 128 + ((ch ^ (r & 7)) << 4));
        const int ar = row0 + r, br = col0 + r;
        const size_t ao = (size_t)ar * K + kc + ch * 8;
        const size_t bo = (size_t)br * K + kc + ch * 8;
        const int asz = (ar < M) ? 16 : 0;
        cp16(base + dsw,         Ah + ao, asz);
        cp16(base + 16384 + dsw, Al + ao, asz);
        cp16(base + 32768 + dsw, Bh + bo, 16);
        cp16(base + 49152 + dsw, Bl + bo, 16);
    }
    CP_COMMIT();
}

__global__ __launch_bounds__(256)
void gemm_mma_kernel(const bf16* __restrict__ Ah, const bf16* __restrict__ Al,
                     const bf16* __restrict__ Bh, const bf16* __restrict__ Bl,
                     float* __restrict__ C, bf16* __restrict__ Oh, bf16* __restrict__ Ol,
                     int osplit, int M, int N, int K,
                     const float* __restrict__ bias, const float* __restrict__ extra,
                     int mode)
{
    extern __shared__ char smem[];
    const int tid = threadIdx.x;
    const int lane = tid & 31, wid = tid >> 5;
    const int wm = wid & 1, wn = wid >> 1;          // 2 x 4 warps
    const int row0 = blockIdx.y * 128, col0 = blockIdx.x * 128;
    const uint32_t sb = smem_u32(smem);

    float acc[4][4][4];
    #pragma unroll
    for (int a = 0; a < 4; a++)
        #pragma unroll
        for (int b = 0; b < 4; b++)
            #pragma unroll
            for (int c = 0; c < 4; c++) acc[a][b][c] = 0.f;

    const int NIT = K >> 6;

    g_load_stage(sb,               Ah, Al, Bh, Bl, row0, col0, M, K, 0,  tid);
    g_load_stage(sb + STAGE_BYTES, Ah, Al, Bh, Bl, row0, col0, M, K, 64, tid);

    int sidx = 0;
    for (int it = 0; it < NIT; it++) {
        if (it + 2 < NIT) {
            const int s2 = (it + 2) % 3;
            g_load_stage(sb + s2 * STAGE_BYTES, Ah, Al, Bh, Bl,
                         row0, col0, M, K, (it + 2) * 64, tid);
            asm volatile("cp.async.wait_group 2;" ::: "memory");
        } else if (it + 1 < NIT) {
            asm volatile("cp.async.wait_group 1;" ::: "memory");
        } else {
            asm volatile("cp.async.wait_group 0;" ::: "memory");
        }
        __syncthreads();

        const uint32_t aTh = sb + sidx * STAGE_BYTES;
        const uint32_t bTh = aTh + 32768;

        #pragma unroll
        for (int ks = 0; ks < 4; ks++) {
            uint32_t ahf[4][4], alf[4][4], bhf[2][4], blf[2][4];
            #pragma unroll
            for (int mt = 0; mt < 4; mt++) {
                const int r = wm * 64 + mt * 16 + (lane & 15);
                const int cch = ks * 2 + (lane >> 4);
                const uint32_t ad = aTh + r * 128 + ((cch ^ (r & 7)) << 4);
                LDSM4(ahf[mt], ad);
                LDSM4(alf[mt], ad + 16384);
            }
            #pragma unroll
            for (int n2 = 0; n2 < 2; n2++) {
                const int r = wn * 32 + n2 * 16 + (lane & 7) + ((lane >> 4) << 3);
                const int cch = ks * 2 + ((lane >> 3) & 1);
                const uint32_t ad = bTh + r * 128 + ((cch ^ (r & 7)) << 4);
                LDSM4(bhf[n2], ad);
                LDSM4(blf[n2], ad + 16384);
            }
            #pragma unroll
            for (int mt = 0; mt < 4; mt++)
                #pragma unroll
                for (int nt = 0; nt < 4; nt++) {
                    uint32_t* b2h = &bhf[nt >> 1][(nt & 1) << 1];
                    uint32_t* b2l = &blf[nt >> 1][(nt & 1) << 1];
                    MMA16816(acc[mt][nt], ahf[mt], b2h);
                    MMA16816(acc[mt][nt], ahf[mt], b2l);
                    MMA16816(acc[mt][nt], alf[mt], b2h);
                }
        }
        __syncthreads();
        if (++sidx == 3) sidx = 0;
    }

    const int g = lane >> 2, tg = lane & 3;
    #pragma unroll
    for (int mt = 0; mt < 4; mt++) {
        const int rb = row0 + wm * 64 + mt * 16 + g;
        #pragma unroll
        for (int nt = 0; nt < 4; nt++) {
            const int c = col0 + wn * 32 + nt * 8 + tg * 2;
            float* cc = acc[mt][nt];
            #pragma unroll
            for (int half = 0; half < 2; half++) {
                const int r = rb + half * 8;
                if (r >= M) continue;
                float v0 = epi(cc[half*2+0], r, c,     N, bias, extra, mode);
                float v1 = epi(cc[half*2+1], r, c + 1, N, bias, extra, mode);
                if (osplit) {
                    __nv_bfloat162 hp, lp;
                    split2(v0, v1, hp, lp);
                    *(__nv_bfloat162*)&Oh[(size_t)r * N + c] = hp;
                    *(__nv_bfloat162*)&Ol[(size_t)r * N + c] = lp;
                } else {
                    float2 v; v.x = v0; v.y = v1;
                    *(float2*)&C[(size_t)r * N + c] = v;
                }
            }
        }
    }
}

// ---------- split / transpose-split ----------
__global__ __launch_bounds__(256)
void split_kernel(const float* __restrict__ in, bf16* __restrict__ hi,
                  bf16* __restrict__ lo, int n)
{
    const int i = (blockIdx.x * blockDim.x + threadIdx.x) * 4;
    if (i >= n) return;
    float4 v = *(const float4*)(in + i);
    __nv_bfloat162 h01, h23, l01, l23;
    split2(v.x, v.y, h01, l01);
    split2(v.z, v.w, h23, l23);
    ((__nv_bfloat162*)(hi + i))[0] = h01;
    ((__nv_bfloat162*)(hi + i))[1] = h23;
    ((__nv_bfloat162*)(lo + i))[0] = l01;
    ((__nv_bfloat162*)(lo + i))[1] = l23;
}

__global__ __launch_bounds__(256)
void tsplit_kernel(const float* __restrict__ W, bf16* __restrict__ Th,
                   bf16* __restrict__ Tl, int K, int N)
{
    __shared__ float t[32][33];
    const int nb = blockIdx.x * 32, kb = blockIdx.y * 32;
    const int tx = threadIdx.x, ty = threadIdx.y;
    #pragma unroll
    for (int j = 0; j < 4; j++)
        t[ty + 8*j][tx] = W[(size_t)(kb + ty + 8*j) * N + nb + tx];
    __syncthreads();
    #pragma unroll
    for (int j = 0; j < 4; j++) {
        const int n = nb + ty + 8*j, k = kb + tx;
        const float v = t[tx][ty + 8*j];
        const bf16 h = __float2bfloat16(v);
        Th[(size_t)n * K + k] = h;
        Tl[(size_t)n * K + k] = __float2bfloat16(v - __bfloat162float(h));
    }
}

// ---------- attention (fp32 math, bf16 hi/lo output) ----------
#define JPAD 704
#define SSTR 68
#define SMEM_ATTN ((JPAD*SSTR + 64*SSTR + 64*SSTR + 64) * 4)

__global__ __launch_bounds__(256, 1)
void attn_kernel(const float* __restrict__ Q, const float* __restrict__ KV,
                 bf16* __restrict__ Oth, bf16* __restrict__ Otl)
{
    extern __shared__ float sm[];
    float* S    = sm;
    float* Qs   = S  + JPAD*SSTR;
    float* Ts   = Qs + 64*SSTR;
    float* rinv = Ts + 64*SSTR;

    const int tid = threadIdx.x;
    const int b   = blockIdx.x / NH_;
    const int h   = blockIdx.x % NH_;

    const float* qbase = Q  + ((size_t)b * NQ_) * H_ + h * HD_;
    const float* kbase = KV + ((size_t)b * NKV) * (2*H_) + h * HD_;
    const float* vbase = kbase + H_;

    #pragma unroll
    for (int r = 0; r < 16; r++) {
        int idx = tid + r * 256;
        int l = idx >> 6, d = idx & 63;
        Qs[d*SSTR + l] = qbase[(size_t)l * H_ + d];
    }
    const int lt = tid >> 4, c4 = tid & 15;

    for (int t = 0; t < 11; t++) {
        const int jbase = t * 64;
        #pragma unroll
        for (int r = 0; r < 16; r++) {
            int idx = tid + r * 256;
            int jj = idx >> 6, d = idx & 63;
            int j = jbase + jj;
            Ts[d*SSTR + jj] = (j < NKV) ? kbase[(size_t)j * (2*H_) + d] : 0.f;
        }
        __syncthreads();
        float acc[4][4];
        #pragma unroll
        for (int i = 0; i < 4; i++)
            #pragma unroll
            for (int j = 0; j < 4; j++) acc[i][j] = 0.f;
        #pragma unroll 8
        for (int d = 0; d < 64; d++) {
            float4 q4 = *(const float4*)&Qs[d*SSTR + lt*4];
            float4 k4 = *(const float4*)&Ts[d*SSTR + c4*4];
            float qa[4] = {q4.x, q4.y, q4.z, q4.w};
            float ka[4] = {k4.x, k4.y, k4.z, k4.w};
            #pragma unroll
            for (int i = 0; i < 4; i++)
                #pragma unroll
                for (int j = 0; j < 4; j++)
                    acc[i][j] = fmaf(qa[i], ka[j], acc[i][j]);
        }
        #pragma unroll
        for (int jj = 0; jj < 4; jj++) {
            const int j = jbase + c4*4 + jj;
            float4 w;
            if (j < NKV) {
                w.x = acc[0][jj]*0.125f; w.y = acc[1][jj]*0.125f;
                w.z = acc[2][jj]*0.125f; w.w = acc[3][jj]*0.125f;
            } else { w.x = w.y = w.z = w.w = -1e30f; }
            *(float4*)&S[(size_t)j*SSTR + lt*4] = w;
        }
        __syncthreads();
    }
    {
        const int l = tid >> 2, sub = tid & 3;
        float m = -1e30f;
        for (int j = sub; j < JPAD; j += 4) m = fmaxf(m, S[j*SSTR + l]);
        m = fmaxf(m, __shfl_xor_sync(0xffffffffu, m, 1));
        m = fmaxf(m, __shfl_xor_sync(0xffffffffu, m, 2));
        float ssum = 0.f;
        for (int j = sub; j < JPAD; j += 4) {
            float e = __expf(S[j*SSTR + l] - m);
            S[j*SSTR + l] = e;
            ssum += e;
        }
        ssum += __shfl_xor_sync(0xffffffffu, ssum, 1);
        ssum += __shfl_xor_sync(0xffffffffu, ssum, 2);
        if (sub == 0) rinv[l] = 1.0f / ssum;
    }
    __syncthreads();

    float oacc[4][4];
    #pragma unroll
    for (int i = 0; i < 4; i++)
        #pragma unroll
        for (int j = 0; j < 4; j++) oacc[i][j] = 0.f;
    for (int t = 0; t < 11; t++) {
        const int jbase = t * 64;
        #pragma unroll
        for (int r = 0; r < 16; r++) {
            int idx = tid + r * 256;
            int jj = idx >> 6, d = idx & 63;
            int j = jbase + jj;
            Ts[jj*SSTR + d] = (j < NKV) ? vbase[(size_t)j * (2*H_) + d] : 0.f;
        }
        __syncthreads();
        #pragma unroll 8
        for (int jj = 0; jj < 64; jj++) {
            float4 p4 = *(const float4*)&S[(size_t)(jbase + jj)*SSTR + lt*4];
            float4 v4 = *(const float4*)&Ts[jj*SSTR + c4*4];
            float pa[4] = {p4.x, p4.y, p4.z, p4.w};
            float va[4] = {v4.x, v4.y, v4.z, v4.w};
            #pragma unroll
            for (int i = 0; i < 4; i++)
                #pragma unroll
                for (int j = 0; j < 4; j++)
                    oacc[i][j] = fmaf(pa[i], va[j], oacc[i][j]);
        }
        __syncthreads();
    }
    #pragma unroll
    for (int i = 0; i < 4; i++) {
        const int l = lt*4 + i;
        const float sc = rinv[l];
        #pragma unroll
        for (int j = 0; j < 2; j++) {
            const int d = c4*4 + j*2;
            const size_t o = ((size_t)(b*NQ_ + l)) * H_ + h*HD_ + d;
            __nv_bfloat162 hp, lp;
            split2(oacc[i][j*2] * sc, oacc[i][j*2+1] * sc, hp, lp);
            *(__nv_bfloat162*)&Oth[o] = hp;
            *(__nv_bfloat162*)&Otl[o] = lp;
        }
    }
}

// ---------- LayerNorm ----------
__device__ inline void block_reduce_2(float& s, float& s2) {
    __shared__ float red[16];
    const int lane = threadIdx.x & 31, w = threadIdx.x >> 5;
    #pragma unroll
    for (int o = 16; o > 0; o >>= 1) {
        s  += __shfl_xor_sync(0xffffffffu, s,  o);
        s2 += __shfl_xor_sync(0xffffffffu, s2, o);
    }
    if (lane == 0) { red[w] = s; red[8 + w] = s2; }
    __syncthreads();
    if (threadIdx.x < 32) {
        s  = (lane < 8) ? red[lane]     : 0.f;
        s2 = (lane < 8) ? red[8 + lane] : 0.f;
        #pragma unroll
        for (int o = 4; o > 0; o >>= 1) {
            s  += __shfl_xor_sync(0xffffffffu, s,  o);
            s2 += __shfl_xor_sync(0xffffffffu, s2, o);
        }
        if (lane == 0) { red[0] = s; red[8] = s2; }
    }
    __syncthreads();
    s = red[0]; s2 = red[8];
}

// LN(h + temb[b]) rows -> cat rows [b*641 + n], bf16 hi/lo
__global__ __launch_bounds__(256)
void ln_h_kernel(const float* __restrict__ in, const float* __restrict__ temb,
                 const float* __restrict__ g, const float* __restrict__ beta,
                 bf16* __restrict__ outh, bf16* __restrict__ outl)
{
    const int r = blockIdx.x;
    const int b = r / N_, n = r % N_;
    const float* x  = in + (size_t)r * H_;
    const float* te = temb + (size_t)b * H_;
    const size_t ob = ((size_t)b * NKV + n) * H_;
    float s = 0.f, s2 = 0.f;
    for (int i = threadIdx.x*2; i < H_; i += 512) {
        float2 v = *(const float2*)(x + i);
        float2 t = *(const float2*)(te + i);
        float a0 = v.x + t.x, a1 = v.y + t.y;
        s += a0 + a1; s2 += a0*a0 + a1*a1;
    }
    block_reduce_2(s, s2);
    const float mean = s * (1.0f / H_);
    const float inv  = rsqrtf(s2 * (1.0f / H_) - mean * mean + 1e-5f);
    for (int i = threadIdx.x*2; i < H_; i += 512) {
        float2 v = *(const float2*)(x + i);
        float2 t = *(const float2*)(te + i);
        float2 gg = *(const float2*)(g + i);
        float2 bb = *(const float2*)(beta + i);
        float o0 = (v.x + t.x - mean) * inv * gg.x + bb.x;
        float o1 = (v.y + t.y - mean) * inv * gg.y + bb.y;
        __nv_bfloat162 hp, lp;
        split2(o0, o1, hp, lp);
        *(__nv_bfloat162*)&outh[ob + i] = hp;
        *(__nv_bfloat162*)&outl[ob + i] = lp;
    }
}

// LN(lat)*(1+sc)+sh -> lm hi/lo (+ optional cat rows hi/lo)
__global__ __launch_bounds__(256)
void ln_mod_kernel(const float* __restrict__ in, const float* __restrict__ g,
                   const float* __restrict__ beta, const float* __restrict__ emb,
                   int shOff, int scOff,
                   bf16* __restrict__ o1h, bf16* __restrict__ o1l,
                   bf16* __restrict__ o2h, bf16* __restrict__ o2l)
{
    const int r = blockIdx.x;
    const int b = r >> 6, qrow = r & 63;
    const float* x  = in + (size_t)r * H_;
    const float* sh = emb + (size_t)b * (4*H_) + shOff;
    const float* sc = emb + (size_t)b * (4*H_) + scOff;
    float s = 0.f, s2 = 0.f;
    for (int i = threadIdx.x*2; i < H_; i += 512) {
        float2 v = *(const float2*)(x + i);
        s += v.x + v.y; s2 += v.x*v.x + v.y*v.y;
    }
    block_reduce_2(s, s2);
    const float mean = s * (1.0f / H_);
    const float inv  = rsqrtf(s2 * (1.0f / H_) - mean * mean + 1e-5f);
    const size_t o1b = (size_t)r * H_;
    const size_t o2b = ((size_t)b * NKV + N_ + qrow) * H_;
    for (int i = threadIdx.x*2; i < H_; i += 512) {
        float2 v = *(const float2*)(x + i);
        float2 gg = *(const float2*)(g + i);
        float2 bb = *(const float2*)(beta + i);
        float2 ss = *(const float2*)(sc + i);
        float2 hh = *(const float2*)(sh + i);
        float o0 = ((v.x - mean) * inv * gg.x + bb.x) * (1.0f + ss.x) + hh.x;
        float o1 = ((v.y - mean) * inv * gg.y + bb.y) * (1.0f + ss.y) + hh.y;
        __nv_bfloat162 hp, lp;
        split2(o0, o1, hp, lp);
        *(__nv_bfloat162*)&o1h[o1b + i] = hp;
        *(__nv_bfloat162*)&o1l[o1b + i] = lp;
        if (o2h) {
            *(__nv_bfloat162*)&o2h[o2b + i] = hp;
            *(__nv_bfloat162*)&o2l[o2b + i] = lp;
        }
    }
}

__global__ __launch_bounds__(256)
void ln_out_kernel(const float* __restrict__ in, const float* __restrict__ g,
                   const float* __restrict__ beta, float* __restrict__ out)
{
    const int r = blockIdx.x;
    const float* x = in + (size_t)r * O_;
    float s = 0.f, s2 = 0.f;
    for (int i = threadIdx.x; i < O_; i += 256) { float v = x[i]; s += v; s2 += v*v; }
    block_reduce_2(s, s2);
    const float mean = s * (1.0f / O_);
    const float inv  = rsqrtf(s2 * (1.0f / O_) - mean * mean + 1e-5f);
    float* o = out + (size_t)r * O_;
    for (int i = threadIdx.x; i < O_; i += 256)
        o[i] = (x[i] - mean) * inv * g[i] + beta[i];
}

// ---------- small kernels ----------
__global__ void time_proj_kernel(const float* __restrict__ t,
                                 bf16* __restrict__ tph, bf16* __restrict__ tpl)
{
    const int b = blockIdx.x, k = threadIdx.x;
    const float f = expf(-9.210340371976184f * (float)k / 160.0f);
    const float ang = t[b] * f;
    const float c = cosf(ang), s = sinf(ang);
    bf16 ch = __float2bfloat16(c), sh = __float2bfloat16(s);
    tph[b*TIN_ + k]       = ch;
    tpl[b*TIN_ + k]       = __float2bfloat16(c - __bfloat162float(ch));
    tph[b*TIN_ + 160 + k] = sh;
    tpl[b*TIN_ + 160 + k] = __float2bfloat16(s - __bfloat162float(sh));
}
__global__ void silu_split_kernel(const float* __restrict__ in,
                                  bf16* __restrict__ hi, bf16* __restrict__ lo, int n)
{
    int i = blockIdx.x * blockDim.x + threadIdx.x;
    if (i < n) {
        float v = in[i];
        float s = v / (1.0f + expf(-v));
        bf16 h = __float2bfloat16(s);
        hi[i] = h;
        lo[i] = __float2bfloat16(s - __bfloat162float(h));
    }
}
__global__ void lat_init_kernel(const float* __restrict__ l0, float* __restrict__ lat)
{
    int i = blockIdx.x * blockDim.x + threadIdx.x;
    if (i < ML * H_) lat[i] = l0[i % (NQ_ * H_)];
}
__global__ void copy_kernel(const float* __restrict__ in, float* __restrict__ out, int n)
{
    int i = blockIdx.x * blockDim.x + threadIdx.x;
    if (i < n) out[i] = in[i];
}

// ---------- host driver ----------
static inline void run_mma(const bf16* Ah, const bf16* Al, const bf16* Bh, const bf16* Bl,
                           float* C, bf16* Oh, bf16* Ol, int osplit,
                           int M, int N, int K,
                           const float* bias, const float* extra, int mode)
{
    dim3 grid(N / 128, (M + 127) / 128);
    gemm_mma_kernel<<<grid, 256, GEMM_SMEM>>>(Ah, Al, Bh, Bl, C, Oh, Ol, osplit,
                                              M, N, K, bias, extra, mode);
}
static inline void run_split(const float* in, bf16* hi, bf16* lo, size_t n)
{
    split_kernel<<<(unsigned)((n/4 + 255)/256), 256>>>(in, hi, lo, (int)n);
}
static inline void run_tsplit(const float* W, bf16* Th, bf16* Tl, int K, int N)
{
    tsplit_kernel<<<dim3(N/32, K/32), dim3(32, 8)>>>(W, Th, Tl, K, N);
}

#define GSA(p, sym) cudaGetSymbolAddress((void**)&(p), sym)

extern "C" void kernel_launch(void* const* d_in, const int* in_sizes, int n_in,
                              void* d_out, int out_size)
{
    const float* x          = (const float*)d_in[0];
    const float* timestep   = (const float*)d_in[1];
    const float* latents0   = (const float*)d_in[2];
    const float* proj_in_W  = (const float*)d_in[3];
    const float* proj_in_b  = (const float*)d_in[4];
    const float* te1_W      = (const float*)d_in[5];
    const float* te1_b      = (const float*)d_in[6];
    const float* te2_W      = (const float*)d_in[7];
    const float* te2_b      = (const float*)d_in[8];
    const float* ln0_g      = (const float*)d_in[9];
    const float* ln0_b      = (const float*)d_in[10];
    const float* ln1_g      = (const float*)d_in[11];
    const float* ln1_b      = (const float*)d_in[12];
    const float* Wq         = (const float*)d_in[13];
    const float* Wkv        = (const float*)d_in[14];
    const float* Wo         = (const float*)d_in[15];
    const float* ada_W      = (const float*)d_in[16];
    const float* ada_b      = (const float*)d_in[17];
    const float* lnada_g    = (const float*)d_in[18];
    const float* lnada_b    = (const float*)d_in[19];
    const float* Wff1       = (const float*)d_in[20];
    const float* Wff2       = (const float*)d_in[21];
    const float* proj_out_W = (const float*)d_in[22];
    const float* proj_out_b = (const float*)d_in[23];
    const float* norm_out_g = (const float*)d_in[24];
    const float* norm_out_b = (const float*)d_in[25];

    float *temb, *h, *kv, *lat, *q, *emb, *obuf;
    GSA(temb, g_temb); GSA(h, g_h); GSA(kv, g_kv); GSA(lat, g_lat);
    GSA(q, g_q); GSA(emb, g_emb); GSA(obuf, g_obuf);

    bf16 *wpin_h,*wpin_l,*wte1_h,*wte1_l,*wte2_h,*wte2_l,*wq_h,*wq_l,*wkv_h,*wkv_l,
         *wo_h,*wo_l,*wada_h,*wada_l,*wff1_h,*wff1_l,*wff2_h,*wff2_l,*wpo_h,*wpo_l;
    GSA(wpin_h, g_wpin_h); GSA(wpin_l, g_wpin_l);
    GSA(wte1_h, g_wte1_h); GSA(wte1_l, g_wte1_l);
    GSA(wte2_h, g_wte2_h); GSA(wte2_l, g_wte2_l);
    GSA(wq_h, g_wq_h);     GSA(wq_l, g_wq_l);
    GSA(wkv_h, g_wkv_h);   GSA(wkv_l, g_wkv_l);
    GSA(wo_h, g_wo_h);     GSA(wo_l, g_wo_l);
    GSA(wada_h, g_wada_h); GSA(wada_l, g_wada_l);
    GSA(wff1_h, g_wff1_h); GSA(wff1_l, g_wff1_l);
    GSA(wff2_h, g_wff2_h); GSA(wff2_l, g_wff2_l);
    GSA(wpo_h, g_wpo_h);   GSA(wpo_l, g_wpo_l);

    bf16 *tph,*tpl,*t1h,*t1l,*tsh,*tsl,*xh,*xl,*cath,*catl,*lmh,*lml,*atth,*attl,*ffh,*ffl;
    GSA(tph, g_tp_h);   GSA(tpl, g_tp_l);
    GSA(t1h, g_t1_h);   GSA(t1l, g_t1_l);
    GSA(tsh, g_ts_h);   GSA(tsl, g_ts_l);
    GSA(xh, g_x_h);     GSA(xl, g_x_l);
    GSA(cath, g_cat_h); GSA(catl, g_cat_l);
    GSA(lmh, g_lm_h);   GSA(lml, g_lm_l);
    GSA(atth, g_att_h); GSA(attl, g_att_l);
    GSA(ffh, g_ff_h);   GSA(ffl, g_ff_l);

    cudaFuncSetAttribute(attn_kernel, cudaFuncAttributeMaxDynamicSharedMemorySize, SMEM_ATTN);
    cudaFuncSetAttribute(gemm_mma_kernel, cudaFuncAttributeMaxDynamicSharedMemorySize, GEMM_SMEM);

    // --- ordered so ncu's "-s 5 -c 1" captures the proj_in GEMM (launch idx 5) ---
    run_tsplit(proj_in_W, wpin_h, wpin_l, E_, H_);                     // 0
    run_split(x, xh, xl, (size_t)MH*E_);                               // 1
    time_proj_kernel<<<B_, 160>>>(timestep, tph, tpl);                 // 2
    run_tsplit(te1_W, wte1_h, wte1_l, TIN_, H_);                       // 3
    run_tsplit(te2_W, wte2_h, wte2_l, H_, H_);                         // 4
    run_mma(xh, xl, wpin_h, wpin_l, h, nullptr, nullptr, 0,            // 5 <- profiled
            MH, H_, E_, proj_in_b, nullptr, MODE_BIAS);

    // remaining weight transpose+split
    for (int i = 0; i < DL; i++) {
        run_tsplit(Wq    + (size_t)i*H_*H_,    wq_h   + (size_t)i*H_*H_,   wq_l   + (size_t)i*H_*H_,   H_, H_);
        run_tsplit(Wkv   + (size_t)i*H_*2*H_,  wkv_h  + (size_t)i*2*H_*H_, wkv_l  + (size_t)i*2*H_*H_, H_, 2*H_);
        run_tsplit(Wo    + (size_t)i*H_*H_,    wo_h   + (size_t)i*H_*H_,   wo_l   + (size_t)i*H_*H_,   H_, H_);
        run_tsplit(ada_W + (size_t)i*H_*4*H_,  wada_h + (size_t)i*4*H_*H_, wada_l + (size_t)i*4*H_*H_, H_, 4*H_);
        run_tsplit(Wff1  + (size_t)i*H_*FF_,   wff1_h + (size_t)i*FF_*H_,  wff1_l + (size_t)i*FF_*H_,  H_, FF_);
        run_tsplit(Wff2  + (size_t)i*FF_*H_,   wff2_h + (size_t)i*H_*FF_,  wff2_l + (size_t)i*H_*FF_,  FF_, H_);
    }
    run_tsplit(proj_out_W, wpo_h, wpo_l, H_, O_);

    // time embedding (t1 written split directly; temb kept fp32 for output & ln_h)
    run_mma(tph, tpl, wte1_h, wte1_l, nullptr, t1h, t1l, 1,
            B_, H_, TIN_, te1_b, nullptr, MODE_BIAS_SILU);
    run_mma(t1h, t1l, wte2_h, wte2_l, temb, nullptr, nullptr, 0,
            B_, H_, H_, te2_b, nullptr, MODE_BIAS);
    silu_split_kernel<<<(B_*H_ + 255)/256, 256>>>(temb, tsh, tsl, B_*H_);

    lat_init_kernel<<<(ML*H_ + 255)/256, 256>>>(latents0, lat);

    for (int i = 0; i < DL; i++) {
        run_mma(tsh, tsl, wada_h + (size_t)i*4*H_*H_, wada_l + (size_t)i*4*H_*H_,
                emb, nullptr, nullptr, 0, B_, 4*H_, H_,
                ada_b + (size_t)i*4*H_, nullptr, MODE_BIAS);

        // cat[:, :577] = LN(h + temb); cat[:, 577:] = lm (both written hi/lo directly)
        ln_h_kernel<<<MH, 256>>>(h, temb, ln0_g + i*H_, ln0_b + i*H_, cath, catl);
        ln_mod_kernel<<<ML, 256>>>(lat, ln1_g + i*H_, ln1_b + i*H_, emb, 0, H_,
                                   lmh, lml, cath, catl);

        run_mma(lmh, lml, wq_h + (size_t)i*H_*H_, wq_l + (size_t)i*H_*H_,
                q, nullptr, nullptr, 0, ML, H_, H_, nullptr, nullptr, MODE_NONE);
        run_mma(cath, catl, wkv_h + (size_t)i*2*H_*H_, wkv_l + (size_t)i*2*H_*H_,
                kv, nullptr, nullptr, 0, MC, 2*H_, H_, nullptr, nullptr, MODE_NONE);

        attn_kernel<<<B_*NH_, 256, SMEM_ATTN>>>(q, kv, atth, attl);

        run_mma(atth, attl, wo_h + (size_t)i*H_*H_, wo_l + (size_t)i*H_*H_,
                lat, nullptr, nullptr, 0, ML, H_, H_, nullptr, lat, MODE_RES);

        ln_mod_kernel<<<ML, 256>>>(lat, lnada_g + i*H_, lnada_b + i*H_, emb, 2*H_, 3*H_,
                                   lmh, lml, nullptr, nullptr);
        run_mma(lmh, lml, wff1_h + (size_t)i*FF_*H_, wff1_l + (size_t)i*FF_*H_,
                nullptr, ffh, ffl, 1, ML, FF_, H_, nullptr, nullptr, MODE_GELU);
        run_mma(ffh, ffl, wff2_h + (size_t)i*H_*FF_, wff2_l + (size_t)i*H_*FF_,
                lat, nullptr, nullptr, 0, ML, H_, FF_, nullptr, lat, MODE_RES);
    }

    run_split(lat, lmh, lml, (size_t)ML*H_);
    run_mma(lmh, lml, wpo_h, wpo_l, obuf, nullptr, nullptr, 0,
            ML, O_, H_, proj_out_b, nullptr, MODE_BIAS);
    ln_out_kernel<<<ML, 256>>>(obuf, norm_out_g, norm_out_b, (float*)d_out);

    const int out0 = ML * O_;
    if (out_size >= out0 + B_*H_)
        copy_kernel<<<(B_*H_ + 255)/256, 256>>>(temb, (float*)d_out + out0, B_*H_);
}

// round 12
// speedup vs baseline: 2.9119x; 1.0247x over previous
#include <cuda_runtime.h>
#include <cuda_bf16.h>
#include <cstdint>

using bf16 = __nv_bfloat16;

#define E_    1152
#define H_    1280
#define O_    2432
#define DL    4
#define HD_   64
#define NH_   20
#define NQ_   64
#define TIN_  320
#define FF_   5120
#define B_    32
#define N_    577
#define NKV   641
#define MH    (B_*N_)
#define MC    (B_*NKV)
#define ML    (B_*NQ_)

// fp32 scratch
__device__ float g_temb[B_*H_];
__device__ float g_h[(size_t)MH*H_];
__device__ float g_kv[(size_t)MC*2*H_];
__device__ float g_lat[(size_t)ML*H_];
__device__ float g_q[(size_t)ML*H_];
__device__ float g_emb[B_*4*H_];
__device__ float g_obuf[(size_t)ML*O_];
__device__ float g_bkv[DL*2*H_];

// bf16 weights transposed to [N,K], hi/lo
__device__ bf16 g_wpin_h[(size_t)H_*E_],      g_wpin_l[(size_t)H_*E_];
__device__ bf16 g_wte1_h[(size_t)H_*TIN_],    g_wte1_l[(size_t)H_*TIN_];
__device__ bf16 g_wte2_h[(size_t)H_*H_],      g_wte2_l[(size_t)H_*H_];
__device__ bf16 g_wq_h[(size_t)DL*H_*H_],     g_wq_l[(size_t)DL*H_*H_];
__device__ bf16 g_wkv_h[(size_t)DL*2*H_*H_],  g_wkv_l[(size_t)DL*2*H_*H_];
__device__ bf16 g_wkvS_h[(size_t)DL*2*H_*H_], g_wkvS_l[(size_t)DL*2*H_*H_];
__device__ bf16 g_wo_h[(size_t)DL*H_*H_],     g_wo_l[(size_t)DL*H_*H_];
__device__ bf16 g_wada_h[(size_t)DL*4*H_*H_], g_wada_l[(size_t)DL*4*H_*H_];
__device__ bf16 g_wff1_h[(size_t)DL*FF_*H_],  g_wff1_l[(size_t)DL*FF_*H_];
__device__ bf16 g_wff2_h[(size_t)DL*H_*FF_],  g_wff2_l[(size_t)DL*H_*FF_];
__device__ bf16 g_wpo_h[(size_t)O_*H_],       g_wpo_l[(size_t)O_*H_];

// bf16 activations hi/lo
__device__ bf16 g_tp_h[B_*TIN_],        g_tp_l[B_*TIN_];
__device__ bf16 g_t1_h[B_*H_],          g_t1_l[B_*H_];
__device__ bf16 g_ts_h[B_*H_],          g_ts_l[B_*H_];
__device__ bf16 g_x_h[(size_t)MH*E_],   g_x_l[(size_t)MH*E_];
__device__ bf16 g_hn_h[(size_t)MH*H_],  g_hn_l[(size_t)MH*H_];
__device__ bf16 g_lm_h[(size_t)ML*H_],  g_lm_l[(size_t)ML*H_];
__device__ bf16 g_att_h[(size_t)ML*H_], g_att_l[(size_t)ML*H_];
__device__ bf16 g_ff_h[(size_t)ML*FF_], g_ff_l[(size_t)ML*FF_];

#define MODE_NONE      0
#define MODE_BIAS      1
#define MODE_BIAS_SILU 3
#define MODE_GELU      4
#define MODE_RES       5

// ---------- PTX helpers ----------
__device__ __forceinline__ uint32_t smem_u32(const void* p) {
    uint32_t a;
    asm("{ .reg .u64 t; cvta.to.shared.u64 t, %1; cvt.u32.u64 %0, t; }" : "=r"(a) : "l"(p));
    return a;
}
__device__ __forceinline__ void cp16(uint32_t dst, const void* src, int sz) {
    asm volatile("cp.async.cg.shared.global [%0], [%1], 16, %2;" :: "r"(dst), "l"(src), "r"(sz));
}
#define CP_COMMIT() asm volatile("cp.async.commit_group;" ::: "memory")

#define LDSM4(r, a) asm volatile( \
    "ldmatrix.sync.aligned.m8n8.x4.shared.b16 {%0,%1,%2,%3}, [%4];" \
    : "=r"((r)[0]), "=r"((r)[1]), "=r"((r)[2]), "=r"((r)[3]) : "r"(a))

#define MMA16816(d, a, b) asm volatile( \
    "mma.sync.aligned.m16n8k16.row.col.f32.bf16.bf16.f32 " \
    "{%0,%1,%2,%3}, {%4,%5,%6,%7}, {%8,%9}, {%0,%1,%2,%3};" \
    : "+f"((d)[0]), "+f"((d)[1]), "+f"((d)[2]), "+f"((d)[3]) \
    : "r"((a)[0]), "r"((a)[1]), "r"((a)[2]), "r"((a)[3]), "r"((b)[0]), "r"((b)[1]))

__device__ __forceinline__ void split2(float a, float b, __nv_bfloat162& hp, __nv_bfloat162& lp)
{
    bf16 h0 = __float2bfloat16(a), h1 = __float2bfloat16(b);
    hp.x = h0; hp.y = h1;
    lp.x = __float2bfloat16(a - __bfloat162float(h0));
    lp.y = __float2bfloat16(b - __bfloat162float(h1));
}

// ---------- bf16 3-split GEMM via mma.sync (templated BM) ----------
// C[M,N] = Ah@Bh^T + Ah@Bl^T + Al@Bh^T (+epilogue)
// rowmap: 0 identity; 1 lm rows -> b*641+577+q; 2 h rows -> b*641+n
__device__ __forceinline__ float epi(float v, size_t crow, int c, int ldc,
                                     const float* __restrict__ bias,
                                     const float* __restrict__ extra, int mode)
{
    if (mode == MODE_BIAS) v += bias[c];
    else if (mode == MODE_BIAS_SILU) { float s = v + bias[c]; v = s / (1.0f + expf(-s)); }
    else if (mode == MODE_GELU) v = 0.5f * v * (1.0f + erff(v * 0.70710678118654752f));
    else if (mode == MODE_RES) v += extra[crow * ldc + c];
    return v;
}

template<int BM>
__device__ __forceinline__ void load_stage(
    uint32_t base, const bf16* __restrict__ Ah, const bf16* __restrict__ Al,
    const bf16* __restrict__ Bh, const bf16* __restrict__ Bl,
    int row0, int col0, int M, int K, int kc, int tid)
{
    #pragma unroll
    for (int idx = tid; idx < BM*8; idx += 256) {
        const int r = idx >> 3, ch = idx & 7;
        const uint32_t dsw = (uint32_t)(r * 128 + ((ch ^ (r & 7)) << 4));
        const int ar = row0 + r;
        const size_t ao = (size_t)ar * K + kc + ch * 8;
        const int asz = (ar < M) ? 16 : 0;
        cp16(base + dsw,            Ah + ao, asz);
        cp16(base + BM*128 + dsw,   Al + ao, asz);
    }
    #pragma unroll
    for (int idx = tid; idx < 1024; idx += 256) {
        const int r = idx >> 3, ch = idx & 7;
        const uint32_t dsw = (uint32_t)(r * 128 + ((ch ^ (r & 7)) << 4));
        const size_t bo = (size_t)(col0 + r) * K + kc + ch * 8;
        cp16(base + 2*BM*128 + dsw,         Bh + bo, 16);
        cp16(base + 2*BM*128 + 16384 + dsw, Bl + bo, 16);
    }
    CP_COMMIT();
}

template<int BM, int NST>
__global__ __launch_bounds__(256)
void gemm_mma_kernel(const bf16* __restrict__ Ah, const bf16* __restrict__ Al,
                     const bf16* __restrict__ Bh, const bf16* __restrict__ Bl,
                     float* __restrict__ C, bf16* __restrict__ Oh, bf16* __restrict__ Ol,
                     int osplit, int rowmap, int M, int N, int K, int ldc,
                     const float* __restrict__ bias, const float* __restrict__ extra,
                     int mode)
{
    extern __shared__ char smem[];
    constexpr int STAGE = 2*BM*128 + 32768;
    constexpr int WN = (BM == 128) ? 32 : 16;
    constexpr int NT = WN / 8;
    const int tid = threadIdx.x;
    const int lane = tid & 31, wid = tid >> 5;
    const int wm = (BM == 128) ? (wid & 1) : 0;
    const int wn = (BM == 128) ? (wid >> 1) : wid;
    const int row0 = blockIdx.y * BM, col0 = blockIdx.x * 128;
    const uint32_t sb = smem_u32(smem);

    float acc[4][NT][4];
    #pragma unroll
    for (int a = 0; a < 4; a++)
        #pragma unroll
        for (int b = 0; b < NT; b++)
            #pragma unroll
            for (int c = 0; c < 4; c++) acc[a][b][c] = 0.f;

    const int NIT = K >> 6;

    load_stage<BM>(sb, Ah, Al, Bh, Bl, row0, col0, M, K, 0, tid);
    if (NST == 3) load_stage<BM>(sb + STAGE, Ah, Al, Bh, Bl, row0, col0, M, K, 64, tid);

    int sidx = 0;
    for (int it = 0; it < NIT; it++) {
        if (it + NST - 1 < NIT) {
            load_stage<BM>(sb + ((it + NST - 1) % NST) * STAGE, Ah, Al, Bh, Bl,
                           row0, col0, M, K, (it + NST - 1) * 64, tid);
            if (NST == 3) asm volatile("cp.async.wait_group 2;" ::: "memory");
            else          asm volatile("cp.async.wait_group 1;" ::: "memory");
        } else if (NST == 3 && it + 1 < NIT) {
            asm volatile("cp.async.wait_group 1;" ::: "memory");
        } else {
            asm volatile("cp.async.wait_group 0;" ::: "memory");
        }
        __syncthreads();

        const uint32_t aTh = sb + sidx * STAGE;
        const uint32_t bTh = aTh + 2*BM*128;

        #pragma unroll
        for (int ks = 0; ks < 4; ks++) {
            uint32_t ahf[4][4], alf[4][4], bhf[NT/2][4], blf[NT/2][4];
            #pragma unroll
            for (int mt = 0; mt < 4; mt++) {
                const int r = wm * 64 + mt * 16 + (lane & 15);
                const int cch = ks * 2 + (lane >> 4);
                const uint32_t ad = aTh + r * 128 + ((cch ^ (r & 7)) << 4);
                LDSM4(ahf[mt], ad);
                LDSM4(alf[mt], ad + BM*128);
            }
            #pragma unroll
            for (int n2 = 0; n2 < NT/2; n2++) {
                const int r = wn * WN + n2 * 16 + (lane & 7) + ((lane >> 4) << 3);
                const int cch = ks * 2 + ((lane >> 3) & 1);
                const uint32_t ad = bTh + r * 128 + ((cch ^ (r & 7)) << 4);
                LDSM4(bhf[n2], ad);
                LDSM4(blf[n2], ad + 16384);
            }
            #pragma unroll
            for (int mt = 0; mt < 4; mt++)
                #pragma unroll
                for (int nt = 0; nt < NT; nt++) {
                    uint32_t* b2h = &bhf[nt >> 1][(nt & 1) << 1];
                    uint32_t* b2l = &blf[nt >> 1][(nt & 1) << 1];
                    MMA16816(acc[mt][nt], ahf[mt], b2h);
                    MMA16816(acc[mt][nt], ahf[mt], b2l);
                    MMA16816(acc[mt][nt], alf[mt], b2h);
                }
        }
        __syncthreads();
        if (++sidx == NST) sidx = 0;
    }

    const int g = lane >> 2, tg = lane & 3;
    #pragma unroll
    for (int mt = 0; mt < 4; mt++) {
        const int rb = row0 + wm * 64 + mt * 16 + g;
        #pragma unroll
        for (int nt = 0; nt < NT; nt++) {
            const int c = col0 + wn * WN + nt * 8 + tg * 2;
            float* cc = acc[mt][nt];
            #pragma unroll
            for (int half = 0; half < 2; half++) {
                const int r = rb + half * 8;
                if (r >= M) continue;
                size_t crow;
                if (rowmap == 1)      crow = (size_t)(r >> 6) * NKV + N_ + (r & 63);
                else if (rowmap == 2) crow = (size_t)(r / N_) * NKV + (r % N_);
                else                  crow = (size_t)r;
                float v0 = epi(cc[half*2+0], crow, c,     ldc, bias, extra, mode);
                float v1 = epi(cc[half*2+1], crow, c + 1, ldc, bias, extra, mode);
                if (osplit) {
                    __nv_bfloat162 hp, lp;
                    split2(v0, v1, hp, lp);
                    *(__nv_bfloat162*)&Oh[crow * ldc + c] = hp;
                    *(__nv_bfloat162*)&Ol[crow * ldc + c] = lp;
                } else {
                    float2 v; v.x = v0; v.y = v1;
                    *(float2*)&C[crow * ldc + c] = v;
                }
            }
        }
    }
}

// ---------- split / transpose-split ----------
__global__ __launch_bounds__(256)
void split_kernel(const float* __restrict__ in, bf16* __restrict__ hi,
                  bf16* __restrict__ lo, int n)
{
    const int i = (blockIdx.x * blockDim.x + threadIdx.x) * 4;
    if (i >= n) return;
    float4 v = *(const float4*)(in + i);
    __nv_bfloat162 h01, h23, l01, l23;
    split2(v.x, v.y, h01, l01);
    split2(v.z, v.w, h23, l23);
    ((__nv_bfloat162*)(hi + i))[0] = h01;
    ((__nv_bfloat162*)(hi + i))[1] = h23;
    ((__nv_bfloat162*)(lo + i))[0] = l01;
    ((__nv_bfloat162*)(lo + i))[1] = l23;
}

// W[K,N] -> [N,K] hi/lo; optional per-k scale g (g==nullptr -> 1)
__global__ __launch_bounds__(256)
void tsplit_kernel(const float* __restrict__ W, const float* __restrict__ g,
                   bf16* __restrict__ Th, bf16* __restrict__ Tl, int K, int N)
{
    __shared__ float t[32][33];
    const int nb = blockIdx.x * 32, kb = blockIdx.y * 32;
    const int tx = threadIdx.x, ty = threadIdx.y;
    #pragma unroll
    for (int j = 0; j < 4; j++)
        t[ty + 8*j][tx] = W[(size_t)(kb + ty + 8*j) * N + nb + tx];
    __syncthreads();
    const float gs = g ? g[kb + tx] : 1.0f;
    #pragma unroll
    for (int j = 0; j < 4; j++) {
        const int n = nb + ty + 8*j, k = kb + tx;
        const float v = t[tx][ty + 8*j] * gs;
        const bf16 h = __float2bfloat16(v);
        Th[(size_t)n * K + k] = h;
        Tl[(size_t)n * K + k] = __float2bfloat16(v - __bfloat162float(h));
    }
}

// out[n] = sum_k b[k] * W[k,n]
__global__ void colwsum_kernel(const float* __restrict__ b, const float* __restrict__ W,
                               int K, int N, float* __restrict__ out)
{
    const int n = blockIdx.x * 256 + threadIdx.x;
    if (n >= N) return;
    float s = 0.f;
    for (int k = 0; k < K; k++) s += b[k] * W[(size_t)k * N + n];
    out[n] = s;
}

// ---------- attention (fp32 math, bf16 hi/lo output) ----------
#define JPAD 704
#define SSTR 68
#define SMEM_ATTN ((JPAD*SSTR + 64*SSTR + 64*SSTR + 64) * 4)

__global__ __launch_bounds__(256, 1)
void attn_kernel(const float* __restrict__ Q, const float* __restrict__ KV,
                 bf16* __restrict__ Oth, bf16* __restrict__ Otl)
{
    extern __shared__ float sm[];
    float* S    = sm;
    float* Qs   = S  + JPAD*SSTR;
    float* Ts   = Qs + 64*SSTR;
    float* rinv = Ts + 64*SSTR;

    const int tid = threadIdx.x;
    const int b   = blockIdx.x / NH_;
    const int h   = blockIdx.x % NH_;

    const float* qbase = Q  + ((size_t)b * NQ_) * H_ + h * HD_;
    const float* kbase = KV + ((size_t)b * NKV) * (2*H_) + h * HD_;
    const float* vbase = kbase + H_;

    #pragma unroll
    for (int r = 0; r < 16; r++) {
        int idx = tid + r * 256;
        int l = idx >> 6, d = idx & 63;
        Qs[d*SSTR + l] = qbase[(size_t)l * H_ + d];
    }
    const int lt = tid >> 4, c4 = tid & 15;

    for (int t = 0; t < 11; t++) {
        const int jbase = t * 64;
        #pragma unroll
        for (int r = 0; r < 16; r++) {
            int idx = tid + r * 256;
            int jj = idx >> 6, d = idx & 63;
            int j = jbase + jj;
            Ts[d*SSTR + jj] = (j < NKV) ? kbase[(size_t)j * (2*H_) + d] : 0.f;
        }
        __syncthreads();
        float acc[4][4];
        #pragma unroll
        for (int i = 0; i < 4; i++)
            #pragma unroll
            for (int j = 0; j < 4; j++) acc[i][j] = 0.f;
        #pragma unroll 8
        for (int d = 0; d < 64; d++) {
            float4 q4 = *(const float4*)&Qs[d*SSTR + lt*4];
            float4 k4 = *(const float4*)&Ts[d*SSTR + c4*4];
            float qa[4] = {q4.x, q4.y, q4.z, q4.w};
            float ka[4] = {k4.x, k4.y, k4.z, k4.w};
            #pragma unroll
            for (int i = 0; i < 4; i++)
                #pragma unroll
                for (int j = 0; j < 4; j++)
                    acc[i][j] = fmaf(qa[i], ka[j], acc[i][j]);
        }
        #pragma unroll
        for (int jj = 0; jj < 4; jj++) {
            const int j = jbase + c4*4 + jj;
            float4 w;
            if (j < NKV) {
                w.x = acc[0][jj]*0.125f; w.y = acc[1][jj]*0.125f;
                w.z = acc[2][jj]*0.125f; w.w = acc[3][jj]*0.125f;
            } else { w.x = w.y = w.z = w.w = -1e30f; }
            *(float4*)&S[(size_t)j*SSTR + lt*4] = w;
        }
        __syncthreads();
    }
    {
        const int l = tid >> 2, sub = tid & 3;
        float m = -1e30f;
        for (int j = sub; j < JPAD; j += 4) m = fmaxf(m, S[j*SSTR + l]);
        m = fmaxf(m, __shfl_xor_sync(0xffffffffu, m, 1));
        m = fmaxf(m, __shfl_xor_sync(0xffffffffu, m, 2));
        float ssum = 0.f;
        for (int j = sub; j < JPAD; j += 4) {
            float e = __expf(S[j*SSTR + l] - m);
            S[j*SSTR + l] = e;
            ssum += e;
        }
        ssum += __shfl_xor_sync(0xffffffffu, ssum, 1);
        ssum += __shfl_xor_sync(0xffffffffu, ssum, 2);
        if (sub == 0) rinv[l] = 1.0f / ssum;
    }
    __syncthreads();

    float oacc[4][4];
    #pragma unroll
    for (int i = 0; i < 4; i++)
        #pragma unroll
        for (int j = 0; j < 4; j++) oacc[i][j] = 0.f;
    for (int t = 0; t < 11; t++) {
        const int jbase = t * 64;
        #pragma unroll
        for (int r = 0; r < 16; r++) {
            int idx = tid + r * 256;
            int jj = idx >> 6, d = idx & 63;
            int j = jbase + jj;
            Ts[jj*SSTR + d] = (j < NKV) ? vbase[(size_t)j * (2*H_) + d] : 0.f;
        }
        __syncthreads();
        #pragma unroll 8
        for (int jj = 0; jj < 64; jj++) {
            float4 p4 = *(const float4*)&S[(size_t)(jbase + jj)*SSTR + lt*4];
            float4 v4 = *(const float4*)&Ts[jj*SSTR + c4*4];
            float pa[4] = {p4.x, p4.y, p4.z, p4.w};
            float va[4] = {v4.x, v4.y, v4.z, v4.w};
            #pragma unroll
            for (int i = 0; i < 4; i++)
                #pragma unroll
                for (int j = 0; j < 4; j++)
                    oacc[i][j] = fmaf(pa[i], va[j], oacc[i][j]);
        }
        __syncthreads();
    }
    #pragma unroll
    for (int i = 0; i < 4; i++) {
        const int l = lt*4 + i;
        const float sc = rinv[l];
        #pragma unroll
        for (int j = 0; j < 2; j++) {
            const int d = c4*4 + j*2;
            const size_t o = ((size_t)(b*NQ_ + l)) * H_ + h*HD_ + d;
            __nv_bfloat162 hp, lp;
            split2(oacc[i][j*2] * sc, oacc[i][j*2+1] * sc, hp, lp);
            *(__nv_bfloat162*)&Oth[o] = hp;
            *(__nv_bfloat162*)&Otl[o] = lp;
        }
    }
}

// ---------- LayerNorm ----------
__device__ inline void block_reduce_2(float& s, float& s2) {
    __shared__ float red[16];
    const int lane = threadIdx.x & 31, w = threadIdx.x >> 5;
    #pragma unroll
    for (int o = 16; o > 0; o >>= 1) {
        s  += __shfl_xor_sync(0xffffffffu, s,  o);
        s2 += __shfl_xor_sync(0xffffffffu, s2, o);
    }
    if (lane == 0) { red[w] = s; red[8 + w] = s2; }
    __syncthreads();
    if (threadIdx.x < 32) {
        s  = (lane < 8) ? red[lane]     : 0.f;
        s2 = (lane < 8) ? red[8 + lane] : 0.f;
        #pragma unroll
        for (int o = 4; o > 0; o >>= 1) {
            s  += __shfl_xor_sync(0xffffffffu, s,  o);
            s2 += __shfl_xor_sync(0xffffffffu, s2, o);
        }
        if (lane == 0) { red[0] = s; red[8] = s2; }
    }
    __syncthreads();
    s = red[0]; s2 = red[8];
}

// hn = normalize(h + temb[b]) once -> hi/lo bf16 (gamma/beta folded into kv weights)
__global__ __launch_bounds__(256)
void ln_hn_kernel(const float* __restrict__ in, const float* __restrict__ temb,
                  bf16* __restrict__ outh, bf16* __restrict__ outl)
{
    const int r = blockIdx.x;
    const int b = r / N_;
    const float* x  = in + (size_t)r * H_;
    const float* te = temb + (size_t)b * H_;
    float s = 0.f, s2 = 0.f;
    for (int i = threadIdx.x*2; i < H_; i += 512) {
        float2 v = *(const float2*)(x + i);
        float2 t = *(const float2*)(te + i);
        float a0 = v.x + t.x, a1 = v.y + t.y;
        s += a0 + a1; s2 += a0*a0 + a1*a1;
    }
    block_reduce_2(s, s2);
    const float mean = s * (1.0f / H_);
    const float inv  = rsqrtf(s2 * (1.0f / H_) - mean * mean + 1e-5f);
    const size_t ob = (size_t)r * H_;
    for (int i = threadIdx.x*2; i < H_; i += 512) {
        float2 v = *(const float2*)(x + i);
        float2 t = *(const float2*)(te + i);
        float o0 = (v.x + t.x - mean) * inv;
        float o1 = (v.y + t.y - mean) * inv;
        __nv_bfloat162 hp, lp;
        split2(o0, o1, hp, lp);
        *(__nv_bfloat162*)&outh[ob + i] = hp;
        *(__nv_bfloat162*)&outl[ob + i] = lp;
    }
}

// LN(lat)*(1+sc)+sh -> lm hi/lo
__global__ __launch_bounds__(256)
void ln_mod_kernel(const float* __restrict__ in, const float* __restrict__ g,
                   const float* __restrict__ beta, const float* __restrict__ emb,
                   int shOff, int scOff,
                   bf16* __restrict__ o1h, bf16* __restrict__ o1l)
{
    const int r = blockIdx.x;
    const int b = r >> 6;
    const float* x  = in + (size_t)r * H_;
    const float* sh = emb + (size_t)b * (4*H_) + shOff;
    const float* sc = emb + (size_t)b * (4*H_) + scOff;
    float s = 0.f, s2 = 0.f;
    for (int i = threadIdx.x*2; i < H_; i += 512) {
        float2 v = *(const float2*)(x + i);
        s += v.x + v.y; s2 += v.x*v.x + v.y*v.y;
    }
    block_reduce_2(s, s2);
    const float mean = s * (1.0f / H_);
    const float inv  = rsqrtf(s2 * (1.0f / H_) - mean * mean + 1e-5f);
    const size_t o1b = (size_t)r * H_;
    for (int i = threadIdx.x*2; i < H_; i += 512) {
        float2 v = *(const float2*)(x + i);
        float2 gg = *(const float2*)(g + i);
        float2 bb = *(const float2*)(beta + i);
        float2 ss = *(const float2*)(sc + i);
        float2 hh = *(const float2*)(sh + i);
        float o0 = ((v.x - mean) * inv * gg.x + bb.x) * (1.0f + ss.x) + hh.x;
        float o1 = ((v.y - mean) * inv * gg.y + bb.y) * (1.0f + ss.y) + hh.y;
        __nv_bfloat162 hp, lp;
        split2(o0, o1, hp, lp);
        *(__nv_bfloat162*)&o1h[o1b + i] = hp;
        *(__nv_bfloat162*)&o1l[o1b + i] = lp;
    }
}

__global__ __launch_bounds__(256)
void ln_out_kernel(const float* __restrict__ in, const float* __restrict__ g,
                   const float* __restrict__ beta, float* __restrict__ out)
{
    const int r = blockIdx.x;
    const float* x = in + (size_t)r * O_;
    float s = 0.f, s2 = 0.f;
    for (int i = threadIdx.x; i < O_; i += 256) { float v = x[i]; s += v; s2 += v*v; }
    block_reduce_2(s, s2);
    const float mean = s * (1.0f / O_);
    const float inv  = rsqrtf(s2 * (1.0f / O_) - mean * mean + 1e-5f);
    float* o = out + (size_t)r * O_;
    for (int i = threadIdx.x; i < O_; i += 256)
        o[i] = (x[i] - mean) * inv * g[i] + beta[i];
}

// ---------- small kernels ----------
__global__ void time_proj_kernel(const float* __restrict__ t,
                                 bf16* __restrict__ tph, bf16* __restrict__ tpl)
{
    const int b = blockIdx.x, k = threadIdx.x;
    const float f = expf(-9.210340371976184f * (float)k / 160.0f);
    const float ang = t[b] * f;
    const float c = cosf(ang), s = sinf(ang);
    bf16 ch = __float2bfloat16(c), sh = __float2bfloat16(s);
    tph[b*TIN_ + k]       = ch;
    tpl[b*TIN_ + k]       = __float2bfloat16(c - __bfloat162float(ch));
    tph[b*TIN_ + 160 + k] = sh;
    tpl[b*TIN_ + 160 + k] = __float2bfloat16(s - __bfloat162float(sh));
}
__global__ void silu_split_kernel(const float* __restrict__ in,
                                  bf16* __restrict__ hi, bf16* __restrict__ lo, int n)
{
    int i = blockIdx.x * blockDim.x + threadIdx.x;
    if (i < n) {
        float v = in[i];
        float s = v / (1.0f + expf(-v));
        bf16 h = __float2bfloat16(s);
        hi[i] = h;
        lo[i] = __float2bfloat16(s - __bfloat162float(h));
    }
}
__global__ void lat_init_kernel(const float* __restrict__ l0, float* __restrict__ lat)
{
    int i = blockIdx.x * blockDim.x + threadIdx.x;
    if (i < ML * H_) lat[i] = l0[i % (NQ_ * H_)];
}
__global__ void copy_kernel(const float* __restrict__ in, float* __restrict__ out, int n)
{
    int i = blockIdx.x * blockDim.x + threadIdx.x;
    if (i < n) out[i] = in[i];
}

// ---------- host driver ----------
#define SMEM128 (3*(2*128*128 + 32768))
#define SMEM64  (2*(2*64*128 + 32768))

static inline void run_mma(int BM, const bf16* Ah, const bf16* Al,
                           const bf16* Bh, const bf16* Bl,
                           float* C, bf16* Oh, bf16* Ol, int osplit, int rowmap,
                           int M, int N, int K, int ldc,
                           const float* bias, const float* extra, int mode)
{
    dim3 grid(N / 128, (M + BM - 1) / BM);
    if (BM == 128)
        gemm_mma_kernel<128,3><<<grid, 256, SMEM128>>>(Ah, Al, Bh, Bl, C, Oh, Ol,
            osplit, rowmap, M, N, K, ldc, bias, extra, mode);
    else
        gemm_mma_kernel<64,2><<<grid, 256, SMEM64>>>(Ah, Al, Bh, Bl, C, Oh, Ol,
            osplit, rowmap, M, N, K, ldc, bias, extra, mode);
}
static inline void run_split(const float* in, bf16* hi, bf16* lo, size_t n)
{
    split_kernel<<<(unsigned)((n/4 + 255)/256), 256>>>(in, hi, lo, (int)n);
}
static inline void run_tsplit(const float* W, const float* g, bf16* Th, bf16* Tl, int K, int N)
{
    tsplit_kernel<<<dim3(N/32, K/32), dim3(32, 8)>>>(W, g, Th, Tl, K, N);
}

#define GSA(p, sym) cudaGetSymbolAddress((void**)&(p), sym)

extern "C" void kernel_launch(void* const* d_in, const int* in_sizes, int n_in,
                              void* d_out, int out_size)
{
    const float* x          = (const float*)d_in[0];
    const float* timestep   = (const float*)d_in[1];
    const float* latents0   = (const float*)d_in[2];
    const float* proj_in_W  = (const float*)d_in[3];
    const float* proj_in_b  = (const float*)d_in[4];
    const float* te1_W      = (const float*)d_in[5];
    const float* te1_b      = (const float*)d_in[6];
    const float* te2_W      = (const float*)d_in[7];
    const float* te2_b      = (const float*)d_in[8];
    const float* ln0_g      = (const float*)d_in[9];
    const float* ln0_b      = (const float*)d_in[10];
    const float* ln1_g      = (const float*)d_in[11];
    const float* ln1_b      = (const float*)d_in[12];
    const float* Wq         = (const float*)d_in[13];
    const float* Wkv        = (const float*)d_in[14];
    const float* Wo         = (const float*)d_in[15];
    const float* ada_W      = (const float*)d_in[16];
    const float* ada_b      = (const float*)d_in[17];
    const float* lnada_g    = (const float*)d_in[18];
    const float* lnada_b    = (const float*)d_in[19];
    const float* Wff1       = (const float*)d_in[20];
    const float* Wff2       = (const float*)d_in[21];
    const float* proj_out_W = (const float*)d_in[22];
    const float* proj_out_b = (const float*)d_in[23];
    const float* norm_out_g = (const float*)d_in[24];
    const float* norm_out_b = (const float*)d_in[25];

    float *temb, *h, *kv, *lat, *q, *emb, *obuf, *bkv;
    GSA(temb, g_temb); GSA(h, g_h); GSA(kv, g_kv); GSA(lat, g_lat);
    GSA(q, g_q); GSA(emb, g_emb); GSA(obuf, g_obuf); GSA(bkv, g_bkv);

    bf16 *wpin_h,*wpin_l,*wte1_h,*wte1_l,*wte2_h,*wte2_l,*wq_h,*wq_l,*wkv_h,*wkv_l,
         *wkvS_h,*wkvS_l,*wo_h,*wo_l,*wada_h,*wada_l,*wff1_h,*wff1_l,*wff2_h,*wff2_l,
         *wpo_h,*wpo_l;
    GSA(wpin_h, g_wpin_h); GSA(wpin_l, g_wpin_l);
    GSA(wte1_h, g_wte1_h); GSA(wte1_l, g_wte1_l);
    GSA(wte2_h, g_wte2_h); GSA(wte2_l, g_wte2_l);
    GSA(wq_h, g_wq_h);     GSA(wq_l, g_wq_l);
    GSA(wkv_h, g_wkv_h);   GSA(wkv_l, g_wkv_l);
    GSA(wkvS_h, g_wkvS_h); GSA(wkvS_l, g_wkvS_l);
    GSA(wo_h, g_wo_h);     GSA(wo_l, g_wo_l);
    GSA(wada_h, g_wada_h); GSA(wada_l, g_wada_l);
    GSA(wff1_h, g_wff1_h); GSA(wff1_l, g_wff1_l);
    GSA(wff2_h, g_wff2_h); GSA(wff2_l, g_wff2_l);
    GSA(wpo_h, g_wpo_h);   GSA(wpo_l, g_wpo_l);

    bf16 *tph,*tpl,*t1h,*t1l,*tsh,*tsl,*xh,*xl,*hnh,*hnl,*lmh,*lml,*atth,*attl,*ffh,*ffl;
    GSA(tph, g_tp_h);   GSA(tpl, g_tp_l);
    GSA(t1h, g_t1_h);   GSA(t1l, g_t1_l);
    GSA(tsh, g_ts_h);   GSA(tsl, g_ts_l);
    GSA(xh, g_x_h);     GSA(xl, g_x_l);
    GSA(hnh, g_hn_h);   GSA(hnl, g_hn_l);
    GSA(lmh, g_lm_h);   GSA(lml, g_lm_l);
    GSA(atth, g_att_h); GSA(attl, g_att_l);
    GSA(ffh, g_ff_h);   GSA(ffl, g_ff_l);

    cudaFuncSetAttribute(attn_kernel, cudaFuncAttributeMaxDynamicSharedMemorySize, SMEM_ATTN);
    cudaFuncSetAttribute(gemm_mma_kernel<128,3>, cudaFuncAttributeMaxDynamicSharedMemorySize, SMEM128);
    cudaFuncSetAttribute(gemm_mma_kernel<64,2>,  cudaFuncAttributeMaxDynamicSharedMemorySize, SMEM64);

    // --- launches 0-1: deps for proj_in GEMM; 2-6: GEMM col-chunks (ncu target) ---
    run_tsplit(proj_in_W, nullptr, wpin_h, wpin_l, E_, H_);            // 0
    run_split(x, xh, xl, (size_t)MH*E_);                               // 1
    for (int cc = 0; cc < 5; cc++) {                                   // 2..6
        run_mma(128, xh, xl, wpin_h + (size_t)cc*256*E_, wpin_l + (size_t)cc*256*E_,
                h + cc*256, nullptr, nullptr, 0, 0,
                MH, 256, E_, H_, proj_in_b + cc*256, nullptr, MODE_BIAS);
    }

    // time embedding
    time_proj_kernel<<<B_, 160>>>(timestep, tph, tpl);
    run_tsplit(te1_W, nullptr, wte1_h, wte1_l, TIN_, H_);
    run_tsplit(te2_W, nullptr, wte2_h, wte2_l, H_, H_);
    run_mma(64, tph, tpl, wte1_h, wte1_l, nullptr, t1h, t1l, 1, 0,
            B_, H_, TIN_, H_, te1_b, nullptr, MODE_BIAS_SILU);
    run_mma(64, t1h, t1l, wte2_h, wte2_l, temb, nullptr, nullptr, 0, 0,
            B_, H_, H_, H_, te2_b, nullptr, MODE_BIAS);
    silu_split_kernel<<<(B_*H_ + 255)/256, 256>>>(temb, tsh, tsl, B_*H_);

    // hn = normalize(h + temb) once, hi/lo
    ln_hn_kernel<<<MH, 256>>>(h, temb, hnh, hnl);
    lat_init_kernel<<<(ML*H_ + 255)/256, 256>>>(latents0, lat);

    // per-layer weight prep
    for (int i = 0; i < DL; i++) {
        run_tsplit(Wq    + (size_t)i*H_*H_,   nullptr,    wq_h   + (size_t)i*H_*H_,   wq_l   + (size_t)i*H_*H_,   H_, H_);
        run_tsplit(Wkv   + (size_t)i*H_*2*H_, nullptr,    wkv_h  + (size_t)i*2*H_*H_, wkv_l  + (size_t)i*2*H_*H_, H_, 2*H_);
        run_tsplit(Wkv   + (size_t)i*H_*2*H_, ln0_g+i*H_, wkvS_h + (size_t)i*2*H_*H_, wkvS_l + (size_t)i*2*H_*H_, H_, 2*H_);
        colwsum_kernel<<<(2*H_+255)/256, 256>>>(ln0_b + i*H_, Wkv + (size_t)i*H_*2*H_,
                                                H_, 2*H_, bkv + i*2*H_);
        run_tsplit(Wo    + (size_t)i*H_*H_,   nullptr, wo_h   + (size_t)i*H_*H_,   wo_l   + (size_t)i*H_*H_,   H_, H_);
        run_tsplit(ada_W + (size_t)i*H_*4*H_, nullptr, wada_h + (size_t)i*4*H_*H_, wada_l + (size_t)i*4*H_*H_, H_, 4*H_);
        run_tsplit(Wff1  + (size_t)i*H_*FF_,  nullptr, wff1_h + (size_t)i*FF_*H_,  wff1_l + (size_t)i*FF_*H_,  H_, FF_);
        run_tsplit(Wff2  + (size_t)i*FF_*H_,  nullptr, wff2_h + (size_t)i*H_*FF_,  wff2_l + (size_t)i*H_*FF_,  FF_, H_);
    }
    run_tsplit(proj_out_W, nullptr, wpo_h, wpo_l, H_, O_);

    for (int i = 0; i < DL; i++) {
        run_mma(64, tsh, tsl, wada_h + (size_t)i*4*H_*H_, wada_l + (size_t)i*4*H_*H_,
                emb, nullptr, nullptr, 0, 0, B_, 4*H_, H_, 4*H_,
                ada_b + (size_t)i*4*H_, nullptr, MODE_BIAS);

        ln_mod_kernel<<<ML, 256>>>(lat, ln1_g + i*H_, ln1_b + i*H_, emb, 0, H_, lmh, lml);

        run_mma(64, lmh, lml, wq_h + (size_t)i*H_*H_, wq_l + (size_t)i*H_*H_,
                q, nullptr, nullptr, 0, 0, ML, H_, H_, H_, nullptr, nullptr, MODE_NONE);
        // kv h-rows: hn @ (g*Wkv) + b@Wkv, remapped to b*641+n
        run_mma(128, hnh, hnl, wkvS_h + (size_t)i*2*H_*H_, wkvS_l + (size_t)i*2*H_*H_,
                kv, nullptr, nullptr, 0, 2, MH, 2*H_, H_, 2*H_,
                bkv + i*2*H_, nullptr, MODE_BIAS);
        // kv lm-rows: lm @ Wkv, remapped to b*641+577+q
        run_mma(64, lmh, lml, wkv_h + (size_t)i*2*H_*H_, wkv_l + (size_t)i*2*H_*H_,
                kv, nullptr, nullptr, 0, 1, ML, 2*H_, H_, 2*H_,
                nullptr, nullptr, MODE_NONE);

        attn_kernel<<<B_*NH_, 256, SMEM_ATTN>>>(q, kv, atth, attl);

        run_mma(64, atth, attl, wo_h + (size_t)i*H_*H_, wo_l + (size_t)i*H_*H_,
                lat, nullptr, nullptr, 0, 0, ML, H_, H_, H_, nullptr, lat, MODE_RES);

        ln_mod_kernel<<<ML, 256>>>(lat, lnada_g + i*H_, lnada_b + i*H_, emb, 2*H_, 3*H_,
                                   lmh, lml);
        run_mma(64, lmh, lml, wff1_h + (size_t)i*FF_*H_, wff1_l + (size_t)i*FF_*H_,
                nullptr, ffh, ffl, 1, 0, ML, FF_, H_, FF_, nullptr, nullptr, MODE_GELU);
        run_mma(64, ffh, ffl, wff2_h + (size_t)i*H_*FF_, wff2_l + (size_t)i*H_*FF_,
                lat, nullptr, nullptr, 0, 0, ML, H_, FF_, H_, nullptr, lat, MODE_RES);
    }

    run_split(lat, lmh, lml, (size_t)ML*H_);
    run_mma(64, lmh, lml, wpo_h, wpo_l, obuf, nullptr, nullptr, 0, 0,
            ML, O_, H_, O_, proj_out_b, nullptr, MODE_BIAS);
    ln_out_kernel<<<ML, 256>>>(obuf, norm_out_g, norm_out_b, (float*)d_out);

    const int out0 = ML * O_;
    if (out_size >= out0 + B_*H_)
        copy_kernel<<<(B_*H_ + 255)/256, 256>>>(temb, (float*)d_out + out0, B_*H_);
}

// round 13
// speedup vs baseline: 3.0969x; 1.0635x over previous
#include <cuda_runtime.h>
#include <cuda_bf16.h>
#include <cstdint>

using bf16 = __nv_bfloat16;

#define E_    1152
#define H_    1280
#define O_    2432
#define DL    4
#define HD_   64
#define NH_   20
#define NQ_   64
#define TIN_  320
#define FF_   5120
#define B_    32
#define N_    577
#define NKV   641
#define MH    (B_*N_)
#define MC    (B_*NKV)
#define ML    (B_*NQ_)

// fp32 scratch
__device__ float g_temb[B_*H_];
__device__ float g_h[(size_t)MH*H_];
__device__ float g_kv[(size_t)MC*2*H_];
__device__ float g_lat[(size_t)ML*H_];
__device__ float g_q[(size_t)ML*H_];
__device__ float g_emb[B_*4*H_];
__device__ float g_obuf[(size_t)ML*O_];
__device__ float g_bkv[DL*2*H_];

// bf16 weights transposed to [N,K], hi/lo
__device__ bf16 g_wpin_h[(size_t)H_*E_],      g_wpin_l[(size_t)H_*E_];
__device__ bf16 g_wte1_h[(size_t)H_*TIN_],    g_wte1_l[(size_t)H_*TIN_];
__device__ bf16 g_wte2_h[(size_t)H_*H_],      g_wte2_l[(size_t)H_*H_];
__device__ bf16 g_wq_h[(size_t)DL*H_*H_],     g_wq_l[(size_t)DL*H_*H_];
__device__ bf16 g_wkv_h[(size_t)DL*2*H_*H_],  g_wkv_l[(size_t)DL*2*H_*H_];
__device__ bf16 g_wkvS_h[(size_t)DL*2*H_*H_], g_wkvS_l[(size_t)DL*2*H_*H_];
__device__ bf16 g_wo_h[(size_t)DL*H_*H_],     g_wo_l[(size_t)DL*H_*H_];
__device__ bf16 g_wada_h[(size_t)DL*4*H_*H_], g_wada_l[(size_t)DL*4*H_*H_];
__device__ bf16 g_wff1_h[(size_t)DL*FF_*H_],  g_wff1_l[(size_t)DL*FF_*H_];
__device__ bf16 g_wff2_h[(size_t)DL*H_*FF_],  g_wff2_l[(size_t)DL*H_*FF_];
__device__ bf16 g_wpo_h[(size_t)O_*H_],       g_wpo_l[(size_t)O_*H_];

// bf16 activations hi/lo
__device__ bf16 g_tp_h[B_*TIN_],        g_tp_l[B_*TIN_];
__device__ bf16 g_t1_h[B_*H_],          g_t1_l[B_*H_];
__device__ bf16 g_ts_h[B_*H_],          g_ts_l[B_*H_];
__device__ bf16 g_x_h[(size_t)MH*E_],   g_x_l[(size_t)MH*E_];
__device__ bf16 g_hn_h[(size_t)MH*H_],  g_hn_l[(size_t)MH*H_];
__device__ bf16 g_lm_h[(size_t)ML*H_],  g_lm_l[(size_t)ML*H_];
__device__ bf16 g_att_h[(size_t)ML*H_], g_att_l[(size_t)ML*H_];
__device__ bf16 g_ff_h[(size_t)ML*FF_], g_ff_l[(size_t)ML*FF_];

#define MODE_NONE      0
#define MODE_BIAS      1
#define MODE_BIAS_SILU 3
#define MODE_GELU      4
#define MODE_RES       5

// ---------- PTX helpers ----------
__device__ __forceinline__ uint32_t smem_u32(const void* p) {
    uint32_t a;
    asm("{ .reg .u64 t; cvta.to.shared.u64 t, %1; cvt.u32.u64 %0, t; }" : "=r"(a) : "l"(p));
    return a;
}
__device__ __forceinline__ void cp16(uint32_t dst, const void* src, int sz) {
    asm volatile("cp.async.cg.shared.global [%0], [%1], 16, %2;" :: "r"(dst), "l"(src), "r"(sz));
}
#define CP_COMMIT() asm volatile("cp.async.commit_group;" ::: "memory")

#define LDSM4(r, a) asm volatile( \
    "ldmatrix.sync.aligned.m8n8.x4.shared.b16 {%0,%1,%2,%3}, [%4];" \
    : "=r"((r)[0]), "=r"((r)[1]), "=r"((r)[2]), "=r"((r)[3]) : "r"(a))

#define MMA16816(d, a, b) asm volatile( \
    "mma.sync.aligned.m16n8k16.row.col.f32.bf16.bf16.f32 " \
    "{%0,%1,%2,%3}, {%4,%5,%6,%7}, {%8,%9}, {%0,%1,%2,%3};" \
    : "+f"((d)[0]), "+f"((d)[1]), "+f"((d)[2]), "+f"((d)[3]) \
    : "r"((a)[0]), "r"((a)[1]), "r"((a)[2]), "r"((a)[3]), "r"((b)[0]), "r"((b)[1]))

__device__ __forceinline__ void split2(float a, float b, __nv_bfloat162& hp, __nv_bfloat162& lp)
{
    bf16 h0 = __float2bfloat16(a), h1 = __float2bfloat16(b);
    hp.x = h0; hp.y = h1;
    lp.x = __float2bfloat16(a - __bfloat162float(h0));
    lp.y = __float2bfloat16(b - __bfloat162float(h1));
}

// ---------- bf16 3-split GEMM via mma.sync (templated BM) ----------
__device__ __forceinline__ float epi(float v, size_t crow, int c, int ldc,
                                     const float* __restrict__ bias,
                                     const float* __restrict__ extra, int mode)
{
    if (mode == MODE_BIAS) v += bias[c];
    else if (mode == MODE_BIAS_SILU) { float s = v + bias[c]; v = s / (1.0f + expf(-s)); }
    else if (mode == MODE_GELU) v = 0.5f * v * (1.0f + erff(v * 0.70710678118654752f));
    else if (mode == MODE_RES) v += extra[crow * ldc + c];
    return v;
}

template<int BM>
__device__ __forceinline__ void load_stage(
    uint32_t base, const bf16* __restrict__ Ah, const bf16* __restrict__ Al,
    const bf16* __restrict__ Bh, const bf16* __restrict__ Bl,
    int row0, int col0, int M, int K, int kc, int tid)
{
    #pragma unroll
    for (int idx = tid; idx < BM*8; idx += 256) {
        const int r = idx >> 3, ch = idx & 7;
        const uint32_t dsw = (uint32_t)(r * 128 + ((ch ^ (r & 7)) << 4));
        const int ar = row0 + r;
        const size_t ao = (size_t)ar * K + kc + ch * 8;
        const int asz = (ar < M) ? 16 : 0;
        cp16(base + dsw,            Ah + ao, asz);
        cp16(base + BM*128 + dsw,   Al + ao, asz);
    }
    #pragma unroll
    for (int idx = tid; idx < 1024; idx += 256) {
        const int r = idx >> 3, ch = idx & 7;
        const uint32_t dsw = (uint32_t)(r * 128 + ((ch ^ (r & 7)) << 4));
        const size_t bo = (size_t)(col0 + r) * K + kc + ch * 8;
        cp16(base + 2*BM*128 + dsw,         Bh + bo, 16);
        cp16(base + 2*BM*128 + 16384 + dsw, Bl + bo, 16);
    }
    CP_COMMIT();
}

template<int BM, int NST>
__global__ __launch_bounds__(256, (BM == 64) ? 2 : 1)
void gemm_mma_kernel(const bf16* __restrict__ Ah, const bf16* __restrict__ Al,
                     const bf16* __restrict__ Bh, const bf16* __restrict__ Bl,
                     float* __restrict__ C, bf16* __restrict__ Oh, bf16* __restrict__ Ol,
                     int osplit, int rowmap, int M, int N, int K, int ldc,
                     const float* __restrict__ bias, const float* __restrict__ extra,
                     int mode)
{
    extern __shared__ char smem[];
    constexpr int STAGE = 2*BM*128 + 32768;
    constexpr int WN = (BM == 128) ? 32 : 16;
    constexpr int NT = WN / 8;
    const int tid = threadIdx.x;
    const int lane = tid & 31, wid = tid >> 5;
    const int wm = (BM == 128) ? (wid & 1) : 0;
    const int wn = (BM == 128) ? (wid >> 1) : wid;
    const int row0 = blockIdx.y * BM, col0 = blockIdx.x * 128;
    const uint32_t sb = smem_u32(smem);

    float acc[4][NT][4];
    #pragma unroll
    for (int a = 0; a < 4; a++)
        #pragma unroll
        for (int b = 0; b < NT; b++)
            #pragma unroll
            for (int c = 0; c < 4; c++) acc[a][b][c] = 0.f;

    const int NIT = K >> 6;

    load_stage<BM>(sb, Ah, Al, Bh, Bl, row0, col0, M, K, 0, tid);
    if (NST == 3) load_stage<BM>(sb + STAGE, Ah, Al, Bh, Bl, row0, col0, M, K, 64, tid);

    int sidx = 0;
    for (int it = 0; it < NIT; it++) {
        if (it + NST - 1 < NIT) {
            load_stage<BM>(sb + ((it + NST - 1) % NST) * STAGE, Ah, Al, Bh, Bl,
                           row0, col0, M, K, (it + NST - 1) * 64, tid);
            if (NST == 3) asm volatile("cp.async.wait_group 2;" ::: "memory");
            else          asm volatile("cp.async.wait_group 1;" ::: "memory");
        } else if (NST == 3 && it + 1 < NIT) {
            asm volatile("cp.async.wait_group 1;" ::: "memory");
        } else {
            asm volatile("cp.async.wait_group 0;" ::: "memory");
        }
        __syncthreads();

        const uint32_t aTh = sb + sidx * STAGE;
        const uint32_t bTh = aTh + 2*BM*128;

        if constexpr (BM == 128) {
            // fragment double-buffered inner loop
            uint32_t ahf[2][4][4], alf[2][4][4], bhf[2][2][4], blf[2][2][4];

#define LOADF(kss, bb) do {                                                   \
    _Pragma("unroll")                                                         \
    for (int mt = 0; mt < 4; mt++) {                                          \
        const int r = wm * 64 + mt * 16 + (lane & 15);                        \
        const int cch = (kss) * 2 + (lane >> 4);                              \
        const uint32_t ad = aTh + r * 128 + ((cch ^ (r & 7)) << 4);           \
        LDSM4(ahf[bb][mt], ad);                                               \
        LDSM4(alf[bb][mt], ad + BM*128);                                      \
    }                                                                         \
    _Pragma("unroll")                                                         \
    for (int n2 = 0; n2 < 2; n2++) {                                          \
        const int r = wn * WN + n2 * 16 + (lane & 7) + ((lane >> 4) << 3);    \
        const int cch = (kss) * 2 + ((lane >> 3) & 1);                        \
        const uint32_t ad = bTh + r * 128 + ((cch ^ (r & 7)) << 4);           \
        LDSM4(bhf[bb][n2], ad);                                               \
        LDSM4(blf[bb][n2], ad + 16384);                                       \
    } } while (0)

            LOADF(0, 0);
            #pragma unroll
            for (int ks = 0; ks < 4; ks++) {
                const int cur = ks & 1;
                if (ks < 3) LOADF(ks + 1, cur ^ 1);
                #pragma unroll
                for (int mt = 0; mt < 4; mt++)
                    #pragma unroll
                    for (int nt = 0; nt < 4; nt++) {
                        uint32_t* b2h = &bhf[cur][nt >> 1][(nt & 1) << 1];
                        uint32_t* b2l = &blf[cur][nt >> 1][(nt & 1) << 1];
                        MMA16816(acc[mt][nt], ahf[cur][mt], b2h);
                        MMA16816(acc[mt][nt], ahf[cur][mt], b2l);
                        MMA16816(acc[mt][nt], alf[cur][mt], b2h);
                    }
            }
#undef LOADF
        } else {
            #pragma unroll
            for (int ks = 0; ks < 4; ks++) {
                uint32_t ahf[4][4], alf[4][4], bhf[NT/2][4], blf[NT/2][4];
                #pragma unroll
                for (int mt = 0; mt < 4; mt++) {
                    const int r = wm * 64 + mt * 16 + (lane & 15);
                    const int cch = ks * 2 + (lane >> 4);
                    const uint32_t ad = aTh + r * 128 + ((cch ^ (r & 7)) << 4);
                    LDSM4(ahf[mt], ad);
                    LDSM4(alf[mt], ad + BM*128);
                }
                #pragma unroll
                for (int n2 = 0; n2 < NT/2; n2++) {
                    const int r = wn * WN + n2 * 16 + (lane & 7) + ((lane >> 4) << 3);
                    const int cch = ks * 2 + ((lane >> 3) & 1);
                    const uint32_t ad = bTh + r * 128 + ((cch ^ (r & 7)) << 4);
                    LDSM4(bhf[n2], ad);
                    LDSM4(blf[n2], ad + 16384);
                }
                #pragma unroll
                for (int mt = 0; mt < 4; mt++)
                    #pragma unroll
                    for (int nt = 0; nt < NT; nt++) {
                        uint32_t* b2h = &bhf[nt >> 1][(nt & 1) << 1];
                        uint32_t* b2l = &blf[nt >> 1][(nt & 1) << 1];
                        MMA16816(acc[mt][nt], ahf[mt], b2h);
                        MMA16816(acc[mt][nt], ahf[mt], b2l);
                        MMA16816(acc[mt][nt], alf[mt], b2h);
                    }
            }
        }
        __syncthreads();
        if (++sidx == NST) sidx = 0;
    }

    const int g = lane >> 2, tg = lane & 3;
    #pragma unroll
    for (int mt = 0; mt < 4; mt++) {
        const int rb = row0 + wm * 64 + mt * 16 + g;
        #pragma unroll
        for (int nt = 0; nt < NT; nt++) {
            const int c = col0 + wn * WN + nt * 8 + tg * 2;
            float* cc = acc[mt][nt];
            #pragma unroll
            for (int half = 0; half < 2; half++) {
                const int r = rb + half * 8;
                if (r >= M) continue;
                size_t crow;
                if (rowmap == 1)      crow = (size_t)(r >> 6) * NKV + N_ + (r & 63);
                else if (rowmap == 2) crow = (size_t)(r / N_) * NKV + (r % N_);
                else                  crow = (size_t)r;
                float v0 = epi(cc[half*2+0], crow, c,     ldc, bias, extra, mode);
                float v1 = epi(cc[half*2+1], crow, c + 1, ldc, bias, extra, mode);
                if (osplit) {
                    __nv_bfloat162 hp, lp;
                    split2(v0, v1, hp, lp);
                    *(__nv_bfloat162*)&Oh[crow * ldc + c] = hp;
                    *(__nv_bfloat162*)&Ol[crow * ldc + c] = lp;
                } else {
                    float2 v; v.x = v0; v.y = v1;
                    *(float2*)&C[crow * ldc + c] = v;
                }
            }
        }
    }
}

// ---------- split / transpose-split ----------
__global__ __launch_bounds__(256)
void split_kernel(const float* __restrict__ in, bf16* __restrict__ hi,
                  bf16* __restrict__ lo, int n)
{
    const int i = (blockIdx.x * blockDim.x + threadIdx.x) * 4;
    if (i >= n) return;
    float4 v = *(const float4*)(in + i);
    __nv_bfloat162 h01, h23, l01, l23;
    split2(v.x, v.y, h01, l01);
    split2(v.z, v.w, h23, l23);
    ((__nv_bfloat162*)(hi + i))[0] = h01;
    ((__nv_bfloat162*)(hi + i))[1] = h23;
    ((__nv_bfloat162*)(lo + i))[0] = l01;
    ((__nv_bfloat162*)(lo + i))[1] = l23;
}

// batched: W[K,N] -> [N,K] hi/lo with per-k scale; blockIdx.z selects layer
__global__ __launch_bounds__(256)
void tsplit_kernel(const float* __restrict__ W, const float* __restrict__ g,
                   bf16* __restrict__ Th, bf16* __restrict__ Tl, int K, int N,
                   size_t wstride, size_t gstride, size_t ostride)
{
    __shared__ float t[32][33];
    const int l = blockIdx.z;
    W  += (size_t)l * wstride;
    if (g) g += (size_t)l * gstride;
    Th += (size_t)l * ostride;
    Tl += (size_t)l * ostride;
    const int nb = blockIdx.x * 32, kb = blockIdx.y * 32;
    const int tx = threadIdx.x, ty = threadIdx.y;
    #pragma unroll
    for (int j = 0; j < 4; j++)
        t[ty + 8*j][tx] = W[(size_t)(kb + ty + 8*j) * N + nb + tx];
    __syncthreads();
    const float gs = g ? g[kb + tx] : 1.0f;
    #pragma unroll
    for (int j = 0; j < 4; j++) {
        const int n = nb + ty + 8*j, k = kb + tx;
        const float v = t[tx][ty + 8*j] * gs;
        const bf16 h = __float2bfloat16(v);
        Th[(size_t)n * K + k] = h;
        Tl[(size_t)n * K + k] = __float2bfloat16(v - __bfloat162float(h));
    }
}

// out[n] = sum_k b[k] * W[k,n], batched over blockIdx.y
__global__ void colwsum_kernel(const float* __restrict__ b, const float* __restrict__ W,
                               int K, int N, float* __restrict__ out,
                               size_t bstride, size_t wstride, size_t ostride)
{
    const int l = blockIdx.y;
    b   += (size_t)l * bstride;
    W   += (size_t)l * wstride;
    out += (size_t)l * ostride;
    const int n = blockIdx.x * 256 + threadIdx.x;
    if (n >= N) return;
    float s = 0.f;
    for (int k = 0; k < K; k++) s += b[k] * W[(size_t)k * N + n];
    out[n] = s;
}

// ---------- attention (fp32 math, bf16 hi/lo output) ----------
#define JPAD 704
#define SSTR 68
#define SMEM_ATTN ((JPAD*SSTR + 64*SSTR + 64*SSTR + 64) * 4)

__global__ __launch_bounds__(256, 1)
void attn_kernel(const float* __restrict__ Q, const float* __restrict__ KV,
                 bf16* __restrict__ Oth, bf16* __restrict__ Otl)
{
    extern __shared__ float sm[];
    float* S    = sm;
    float* Qs   = S  + JPAD*SSTR;
    float* Ts   = Qs + 64*SSTR;
    float* rinv = Ts + 64*SSTR;

    const int tid = threadIdx.x;
    const int b   = blockIdx.x / NH_;
    const int h   = blockIdx.x % NH_;

    const float* qbase = Q  + ((size_t)b * NQ_) * H_ + h * HD_;
    const float* kbase = KV + ((size_t)b * NKV) * (2*H_) + h * HD_;
    const float* vbase = kbase + H_;

    #pragma unroll
    for (int r = 0; r < 16; r++) {
        int idx = tid + r * 256;
        int l = idx >> 6, d = idx & 63;
        Qs[d*SSTR + l] = qbase[(size_t)l * H_ + d];
    }
    const int lt = tid >> 4, c4 = tid & 15;

    for (int t = 0; t < 11; t++) {
        const int jbase = t * 64;
        #pragma unroll
        for (int r = 0; r < 16; r++) {
            int idx = tid + r * 256;
            int jj = idx >> 6, d = idx & 63;
            int j = jbase + jj;
            Ts[d*SSTR + jj] = (j < NKV) ? kbase[(size_t)j * (2*H_) + d] : 0.f;
        }
        __syncthreads();
        float acc[4][4];
        #pragma unroll
        for (int i = 0; i < 4; i++)
            #pragma unroll
            for (int j = 0; j < 4; j++) acc[i][j] = 0.f;
        #pragma unroll 8
        for (int d = 0; d < 64; d++) {
            float4 q4 = *(const float4*)&Qs[d*SSTR + lt*4];
            float4 k4 = *(const float4*)&Ts[d*SSTR + c4*4];
            float qa[4] = {q4.x, q4.y, q4.z, q4.w};
            float ka[4] = {k4.x, k4.y, k4.z, k4.w};
            #pragma unroll
            for (int i = 0; i < 4; i++)
                #pragma unroll
                for (int j = 0; j < 4; j++)
                    acc[i][j] = fmaf(qa[i], ka[j], acc[i][j]);
        }
        #pragma unroll
        for (int jj = 0; jj < 4; jj++) {
            const int j = jbase + c4*4 + jj;
            float4 w;
            if (j < NKV) {
                w.x = acc[0][jj]*0.125f; w.y = acc[1][jj]*0.125f;
                w.z = acc[2][jj]*0.125f; w.w = acc[3][jj]*0.125f;
            } else { w.x = w.y = w.z = w.w = -1e30f; }
            *(float4*)&S[(size_t)j*SSTR + lt*4] = w;
        }
        __syncthreads();
    }
    {
        const int l = tid >> 2, sub = tid & 3;
        float m = -1e30f;
        for (int j = sub; j < JPAD; j += 4) m = fmaxf(m, S[j*SSTR + l]);
        m = fmaxf(m, __shfl_xor_sync(0xffffffffu, m, 1));
        m = fmaxf(m, __shfl_xor_sync(0xffffffffu, m, 2));
        float ssum = 0.f;
        for (int j = sub; j < JPAD; j += 4) {
            float e = __expf(S[j*SSTR + l] - m);
            S[j*SSTR + l] = e;
            ssum += e;
        }
        ssum += __shfl_xor_sync(0xffffffffu, ssum, 1);
        ssum += __shfl_xor_sync(0xffffffffu, ssum, 2);
        if (sub == 0) rinv[l] = 1.0f / ssum;
    }
    __syncthreads();

    float oacc[4][4];
    #pragma unroll
    for (int i = 0; i < 4; i++)
        #pragma unroll
        for (int j = 0; j < 4; j++) oacc[i][j] = 0.f;
    for (int t = 0; t < 11; t++) {
        const int jbase = t * 64;
        #pragma unroll
        for (int r = 0; r < 16; r++) {
            int idx = tid + r * 256;
            int jj = idx >> 6, d = idx & 63;
            int j = jbase + jj;
            Ts[jj*SSTR + d] = (j < NKV) ? vbase[(size_t)j * (2*H_) + d] : 0.f;
        }
        __syncthreads();
        #pragma unroll 8
        for (int jj = 0; jj < 64; jj++) {
            float4 p4 = *(const float4*)&S[(size_t)(jbase + jj)*SSTR + lt*4];
            float4 v4 = *(const float4*)&Ts[jj*SSTR + c4*4];
            float pa[4] = {p4.x, p4.y, p4.z, p4.w};
            float va[4] = {v4.x, v4.y, v4.z, v4.w};
            #pragma unroll
            for (int i = 0; i < 4; i++)
                #pragma unroll
                for (int j = 0; j < 4; j++)
                    oacc[i][j] = fmaf(pa[i], va[j], oacc[i][j]);
        }
        __syncthreads();
    }
    #pragma unroll
    for (int i = 0; i < 4; i++) {
        const int l = lt*4 + i;
        const float sc = rinv[l];
        #pragma unroll
        for (int j = 0; j < 2; j++) {
            const int d = c4*4 + j*2;
            const size_t o = ((size_t)(b*NQ_ + l)) * H_ + h*HD_ + d;
            __nv_bfloat162 hp, lp;
            split2(oacc[i][j*2] * sc, oacc[i][j*2+1] * sc, hp, lp);
            *(__nv_bfloat162*)&Oth[o] = hp;
            *(__nv_bfloat162*)&Otl[o] = lp;
        }
    }
}

// ---------- LayerNorm ----------
__device__ inline void block_reduce_2(float& s, float& s2) {
    __shared__ float red[16];
    const int lane = threadIdx.x & 31, w = threadIdx.x >> 5;
    #pragma unroll
    for (int o = 16; o > 0; o >>= 1) {
        s  += __shfl_xor_sync(0xffffffffu, s,  o);
        s2 += __shfl_xor_sync(0xffffffffu, s2, o);
    }
    if (lane == 0) { red[w] = s; red[8 + w] = s2; }
    __syncthreads();
    if (threadIdx.x < 32) {
        s  = (lane < 8) ? red[lane]     : 0.f;
        s2 = (lane < 8) ? red[8 + lane] : 0.f;
        #pragma unroll
        for (int o = 4; o > 0; o >>= 1) {
            s  += __shfl_xor_sync(0xffffffffu, s,  o);
            s2 += __shfl_xor_sync(0xffffffffu, s2, o);
        }
        if (lane == 0) { red[0] = s; red[8] = s2; }
    }
    __syncthreads();
    s = red[0]; s2 = red[8];
}

__global__ __launch_bounds__(256)
void ln_hn_kernel(const float* __restrict__ in, const float* __restrict__ temb,
                  bf16* __restrict__ outh, bf16* __restrict__ outl)
{
    const int r = blockIdx.x;
    const int b = r / N_;
    const float* x  = in + (size_t)r * H_;
    const float* te = temb + (size_t)b * H_;
    float s = 0.f, s2 = 0.f;
    for (int i = threadIdx.x*2; i < H_; i += 512) {
        float2 v = *(const float2*)(x + i);
        float2 t = *(const float2*)(te + i);
        float a0 = v.x + t.x, a1 = v.y + t.y;
        s += a0 + a1; s2 += a0*a0 + a1*a1;
    }
    block_reduce_2(s, s2);
    const float mean = s * (1.0f / H_);
    const float inv  = rsqrtf(s2 * (1.0f / H_) - mean * mean + 1e-5f);
    const size_t ob = (size_t)r * H_;
    for (int i = threadIdx.x*2; i < H_; i += 512) {
        float2 v = *(const float2*)(x + i);
        float2 t = *(const float2*)(te + i);
        float o0 = (v.x + t.x - mean) * inv;
        float o1 = (v.y + t.y - mean) * inv;
        __nv_bfloat162 hp, lp;
        split2(o0, o1, hp, lp);
        *(__nv_bfloat162*)&outh[ob + i] = hp;
        *(__nv_bfloat162*)&outl[ob + i] = lp;
    }
}

__global__ __launch_bounds__(256)
void ln_mod_kernel(const float* __restrict__ in, const float* __restrict__ g,
                   const float* __restrict__ beta, const float* __restrict__ emb,
                   int shOff, int scOff,
                   bf16* __restrict__ o1h, bf16* __restrict__ o1l)
{
    const int r = blockIdx.x;
    const int b = r >> 6;
    const float* x  = in + (size_t)r * H_;
    const float* sh = emb + (size_t)b * (4*H_) + shOff;
    const float* sc = emb + (size_t)b * (4*H_) + scOff;
    float s = 0.f, s2 = 0.f;
    for (int i = threadIdx.x*2; i < H_; i += 512) {
        float2 v = *(const float2*)(x + i);
        s += v.x + v.y; s2 += v.x*v.x + v.y*v.y;
    }
    block_reduce_2(s, s2);
    const float mean = s * (1.0f / H_);
    const float inv  = rsqrtf(s2 * (1.0f / H_) - mean * mean + 1e-5f);
    const size_t o1b = (size_t)r * H_;
    for (int i = threadIdx.x*2; i < H_; i += 512) {
        float2 v = *(const float2*)(x + i);
        float2 gg = *(const float2*)(g + i);
        float2 bb = *(const float2*)(beta + i);
        float2 ss = *(const float2*)(sc + i);
        float2 hh = *(const float2*)(sh + i);
        float o0 = ((v.x - mean) * inv * gg.x + bb.x) * (1.0f + ss.x) + hh.x;
        float o1 = ((v.y - mean) * inv * gg.y + bb.y) * (1.0f + ss.y) + hh.y;
        __nv_bfloat162 hp, lp;
        split2(o0, o1, hp, lp);
        *(__nv_bfloat162*)&o1h[o1b + i] = hp;
        *(__nv_bfloat162*)&o1l[o1b + i] = lp;
    }
}

__global__ __launch_bounds__(256)
void ln_out_kernel(const float* __restrict__ in, const float* __restrict__ g,
                   const float* __restrict__ beta, float* __restrict__ out)
{
    const int r = blockIdx.x;
    const float* x = in + (size_t)r * O_;
    float s = 0.f, s2 = 0.f;
    for (int i = threadIdx.x; i < O_; i += 256) { float v = x[i]; s += v; s2 += v*v; }
    block_reduce_2(s, s2);
    const float mean = s * (1.0f / O_);
    const float inv  = rsqrtf(s2 * (1.0f / O_) - mean * mean + 1e-5f);
    float* o = out + (size_t)r * O_;
    for (int i = threadIdx.x; i < O_; i += 256)
        o[i] = (x[i] - mean) * inv * g[i] + beta[i];
}

// ---------- small kernels ----------
__global__ void time_proj_kernel(const float* __restrict__ t,
                                 bf16* __restrict__ tph, bf16* __restrict__ tpl)
{
    const int b = blockIdx.x, k = threadIdx.x;
    const float f = expf(-9.210340371976184f * (float)k / 160.0f);
    const float ang = t[b] * f;
    const float c = cosf(ang), s = sinf(ang);
    bf16 ch = __float2bfloat16(c), sh = __float2bfloat16(s);
    tph[b*TIN_ + k]       = ch;
    tpl[b*TIN_ + k]       = __float2bfloat16(c - __bfloat162float(ch));
    tph[b*TIN_ + 160 + k] = sh;
    tpl[b*TIN_ + 160 + k] = __float2bfloat16(s - __bfloat162float(sh));
}
__global__ void silu_split_kernel(const float* __restrict__ in,
                                  bf16* __restrict__ hi, bf16* __restrict__ lo, int n)
{
    int i = blockIdx.x * blockDim.x + threadIdx.x;
    if (i < n) {
        float v = in[i];
        float s = v / (1.0f + expf(-v));
        bf16 h = __float2bfloat16(s);
        hi[i] = h;
        lo[i] = __float2bfloat16(s - __bfloat162float(h));
    }
}
__global__ void lat_init_kernel(const float* __restrict__ l0, float* __restrict__ lat)
{
    int i = blockIdx.x * blockDim.x + threadIdx.x;
    if (i < ML * H_) lat[i] = l0[i % (NQ_ * H_)];
}
__global__ void copy_kernel(const float* __restrict__ in, float* __restrict__ out, int n)
{
    int i = blockIdx.x * blockDim.x + threadIdx.x;
    if (i < n) out[i] = in[i];
}

// ---------- host driver ----------
#define SMEM128 (3*(2*128*128 + 32768))
#define SMEM64  (2*(2*64*128 + 32768))

static inline void run_mma(int BM, const bf16* Ah, const bf16* Al,
                           const bf16* Bh, const bf16* Bl,
                           float* C, bf16* Oh, bf16* Ol, int osplit, int rowmap,
                           int M, int N, int K, int ldc,
                           const float* bias, const float* extra, int mode)
{
    dim3 grid(N / 128, (M + BM - 1) / BM);
    if (BM == 128)
        gemm_mma_kernel<128,3><<<grid, 256, SMEM128>>>(Ah, Al, Bh, Bl, C, Oh, Ol,
            osplit, rowmap, M, N, K, ldc, bias, extra, mode);
    else
        gemm_mma_kernel<64,2><<<grid, 256, SMEM64>>>(Ah, Al, Bh, Bl, C, Oh, Ol,
            osplit, rowmap, M, N, K, ldc, bias, extra, mode);
}
static inline void run_split(const float* in, bf16* hi, bf16* lo, size_t n)
{
    split_kernel<<<(unsigned)((n/4 + 255)/256), 256>>>(in, hi, lo, (int)n);
}
static inline void run_tsplit_b(const float* W, const float* g, bf16* Th, bf16* Tl,
                                int K, int N, size_t wstride, size_t gstride,
                                size_t ostride, int layers)
{
    tsplit_kernel<<<dim3(N/32, K/32, layers), dim3(32, 8)>>>(W, g, Th, Tl, K, N,
                                                             wstride, gstride, ostride);
}

#define GSA(p, sym) cudaGetSymbolAddress((void**)&(p), sym)

extern "C" void kernel_launch(void* const* d_in, const int* in_sizes, int n_in,
                              void* d_out, int out_size)
{
    const float* x          = (const float*)d_in[0];
    const float* timestep   = (const float*)d_in[1];
    const float* latents0   = (const float*)d_in[2];
    const float* proj_in_W  = (const float*)d_in[3];
    const float* proj_in_b  = (const float*)d_in[4];
    const float* te1_W      = (const float*)d_in[5];
    const float* te1_b      = (const float*)d_in[6];
    const float* te2_W      = (const float*)d_in[7];
    const float* te2_b      = (const float*)d_in[8];
    const float* ln0_g      = (const float*)d_in[9];
    const float* ln0_b      = (const float*)d_in[10];
    const float* ln1_g      = (const float*)d_in[11];
    const float* ln1_b      = (const float*)d_in[12];
    const float* Wq         = (const float*)d_in[13];
    const float* Wkv        = (const float*)d_in[14];
    const float* Wo         = (const float*)d_in[15];
    const float* ada_W      = (const float*)d_in[16];
    const float* ada_b      = (const float*)d_in[17];
    const float* lnada_g    = (const float*)d_in[18];
    const float* lnada_b    = (const float*)d_in[19];
    const float* Wff1       = (const float*)d_in[20];
    const float* Wff2       = (const float*)d_in[21];
    const float* proj_out_W = (const float*)d_in[22];
    const float* proj_out_b = (const float*)d_in[23];
    const float* norm_out_g = (const float*)d_in[24];
    const float* norm_out_b = (const float*)d_in[25];

    float *temb, *h, *kv, *lat, *q, *emb, *obuf, *bkv;
    GSA(temb, g_temb); GSA(h, g_h); GSA(kv, g_kv); GSA(lat, g_lat);
    GSA(q, g_q); GSA(emb, g_emb); GSA(obuf, g_obuf); GSA(bkv, g_bkv);

    bf16 *wpin_h,*wpin_l,*wte1_h,*wte1_l,*wte2_h,*wte2_l,*wq_h,*wq_l,*wkv_h,*wkv_l,
         *wkvS_h,*wkvS_l,*wo_h,*wo_l,*wada_h,*wada_l,*wff1_h,*wff1_l,*wff2_h,*wff2_l,
         *wpo_h,*wpo_l;
    GSA(wpin_h, g_wpin_h); GSA(wpin_l, g_wpin_l);
    GSA(wte1_h, g_wte1_h); GSA(wte1_l, g_wte1_l);
    GSA(wte2_h, g_wte2_h); GSA(wte2_l, g_wte2_l);
    GSA(wq_h, g_wq_h);     GSA(wq_l, g_wq_l);
    GSA(wkv_h, g_wkv_h);   GSA(wkv_l, g_wkv_l);
    GSA(wkvS_h, g_wkvS_h); GSA(wkvS_l, g_wkvS_l);
    GSA(wo_h, g_wo_h);     GSA(wo_l, g_wo_l);
    GSA(wada_h, g_wada_h); GSA(wada_l, g_wada_l);
    GSA(wff1_h, g_wff1_h); GSA(wff1_l, g_wff1_l);
    GSA(wff2_h, g_wff2_h); GSA(wff2_l, g_wff2_l);
    GSA(wpo_h, g_wpo_h);   GSA(wpo_l, g_wpo_l);

    bf16 *tph,*tpl,*t1h,*t1l,*tsh,*tsl,*xh,*xl,*hnh,*hnl,*lmh,*lml,*atth,*attl,*ffh,*ffl;
    GSA(tph, g_tp_h);   GSA(tpl, g_tp_l);
    GSA(t1h, g_t1_h);   GSA(t1l, g_t1_l);
    GSA(tsh, g_ts_h);   GSA(tsl, g_ts_l);
    GSA(xh, g_x_h);     GSA(xl, g_x_l);
    GSA(hnh, g_hn_h);   GSA(hnl, g_hn_l);
    GSA(lmh, g_lm_h);   GSA(lml, g_lm_l);
    GSA(atth, g_att_h); GSA(attl, g_att_l);
    GSA(ffh, g_ff_h);   GSA(ffl, g_ff_l);

    cudaFuncSetAttribute(attn_kernel, cudaFuncAttributeMaxDynamicSharedMemorySize, SMEM_ATTN);
    cudaFuncSetAttribute(gemm_mma_kernel<128,3>, cudaFuncAttributeMaxDynamicSharedMemorySize, SMEM128);
    cudaFuncSetAttribute(gemm_mma_kernel<64,2>,  cudaFuncAttributeMaxDynamicSharedMemorySize, SMEM64);

    // --- launches 0-1: deps for proj_in GEMM; 2-6: GEMM col-chunks (ncu target) ---
    run_tsplit_b(proj_in_W, nullptr, wpin_h, wpin_l, E_, H_, 0, 0, 0, 1);   // 0
    run_split(x, xh, xl, (size_t)MH*E_);                                    // 1
    for (int cc = 0; cc < 5; cc++) {                                        // 2..6
        run_mma(128, xh, xl, wpin_h + (size_t)cc*256*E_, wpin_l + (size_t)cc*256*E_,
                h + cc*256, nullptr, nullptr, 0, 0,
                MH, 256, E_, H_, proj_in_b + cc*256, nullptr, MODE_BIAS);
    }

    // time embedding
    time_proj_kernel<<<B_, 160>>>(timestep, tph, tpl);
    run_tsplit_b(te1_W, nullptr, wte1_h, wte1_l, TIN_, H_, 0, 0, 0, 1);
    run_tsplit_b(te2_W, nullptr, wte2_h, wte2_l, H_, H_, 0, 0, 0, 1);
    run_mma(64, tph, tpl, wte1_h, wte1_l, nullptr, t1h, t1l, 1, 0,
            B_, H_, TIN_, H_, te1_b, nullptr, MODE_BIAS_SILU);
    run_mma(64, t1h, t1l, wte2_h, wte2_l, temb, nullptr, nullptr, 0, 0,
            B_, H_, H_, H_, te2_b, nullptr, MODE_BIAS);
    silu_split_kernel<<<(B_*H_ + 255)/256, 256>>>(temb, tsh, tsl, B_*H_);

    // hn = normalize(h + temb) once, hi/lo
    ln_hn_kernel<<<MH, 256>>>(h, temb, hnh, hnl);
    lat_init_kernel<<<(ML*H_ + 255)/256, 256>>>(latents0, lat);

    // per-layer weight prep (batched over layers)
    run_tsplit_b(Wq,    nullptr, wq_h,   wq_l,   H_,  H_,   (size_t)H_*H_,    0,  (size_t)H_*H_,    DL);
    run_tsplit_b(Wkv,   nullptr, wkv_h,  wkv_l,  H_,  2*H_, (size_t)H_*2*H_,  0,  (size_t)2*H_*H_,  DL);
    run_tsplit_b(Wkv,   ln0_g,   wkvS_h, wkvS_l, H_,  2*H_, (size_t)H_*2*H_,  H_, (size_t)2*H_*H_,  DL);
    colwsum_kernel<<<dim3((2*H_+255)/256, DL), 256>>>(ln0_b, Wkv, H_, 2*H_, bkv,
                                                      H_, (size_t)H_*2*H_, 2*H_);
    run_tsplit_b(Wo,    nullptr, wo_h,   wo_l,   H_,  H_,   (size_t)H_*H_,    0,  (size_t)H_*H_,    DL);
    run_tsplit_b(ada_W, nullptr, wada_h, wada_l, H_,  4*H_, (size_t)H_*4*H_,  0,  (size_t)4*H_*H_,  DL);
    run_tsplit_b(Wff1,  nullptr, wff1_h, wff1_l, H_,  FF_,  (size_t)H_*FF_,   0,  (size_t)FF_*H_,   DL);
    run_tsplit_b(Wff2,  nullptr, wff2_h, wff2_l, FF_, H_,   (size_t)FF_*H_,   0,  (size_t)H_*FF_,   DL);
    run_tsplit_b(proj_out_W, nullptr, wpo_h, wpo_l, H_, O_, 0, 0, 0, 1);

    for (int i = 0; i < DL; i++) {
        run_mma(64, tsh, tsl, wada_h + (size_t)i*4*H_*H_, wada_l + (size_t)i*4*H_*H_,
                emb, nullptr, nullptr, 0, 0, B_, 4*H_, H_, 4*H_,
                ada_b + (size_t)i*4*H_, nullptr, MODE_BIAS);

        ln_mod_kernel<<<ML, 256>>>(lat, ln1_g + i*H_, ln1_b + i*H_, emb, 0, H_, lmh, lml);

        run_mma(64, lmh, lml, wq_h + (size_t)i*H_*H_, wq_l + (size_t)i*H_*H_,
                q, nullptr, nullptr, 0, 0, ML, H_, H_, H_, nullptr, nullptr, MODE_NONE);
        run_mma(128, hnh, hnl, wkvS_h + (size_t)i*2*H_*H_, wkvS_l + (size_t)i*2*H_*H_,
                kv, nullptr, nullptr, 0, 2, MH, 2*H_, H_, 2*H_,
                bkv + i*2*H_, nullptr, MODE_BIAS);
        run_mma(64, lmh, lml, wkv_h + (size_t)i*2*H_*H_, wkv_l + (size_t)i*2*H_*H_,
                kv, nullptr, nullptr, 0, 1, ML, 2*H_, H_, 2*H_,
                nullptr, nullptr, MODE_NONE);

        attn_kernel<<<B_*NH_, 256, SMEM_ATTN>>>(q, kv, atth, attl);

        run_mma(64, atth, attl, wo_h + (size_t)i*H_*H_, wo_l + (size_t)i*H_*H_,
                lat, nullptr, nullptr, 0, 0, ML, H_, H_, H_, nullptr, lat, MODE_RES);

        ln_mod_kernel<<<ML, 256>>>(lat, lnada_g + i*H_, lnada_b + i*H_, emb, 2*H_, 3*H_,
                                   lmh, lml);
        run_mma(64, lmh, lml, wff1_h + (size_t)i*FF_*H_, wff1_l + (size_t)i*FF_*H_,
                nullptr, ffh, ffl, 1, 0, ML, FF_, H_, FF_, nullptr, nullptr, MODE_GELU);
        run_mma(64, ffh, ffl, wff2_h + (size_t)i*H_*FF_, wff2_l + (size_t)i*H_*FF_,
                lat, nullptr, nullptr, 0, 0, ML, H_, FF_, H_, nullptr, lat, MODE_RES);
    }

    run_split(lat, lmh, lml, (size_t)ML*H_);
    run_mma(64, lmh, lml, wpo_h, wpo_l, obuf, nullptr, nullptr, 0, 0,
            ML, O_, H_, O_, proj_out_b, nullptr, MODE_BIAS);
    ln_out_kernel<<<ML, 256>>>(obuf, norm_out_g, norm_out_b, (float*)d_out);

    const int out0 = ML * O_;
    if (out_size >= out0 + B_*H_)
        copy_kernel<<<(B_*H_ + 255)/256, 256>>>(temb, (float*)d_out + out0, B_*H_);
}

// round 14
// speedup vs baseline: 3.1889x; 1.0297x over previous
#include <cuda_runtime.h>
#include <cuda_bf16.h>
#include <cstdint>

using bf16 = __nv_bfloat16;

#define E_    1152
#define H_    1280
#define O_    2432
#define DL    4
#define HD_   64
#define NH_   20
#define NQ_   64
#define TIN_  320
#define FF_   5120
#define B_    32
#define N_    577
#define NKV   641
#define MH    (B_*N_)
#define MC    (B_*NKV)
#define ML    (B_*NQ_)

// fp32 scratch
__device__ float g_temb[B_*H_];
__device__ float g_h[(size_t)MH*H_];
__device__ float g_kv[(size_t)MC*2*H_];
__device__ float g_lat[(size_t)ML*H_];
__device__ float g_q[(size_t)ML*H_];
__device__ float g_emb[(size_t)B_*4*H_*DL];
__device__ float g_obuf[(size_t)ML*O_];
__device__ float g_bkv[DL*2*H_];

// bf16 weights transposed to [N,K], hi/lo
__device__ bf16 g_wpin_h[(size_t)H_*E_],      g_wpin_l[(size_t)H_*E_];
__device__ bf16 g_wte1_h[(size_t)H_*TIN_],    g_wte1_l[(size_t)H_*TIN_];
__device__ bf16 g_wte2_h[(size_t)H_*H_],      g_wte2_l[(size_t)H_*H_];
__device__ bf16 g_wq_h[(size_t)DL*H_*H_],     g_wq_l[(size_t)DL*H_*H_];
__device__ bf16 g_wkv_h[(size_t)DL*2*H_*H_],  g_wkv_l[(size_t)DL*2*H_*H_];
__device__ bf16 g_wkvS_h[(size_t)DL*2*H_*H_], g_wkvS_l[(size_t)DL*2*H_*H_];
__device__ bf16 g_wo_h[(size_t)DL*H_*H_],     g_wo_l[(size_t)DL*H_*H_];
__device__ bf16 g_wada_h[(size_t)DL*4*H_*H_], g_wada_l[(size_t)DL*4*H_*H_];
__device__ bf16 g_wff1_h[(size_t)DL*FF_*H_],  g_wff1_l[(size_t)DL*FF_*H_];
__device__ bf16 g_wff2_h[(size_t)DL*H_*FF_],  g_wff2_l[(size_t)DL*H_*FF_];
__device__ bf16 g_wpo_h[(size_t)O_*H_],       g_wpo_l[(size_t)O_*H_];

// bf16 activations hi/lo
__device__ bf16 g_tp_h[B_*TIN_],        g_tp_l[B_*TIN_];
__device__ bf16 g_t1_h[B_*H_],          g_t1_l[B_*H_];
__device__ bf16 g_ts_h[B_*H_],          g_ts_l[B_*H_];
__device__ bf16 g_x_h[(size_t)MH*E_],   g_x_l[(size_t)MH*E_];
__device__ bf16 g_hn_h[(size_t)MH*H_],  g_hn_l[(size_t)MH*H_];
__device__ bf16 g_lm_h[(size_t)ML*H_],  g_lm_l[(size_t)ML*H_];
__device__ bf16 g_att_h[(size_t)ML*H_], g_att_l[(size_t)ML*H_];
__device__ bf16 g_ff_h[(size_t)ML*FF_], g_ff_l[(size_t)ML*FF_];

#define MODE_NONE      0
#define MODE_BIAS      1
#define MODE_BIAS_SILU 3
#define MODE_GELU      4
#define MODE_RES       5

// ---------- PTX helpers ----------
__device__ __forceinline__ uint32_t smem_u32(const void* p) {
    uint32_t a;
    asm("{ .reg .u64 t; cvta.to.shared.u64 t, %1; cvt.u32.u64 %0, t; }" : "=r"(a) : "l"(p));
    return a;
}
__device__ __forceinline__ void cp16(uint32_t dst, const void* src, int sz) {
    asm volatile("cp.async.cg.shared.global [%0], [%1], 16, %2;" :: "r"(dst), "l"(src), "r"(sz));
}
#define CP_COMMIT() asm volatile("cp.async.commit_group;" ::: "memory")

#define LDSM4(r, a) asm volatile( \
    "ldmatrix.sync.aligned.m8n8.x4.shared.b16 {%0,%1,%2,%3}, [%4];" \
    : "=r"((r)[0]), "=r"((r)[1]), "=r"((r)[2]), "=r"((r)[3]) : "r"(a))

#define MMA16816(d, a, b) asm volatile( \
    "mma.sync.aligned.m16n8k16.row.col.f32.bf16.bf16.f32 " \
    "{%0,%1,%2,%3}, {%4,%5,%6,%7}, {%8,%9}, {%0,%1,%2,%3};" \
    : "+f"((d)[0]), "+f"((d)[1]), "+f"((d)[2]), "+f"((d)[3]) \
    : "r"((a)[0]), "r"((a)[1]), "r"((a)[2]), "r"((a)[3]), "r"((b)[0]), "r"((b)[1]))

__device__ __forceinline__ void split2(float a, float b, __nv_bfloat162& hp, __nv_bfloat162& lp)
{
    bf16 h0 = __float2bfloat16(a), h1 = __float2bfloat16(b);
    hp.x = h0; hp.y = h1;
    lp.x = __float2bfloat16(a - __bfloat162float(h0));
    lp.y = __float2bfloat16(b - __bfloat162float(h1));
}

// ---------- bf16 3-split GEMM via mma.sync ----------
__device__ __forceinline__ float epi(float v, size_t crow, int c, int ldc,
                                     const float* __restrict__ bias,
                                     const float* __restrict__ extra, int mode)
{
    if (mode == MODE_BIAS) v += bias[c];
    else if (mode == MODE_BIAS_SILU) { float s = v + bias[c]; v = s / (1.0f + expf(-s)); }
    else if (mode == MODE_GELU) v = 0.5f * v * (1.0f + erff(v * 0.70710678118654752f));
    else if (mode == MODE_RES) v += extra[crow * ldc + c];
    return v;
}

template<int BM, int BN>
__device__ __forceinline__ void load_stage(
    uint32_t base, const bf16* __restrict__ Ah, const bf16* __restrict__ Al,
    const bf16* __restrict__ Bh, const bf16* __restrict__ Bl,
    int row0, int col0, int M, int K, int kc, int tid)
{
    #pragma unroll
    for (int idx = tid; idx < BM*8; idx += 256) {
        const int r = idx >> 3, ch = idx & 7;
        const uint32_t dsw = (uint32_t)(r * 128 + ((ch ^ (r & 7)) << 4));
        const int ar = row0 + r;
        const size_t ao = (size_t)ar * K + kc + ch * 8;
        const int asz = (ar < M) ? 16 : 0;
        cp16(base + dsw,          Ah + ao, asz);
        cp16(base + BM*128 + dsw, Al + ao, asz);
    }
    #pragma unroll
    for (int idx = tid; idx < BN*8; idx += 256) {
        const int r = idx >> 3, ch = idx & 7;
        const uint32_t dsw = (uint32_t)(r * 128 + ((ch ^ (r & 7)) << 4));
        const size_t bo = (size_t)(col0 + r) * K + kc + ch * 8;
        cp16(base + 2*BM*128 + dsw,          Bh + bo, 16);
        cp16(base + 2*BM*128 + BN*128 + dsw, Bl + bo, 16);
    }
    CP_COMMIT();
}

template<int BM, int BN, int NST>
__global__ __launch_bounds__(256, (BM == 64) ? 2 : 1)
void gemm_mma_kernel(const bf16* __restrict__ Ah, const bf16* __restrict__ Al,
                     const bf16* __restrict__ Bh, const bf16* __restrict__ Bl,
                     float* __restrict__ C, bf16* __restrict__ Oh, bf16* __restrict__ Ol,
                     int osplit, int rowmap, int M, int N, int K, int ldc,
                     const float* __restrict__ bias, const float* __restrict__ extra,
                     int mode)
{
    extern __shared__ char smem[];
    constexpr int STAGE = 2*BM*128 + 2*BN*128;
    constexpr int WN = (BN == 256) ? 64 : ((BM == 128) ? 32 : 16);
    constexpr int NT = WN / 8;
    const int tid = threadIdx.x;
    const int lane = tid & 31, wid = tid >> 5;
    const int wm = (BM == 128) ? (wid & 1) : 0;
    const int wn = (BM == 128) ? (wid >> 1) : wid;
    const int row0 = blockIdx.y * BM, col0 = blockIdx.x * BN;
    const uint32_t sb = smem_u32(smem);

    float acc[4][NT][4];
    #pragma unroll
    for (int a = 0; a < 4; a++)
        #pragma unroll
        for (int b = 0; b < NT; b++)
            #pragma unroll
            for (int c = 0; c < 4; c++) acc[a][b][c] = 0.f;

    const int NIT = K >> 6;

    load_stage<BM,BN>(sb, Ah, Al, Bh, Bl, row0, col0, M, K, 0, tid);
    if (NST == 3) load_stage<BM,BN>(sb + STAGE, Ah, Al, Bh, Bl, row0, col0, M, K, 64, tid);

    int sidx = 0;
    for (int it = 0; it < NIT; it++) {
        if (it + NST - 1 < NIT) {
            load_stage<BM,BN>(sb + ((it + NST - 1) % NST) * STAGE, Ah, Al, Bh, Bl,
                              row0, col0, M, K, (it + NST - 1) * 64, tid);
            if (NST == 3) asm volatile("cp.async.wait_group 2;" ::: "memory");
            else          asm volatile("cp.async.wait_group 1;" ::: "memory");
        } else if (NST == 3 && it + 1 < NIT) {
            asm volatile("cp.async.wait_group 1;" ::: "memory");
        } else {
            asm volatile("cp.async.wait_group 0;" ::: "memory");
        }
        __syncthreads();

        const uint32_t aTh = sb + sidx * STAGE;
        const uint32_t bTh = aTh + 2*BM*128;

        if constexpr (BM == 128 && BN == 128) {
            uint32_t ahf[2][4][4], alf[2][4][4], bhf[2][2][4], blf[2][2][4];
#define LOADF(kss, bb) do {                                                   \
    _Pragma("unroll")                                                         \
    for (int mt = 0; mt < 4; mt++) {                                          \
        const int r = wm * 64 + mt * 16 + (lane & 15);                        \
        const int cch = (kss) * 2 + (lane >> 4);                              \
        const uint32_t ad = aTh + r * 128 + ((cch ^ (r & 7)) << 4);           \
        LDSM4(ahf[bb][mt], ad);                                               \
        LDSM4(alf[bb][mt], ad + BM*128);                                      \
    }                                                                         \
    _Pragma("unroll")                                                         \
    for (int n2 = 0; n2 < 2; n2++) {                                          \
        const int r = wn * WN + n2 * 16 + (lane & 7) + ((lane >> 4) << 3);    \
        const int cch = (kss) * 2 + ((lane >> 3) & 1);                        \
        const uint32_t ad = bTh + r * 128 + ((cch ^ (r & 7)) << 4);           \
        LDSM4(bhf[bb][n2], ad);                                               \
        LDSM4(blf[bb][n2], ad + BN*128);                                      \
    } } while (0)
            LOADF(0, 0);
            #pragma unroll
            for (int ks = 0; ks < 4; ks++) {
                const int cur = ks & 1;
                if (ks < 3) LOADF(ks + 1, cur ^ 1);
                #pragma unroll
                for (int mt = 0; mt < 4; mt++)
                    #pragma unroll
                    for (int nt = 0; nt < 4; nt++) {
                        uint32_t* b2h = &bhf[cur][nt >> 1][(nt & 1) << 1];
                        uint32_t* b2l = &blf[cur][nt >> 1][(nt & 1) << 1];
                        MMA16816(acc[mt][nt], ahf[cur][mt], b2h);
                        MMA16816(acc[mt][nt], ahf[cur][mt], b2l);
                        MMA16816(acc[mt][nt], alf[cur][mt], b2h);
                    }
            }
#undef LOADF
        } else {
            #pragma unroll
            for (int ks = 0; ks < 4; ks++) {
                uint32_t ahf[4][4], alf[4][4], bhf[NT/2][4], blf[NT/2][4];
                #pragma unroll
                for (int mt = 0; mt < 4; mt++) {
                    const int r = wm * 64 + mt * 16 + (lane & 15);
                    const int cch = ks * 2 + (lane >> 4);
                    const uint32_t ad = aTh + r * 128 + ((cch ^ (r & 7)) << 4);
                    LDSM4(ahf[mt], ad);
                    LDSM4(alf[mt], ad + BM*128);
                }
                #pragma unroll
                for (int n2 = 0; n2 < NT/2; n2++) {
                    const int r = wn * WN + n2 * 16 + (lane & 7) + ((lane >> 4) << 3);
                    const int cch = ks * 2 + ((lane >> 3) & 1);
                    const uint32_t ad = bTh + r * 128 + ((cch ^ (r & 7)) << 4);
                    LDSM4(bhf[n2], ad);
                    LDSM4(blf[n2], ad + BN*128);
                }
                #pragma unroll
                for (int mt = 0; mt < 4; mt++)
                    #pragma unroll
                    for (int nt = 0; nt < NT; nt++) {
                        uint32_t* b2h = &bhf[nt >> 1][(nt & 1) << 1];
                        uint32_t* b2l = &blf[nt >> 1][(nt & 1) << 1];
                        MMA16816(acc[mt][nt], ahf[mt], b2h);
                        MMA16816(acc[mt][nt], ahf[mt], b2l);
                        MMA16816(acc[mt][nt], alf[mt], b2h);
                    }
            }
        }
        __syncthreads();
        if (++sidx == NST) sidx = 0;
    }

    const int g = lane >> 2, tg = lane & 3;
    #pragma unroll
    for (int mt = 0; mt < 4; mt++) {
        const int rb = row0 + wm * 64 + mt * 16 + g;
        #pragma unroll
        for (int nt = 0; nt < NT; nt++) {
            const int c = col0 + wn * WN + nt * 8 + tg * 2;
            float* cc = acc[mt][nt];
            #pragma unroll
            for (int half = 0; half < 2; half++) {
                const int r = rb + half * 8;
                if (r >= M) continue;
                size_t crow;
                if (rowmap == 1)      crow = (size_t)(r >> 6) * NKV + N_ + (r & 63);
                else if (rowmap == 2) crow = (size_t)(r / N_) * NKV + (r % N_);
                else                  crow = (size_t)r;
                float v0 = epi(cc[half*2+0], crow, c,     ldc, bias, extra, mode);
                float v1 = epi(cc[half*2+1], crow, c + 1, ldc, bias, extra, mode);
                if (osplit) {
                    __nv_bfloat162 hp, lp;
                    split2(v0, v1, hp, lp);
                    *(__nv_bfloat162*)&Oh[crow * ldc + c] = hp;
                    *(__nv_bfloat162*)&Ol[crow * ldc + c] = lp;
                } else {
                    float2 v; v.x = v0; v.y = v1;
                    *(float2*)&C[crow * ldc + c] = v;
                }
            }
        }
    }
}

// ---------- split / transpose-split ----------
__global__ __launch_bounds__(256)
void split_kernel(const float* __restrict__ in, bf16* __restrict__ hi,
                  bf16* __restrict__ lo, int n)
{
    const int i = (blockIdx.x * blockDim.x + threadIdx.x) * 4;
    if (i >= n) return;
    float4 v = *(const float4*)(in + i);
    __nv_bfloat162 h01, h23, l01, l23;
    split2(v.x, v.y, h01, l01);
    split2(v.z, v.w, h23, l23);
    ((__nv_bfloat162*)(hi + i))[0] = h01;
    ((__nv_bfloat162*)(hi + i))[1] = h23;
    ((__nv_bfloat162*)(lo + i))[0] = l01;
    ((__nv_bfloat162*)(lo + i))[1] = l23;
}

// batched: W[K,N] -> [N,K] hi/lo with per-k scale; blockIdx.z selects layer.
// Vectorized write phase: 4 consecutive k per thread (8B stores).
__global__ __launch_bounds__(256)
void tsplit_kernel(const float* __restrict__ W, const float* __restrict__ g,
                   bf16* __restrict__ Th, bf16* __restrict__ Tl, int K, int N,
                   size_t wstride, size_t gstride, size_t ostride)
{
    __shared__ float t[32][33];
    __shared__ float gsm[32];
    const int l = blockIdx.z;
    W  += (size_t)l * wstride;
    if (g) g += (size_t)l * gstride;
    Th += (size_t)l * ostride;
    Tl += (size_t)l * ostride;
    const int nb = blockIdx.x * 32, kb = blockIdx.y * 32;
    const int tx = threadIdx.x, ty = threadIdx.y;
    const int tid = ty * 32 + tx;
    #pragma unroll
    for (int j = 0; j < 4; j++)
        t[ty + 8*j][tx] = W[(size_t)(kb + ty + 8*j) * N + nb + tx];
    if (tid < 32) gsm[tid] = g ? g[kb + tid] : 1.0f;
    __syncthreads();
    const int nl = tid >> 3;            // 0..31
    const int k0 = (tid & 7) * 4;       // 0,4,..28
    __nv_bfloat162 hv[2], lv[2];
    #pragma unroll
    for (int p = 0; p < 2; p++) {
        const float v0 = t[k0 + p*2 + 0][nl] * gsm[k0 + p*2 + 0];
        const float v1 = t[k0 + p*2 + 1][nl] * gsm[k0 + p*2 + 1];
        split2(v0, v1, hv[p], lv[p]);
    }
    const size_t ob = (size_t)(nb + nl) * K + kb + k0;
    *(uint2*)&Th[ob] = *(uint2*)hv;
    *(uint2*)&Tl[ob] = *(uint2*)lv;
}

// out[n] = sum_k b[k] * W[k,n], batched over blockIdx.y
__global__ void colwsum_kernel(const float* __restrict__ b, const float* __restrict__ W,
                               int K, int N, float* __restrict__ out,
                               size_t bstride, size_t wstride, size_t ostride)
{
    const int l = blockIdx.y;
    b   += (size_t)l * bstride;
    W   += (size_t)l * wstride;
    out += (size_t)l * ostride;
    const int n = blockIdx.x * 256 + threadIdx.x;
    if (n >= N) return;
    float s = 0.f;
    for (int k = 0; k < K; k++) s += b[k] * W[(size_t)k * N + n];
    out[n] = s;
}

// ---------- attention (fp32 math, bf16 hi/lo output) ----------
#define JPAD 704
#define SSTR 68
#define SMEM_ATTN ((JPAD*SSTR + 64*SSTR + 64*SSTR + 64) * 4)

__global__ __launch_bounds__(256, 1)
void attn_kernel(const float* __restrict__ Q, const float* __restrict__ KV,
                 bf16* __restrict__ Oth, bf16* __restrict__ Otl)
{
    extern __shared__ float sm[];
    float* S    = sm;
    float* Qs   = S  + JPAD*SSTR;
    float* Ts   = Qs + 64*SSTR;
    float* rinv = Ts + 64*SSTR;

    const int tid = threadIdx.x;
    const int b   = blockIdx.x / NH_;
    const int h   = blockIdx.x % NH_;

    const float* qbase = Q  + ((size_t)b * NQ_) * H_ + h * HD_;
    const float* kbase = KV + ((size_t)b * NKV) * (2*H_) + h * HD_;
    const float* vbase = kbase + H_;

    #pragma unroll
    for (int r = 0; r < 16; r++) {
        int idx = tid + r * 256;
        int l = idx >> 6, d = idx & 63;
        Qs[d*SSTR + l] = qbase[(size_t)l * H_ + d];
    }
    const int lt = tid >> 4, c4 = tid & 15;

    for (int t = 0; t < 11; t++) {
        const int jbase = t * 64;
        #pragma unroll
        for (int r = 0; r < 16; r++) {
            int idx = tid + r * 256;
            int jj = idx >> 6, d = idx & 63;
            int j = jbase + jj;
            Ts[d*SSTR + jj] = (j < NKV) ? kbase[(size_t)j * (2*H_) + d] : 0.f;
        }
        __syncthreads();
        float acc[4][4];
        #pragma unroll
        for (int i = 0; i < 4; i++)
            #pragma unroll
            for (int j = 0; j < 4; j++) acc[i][j] = 0.f;
        #pragma unroll 8
        for (int d = 0; d < 64; d++) {
            float4 q4 = *(const float4*)&Qs[d*SSTR + lt*4];
            float4 k4 = *(const float4*)&Ts[d*SSTR + c4*4];
            float qa[4] = {q4.x, q4.y, q4.z, q4.w};
            float ka[4] = {k4.x, k4.y, k4.z, k4.w};
            #pragma unroll
            for (int i = 0; i < 4; i++)
                #pragma unroll
                for (int j = 0; j < 4; j++)
                    acc[i][j] = fmaf(qa[i], ka[j], acc[i][j]);
        }
        #pragma unroll
        for (int jj = 0; jj < 4; jj++) {
            const int j = jbase + c4*4 + jj;
            float4 w;
            if (j < NKV) {
                w.x = acc[0][jj]*0.125f; w.y = acc[1][jj]*0.125f;
                w.z = acc[2][jj]*0.125f; w.w = acc[3][jj]*0.125f;
            } else { w.x = w.y = w.z = w.w = -1e30f; }
            *(float4*)&S[(size_t)j*SSTR + lt*4] = w;
        }
        __syncthreads();
    }
    {
        const int l = tid >> 2, sub = tid & 3;
        float m = -1e30f;
        for (int j = sub; j < JPAD; j += 4) m = fmaxf(m, S[j*SSTR + l]);
        m = fmaxf(m, __shfl_xor_sync(0xffffffffu, m, 1));
        m = fmaxf(m, __shfl_xor_sync(0xffffffffu, m, 2));
        float ssum = 0.f;
        for (int j = sub; j < JPAD; j += 4) {
            float e = __expf(S[j*SSTR + l] - m);
            S[j*SSTR + l] = e;
            ssum += e;
        }
        ssum += __shfl_xor_sync(0xffffffffu, ssum, 1);
        ssum += __shfl_xor_sync(0xffffffffu, ssum, 2);
        if (sub == 0) rinv[l] = 1.0f / ssum;
    }
    __syncthreads();

    float oacc[4][4];
    #pragma unroll
    for (int i = 0; i < 4; i++)
        #pragma unroll
        for (int j = 0; j < 4; j++) oacc[i][j] = 0.f;
    for (int t = 0; t < 11; t++) {
        const int jbase = t * 64;
        #pragma unroll
        for (int r = 0; r < 16; r++) {
            int idx = tid + r * 256;
            int jj = idx >> 6, d = idx & 63;
            int j = jbase + jj;
            Ts[jj*SSTR + d] = (j < NKV) ? vbase[(size_t)j * (2*H_) + d] : 0.f;
        }
        __syncthreads();
        #pragma unroll 8
        for (int jj = 0; jj < 64; jj++) {
            float4 p4 = *(const float4*)&S[(size_t)(jbase + jj)*SSTR + lt*4];
            float4 v4 = *(const float4*)&Ts[jj*SSTR + c4*4];
            float pa[4] = {p4.x, p4.y, p4.z, p4.w};
            float va[4] = {v4.x, v4.y, v4.z, v4.w};
            #pragma unroll
            for (int i = 0; i < 4; i++)
                #pragma unroll
                for (int j = 0; j < 4; j++)
                    oacc[i][j] = fmaf(pa[i], va[j], oacc[i][j]);
        }
        __syncthreads();
    }
    #pragma unroll
    for (int i = 0; i < 4; i++) {
        const int l = lt*4 + i;
        const float sc = rinv[l];
        #pragma unroll
        for (int j = 0; j < 2; j++) {
            const int d = c4*4 + j*2;
            const size_t o = ((size_t)(b*NQ_ + l)) * H_ + h*HD_ + d;
            __nv_bfloat162 hp, lp;
            split2(oacc[i][j*2] * sc, oacc[i][j*2+1] * sc, hp, lp);
            *(__nv_bfloat162*)&Oth[o] = hp;
            *(__nv_bfloat162*)&Otl[o] = lp;
        }
    }
}

// ---------- LayerNorm ----------
__device__ inline void block_reduce_2(float& s, float& s2) {
    __shared__ float red[16];
    const int lane = threadIdx.x & 31, w = threadIdx.x >> 5;
    #pragma unroll
    for (int o = 16; o > 0; o >>= 1) {
        s  += __shfl_xor_sync(0xffffffffu, s,  o);
        s2 += __shfl_xor_sync(0xffffffffu, s2, o);
    }
    if (lane == 0) { red[w] = s; red[8 + w] = s2; }
    __syncthreads();
    if (threadIdx.x < 32) {
        s  = (lane < 8) ? red[lane]     : 0.f;
        s2 = (lane < 8) ? red[8 + lane] : 0.f;
        #pragma unroll
        for (int o = 4; o > 0; o >>= 1) {
            s  += __shfl_xor_sync(0xffffffffu, s,  o);
            s2 += __shfl_xor_sync(0xffffffffu, s2, o);
        }
        if (lane == 0) { red[0] = s; red[8] = s2; }
    }
    __syncthreads();
    s = red[0]; s2 = red[8];
}

__global__ __launch_bounds__(256)
void ln_hn_kernel(const float* __restrict__ in, const float* __restrict__ temb,
                  bf16* __restrict__ outh, bf16* __restrict__ outl)
{
    const int r = blockIdx.x;
    const int b = r / N_;
    const float* x  = in + (size_t)r * H_;
    const float* te = temb + (size_t)b * H_;
    float s = 0.f, s2 = 0.f;
    for (int i = threadIdx.x*2; i < H_; i += 512) {
        float2 v = *(const float2*)(x + i);
        float2 t = *(const float2*)(te + i);
        float a0 = v.x + t.x, a1 = v.y + t.y;
        s += a0 + a1; s2 += a0*a0 + a1*a1;
    }
    block_reduce_2(s, s2);
    const float mean = s * (1.0f / H_);
    const float inv  = rsqrtf(s2 * (1.0f / H_) - mean * mean + 1e-5f);
    const size_t ob = (size_t)r * H_;
    for (int i = threadIdx.x*2; i < H_; i += 512) {
        float2 v = *(const float2*)(x + i);
        float2 t = *(const float2*)(te + i);
        float o0 = (v.x + t.x - mean) * inv;
        float o1 = (v.y + t.y - mean) * inv;
        __nv_bfloat162 hp, lp;
        split2(o0, o1, hp, lp);
        *(__nv_bfloat162*)&outh[ob + i] = hp;
        *(__nv_bfloat162*)&outl[ob + i] = lp;
    }
}

// LN(lat)*(1+sc)+sh -> lm hi/lo; emb row stride parametrized
__global__ __launch_bounds__(256)
void ln_mod_kernel(const float* __restrict__ in, const float* __restrict__ g,
                   const float* __restrict__ beta, const float* __restrict__ emb,
                   int estride, int shOff, int scOff,
                   bf16* __restrict__ o1h, bf16* __restrict__ o1l)
{
    const int r = blockIdx.x;
    const int b = r >> 6;
    const float* x  = in + (size_t)r * H_;
    const float* sh = emb + (size_t)b * estride + shOff;
    const float* sc = emb + (size_t)b * estride + scOff;
    float s = 0.f, s2 = 0.f;
    for (int i = threadIdx.x*2; i < H_; i += 512) {
        float2 v = *(const float2*)(x + i);
        s += v.x + v.y; s2 += v.x*v.x + v.y*v.y;
    }
    block_reduce_2(s, s2);
    const float mean = s * (1.0f / H_);
    const float inv  = rsqrtf(s2 * (1.0f / H_) - mean * mean + 1e-5f);
    const size_t o1b = (size_t)r * H_;
    for (int i = threadIdx.x*2; i < H_; i += 512) {
        float2 v = *(const float2*)(x + i);
        float2 gg = *(const float2*)(g + i);
        float2 bb = *(const float2*)(beta + i);
        float2 ss = *(const float2*)(sc + i);
        float2 hh = *(const float2*)(sh + i);
        float o0 = ((v.x - mean) * inv * gg.x + bb.x) * (1.0f + ss.x) + hh.x;
        float o1 = ((v.y - mean) * inv * gg.y + bb.y) * (1.0f + ss.y) + hh.y;
        __nv_bfloat162 hp, lp;
        split2(o0, o1, hp, lp);
        *(__nv_bfloat162*)&o1h[o1b + i] = hp;
        *(__nv_bfloat162*)&o1l[o1b + i] = lp;
    }
}

__global__ __launch_bounds__(256)
void ln_out_kernel(const float* __restrict__ in, const float* __restrict__ g,
                   const float* __restrict__ beta, float* __restrict__ out)
{
    const int r = blockIdx.x;
    const float* x = in + (size_t)r * O_;
    float s = 0.f, s2 = 0.f;
    for (int i = threadIdx.x; i < O_; i += 256) { float v = x[i]; s += v; s2 += v*v; }
    block_reduce_2(s, s2);
    const float mean = s * (1.0f / O_);
    const float inv  = rsqrtf(s2 * (1.0f / O_) - mean * mean + 1e-5f);
    float* o = out + (size_t)r * O_;
    for (int i = threadIdx.x; i < O_; i += 256)
        o[i] = (x[i] - mean) * inv * g[i] + beta[i];
}

// ---------- small kernels ----------
__global__ void time_proj_kernel(const float* __restrict__ t,
                                 bf16* __restrict__ tph, bf16* __restrict__ tpl)
{
    const int b = blockIdx.x, k = threadIdx.x;
    const float f = expf(-9.210340371976184f * (float)k / 160.0f);
    const float ang = t[b] * f;
    const float c = cosf(ang), s = sinf(ang);
    bf16 ch = __float2bfloat16(c), sh = __float2bfloat16(s);
    tph[b*TIN_ + k]       = ch;
    tpl[b*TIN_ + k]       = __float2bfloat16(c - __bfloat162float(ch));
    tph[b*TIN_ + 160 + k] = sh;
    tpl[b*TIN_ + 160 + k] = __float2bfloat16(s - __bfloat162float(sh));
}
__global__ void silu_split_kernel(const float* __restrict__ in,
                                  bf16* __restrict__ hi, bf16* __restrict__ lo, int n)
{
    int i = blockIdx.x * blockDim.x + threadIdx.x;
    if (i < n) {
        float v = in[i];
        float s = v / (1.0f + expf(-v));
        bf16 h = __float2bfloat16(s);
        hi[i] = h;
        lo[i] = __float2bfloat16(s - __bfloat162float(h));
    }
}
__global__ void lat_init_kernel(const float* __restrict__ l0, float* __restrict__ lat)
{
    int i = blockIdx.x * blockDim.x + threadIdx.x;
    if (i < ML * H_) lat[i] = l0[i % (NQ_ * H_)];
}
__global__ void copy_kernel(const float* __restrict__ in, float* __restrict__ out, int n)
{
    int i = blockIdx.x * blockDim.x + threadIdx.x;
    if (i < n) out[i] = in[i];
}

// ---------- host driver ----------
#define SMEM128_128 (3*(2*128*128 + 2*128*128))
#define SMEM128_256 (2*(2*128*128 + 2*256*128))
#define SMEM64      (2*(2*64*128 + 2*128*128))

static inline void run_mma(int BM, int BN, const bf16* Ah, const bf16* Al,
                           const bf16* Bh, const bf16* Bl,
                           float* C, bf16* Oh, bf16* Ol, int osplit, int rowmap,
                           int M, int N, int K, int ldc,
                           const float* bias, const float* extra, int mode)
{
    dim3 grid(N / BN, (M + BM - 1) / BM);
    if (BM == 128 && BN == 256)
        gemm_mma_kernel<128,256,2><<<grid, 256, SMEM128_256>>>(Ah, Al, Bh, Bl, C, Oh, Ol,
            osplit, rowmap, M, N, K, ldc, bias, extra, mode);
    else if (BM == 128)
        gemm_mma_kernel<128,128,3><<<grid, 256, SMEM128_128>>>(Ah, Al, Bh, Bl, C, Oh, Ol,
            osplit, rowmap, M, N, K, ldc, bias, extra, mode);
    else
        gemm_mma_kernel<64,128,2><<<grid, 256, SMEM64>>>(Ah, Al, Bh, Bl, C, Oh, Ol,
            osplit, rowmap, M, N, K, ldc, bias, extra, mode);
}
static inline void run_split(const float* in, bf16* hi, bf16* lo, size_t n)
{
    split_kernel<<<(unsigned)((n/4 + 255)/256), 256>>>(in, hi, lo, (int)n);
}
static inline void run_tsplit_b(const float* W, const float* g, bf16* Th, bf16* Tl,
                                int K, int N, size_t wstride, size_t gstride,
                                size_t ostride, int layers)
{
    tsplit_kernel<<<dim3(N/32, K/32, layers), dim3(32, 8)>>>(W, g, Th, Tl, K, N,
                                                             wstride, gstride, ostride);
}

#define GSA(p, sym) cudaGetSymbolAddress((void**)&(p), sym)

extern "C" void kernel_launch(void* const* d_in, const int* in_sizes, int n_in,
                              void* d_out, int out_size)
{
    const float* x          = (const float*)d_in[0];
    const float* timestep   = (const float*)d_in[1];
    const float* latents0   = (const float*)d_in[2];
    const float* proj_in_W  = (const float*)d_in[3];
    const float* proj_in_b  = (const float*)d_in[4];
    const float* te1_W      = (const float*)d_in[5];
    const float* te1_b      = (const float*)d_in[6];
    const float* te2_W      = (const float*)d_in[7];
    const float* te2_b      = (const float*)d_in[8];
    const float* ln0_g      = (const float*)d_in[9];
    const float* ln0_b      = (const float*)d_in[10];
    const float* ln1_g      = (const float*)d_in[11];
    const float* ln1_b      = (const float*)d_in[12];
    const float* Wq         = (const float*)d_in[13];
    const float* Wkv        = (const float*)d_in[14];
    const float* Wo         = (const float*)d_in[15];
    const float* ada_W      = (const float*)d_in[16];
    const float* ada_b      = (const float*)d_in[17];
    const float* lnada_g    = (const float*)d_in[18];
    const float* lnada_b    = (const float*)d_in[19];
    const float* Wff1       = (const float*)d_in[20];
    const float* Wff2       = (const float*)d_in[21];
    const float* proj_out_W = (const float*)d_in[22];
    const float* proj_out_b = (const float*)d_in[23];
    const float* norm_out_g = (const float*)d_in[24];
    const float* norm_out_b = (const float*)d_in[25];

    float *temb, *h, *kv, *lat, *q, *emb, *obuf, *bkv;
    GSA(temb, g_temb); GSA(h, g_h); GSA(kv, g_kv); GSA(lat, g_lat);
    GSA(q, g_q); GSA(emb, g_emb); GSA(obuf, g_obuf); GSA(bkv, g_bkv);

    bf16 *wpin_h,*wpin_l,*wte1_h,*wte1_l,*wte2_h,*wte2_l,*wq_h,*wq_l,*wkv_h,*wkv_l,
         *wkvS_h,*wkvS_l,*wo_h,*wo_l,*wada_h,*wada_l,*wff1_h,*wff1_l,*wff2_h,*wff2_l,
         *wpo_h,*wpo_l;
    GSA(wpin_h, g_wpin_h); GSA(wpin_l, g_wpin_l);
    GSA(wte1_h, g_wte1_h); GSA(wte1_l, g_wte1_l);
    GSA(wte2_h, g_wte2_h); GSA(wte2_l, g_wte2_l);
    GSA(wq_h, g_wq_h);     GSA(wq_l, g_wq_l);
    GSA(wkv_h, g_wkv_h);   GSA(wkv_l, g_wkv_l);
    GSA(wkvS_h, g_wkvS_h); GSA(wkvS_l, g_wkvS_l);
    GSA(wo_h, g_wo_h);     GSA(wo_l, g_wo_l);
    GSA(wada_h, g_wada_h); GSA(wada_l, g_wada_l);
    GSA(wff1_h, g_wff1_h); GSA(wff1_l, g_wff1_l);
    GSA(wff2_h, g_wff2_h); GSA(wff2_l, g_wff2_l);
    GSA(wpo_h, g_wpo_h);   GSA(wpo_l, g_wpo_l);

    bf16 *tph,*tpl,*t1h,*t1l,*tsh,*tsl,*xh,*xl,*hnh,*hnl,*lmh,*lml,*atth,*attl,*ffh,*ffl;
    GSA(tph, g_tp_h);   GSA(tpl, g_tp_l);
    GSA(t1h, g_t1_h);   GSA(t1l, g_t1_l);
    GSA(tsh, g_ts_h);   GSA(tsl, g_ts_l);
    GSA(xh, g_x_h);     GSA(xl, g_x_l);
    GSA(hnh, g_hn_h);   GSA(hnl, g_hn_l);
    GSA(lmh, g_lm_h);   GSA(lml, g_lm_l);
    GSA(atth, g_att_h); GSA(attl, g_att_l);
    GSA(ffh, g_ff_h);   GSA(ffl, g_ff_l);

    cudaFuncSetAttribute(attn_kernel, cudaFuncAttributeMaxDynamicSharedMemorySize, SMEM_ATTN);
    cudaFuncSetAttribute(gemm_mma_kernel<128,128,3>, cudaFuncAttributeMaxDynamicSharedMemorySize, SMEM128_128);
    cudaFuncSetAttribute(gemm_mma_kernel<128,256,2>, cudaFuncAttributeMaxDynamicSharedMemorySize, SMEM128_256);
    cudaFuncSetAttribute(gemm_mma_kernel<64,128,2>,  cudaFuncAttributeMaxDynamicSharedMemorySize, SMEM64);

    // --- launch order: index 3 = BN256 proj_in GEMM (ncu capture target) ---
    run_tsplit_b(proj_in_W, nullptr, wpin_h, wpin_l, E_, H_, 0, 0, 0, 1);   // 0
    run_split(x, xh, xl, (size_t)MH*E_);                                    // 1
    time_proj_kernel<<<B_, 160>>>(timestep, tph, tpl);                      // 2
    run_mma(128, 256, xh, xl, wpin_h, wpin_l, h, nullptr, nullptr, 0, 0,    // 3 <- profiled
            MH, H_, E_, H_, proj_in_b, nullptr, MODE_BIAS);

    // time embedding
    run_tsplit_b(te1_W, nullptr, wte1_h, wte1_l, TIN_, H_, 0, 0, 0, 1);
    run_tsplit_b(te2_W, nullptr, wte2_h, wte2_l, H_, H_, 0, 0, 0, 1);
    run_mma(64, 128, tph, tpl, wte1_h, wte1_l, nullptr, t1h, t1l, 1, 0,
            B_, H_, TIN_, H_, te1_b, nullptr, MODE_BIAS_SILU);
    run_mma(64, 128, t1h, t1l, wte2_h, wte2_l, temb, nullptr, nullptr, 0, 0,
            B_, H_, H_, H_, te2_b, nullptr, MODE_BIAS);
    silu_split_kernel<<<(B_*H_ + 255)/256, 256>>>(temb, tsh, tsl, B_*H_);

    // hn = normalize(h + temb) once, hi/lo
    ln_hn_kernel<<<MH, 256>>>(h, temb, hnh, hnl);
    lat_init_kernel<<<(ML*H_ + 255)/256, 256>>>(latents0, lat);

    // per-layer weight prep (batched over layers)
    run_tsplit_b(Wq,    nullptr, wq_h,   wq_l,   H_,  H_,   (size_t)H_*H_,    0,  (size_t)H_*H_,    DL);
    run_tsplit_b(Wkv,   nullptr, wkv_h,  wkv_l,  H_,  2*H_, (size_t)H_*2*H_,  0,  (size_t)2*H_*H_,  DL);
    run_tsplit_b(Wkv,   ln0_g,   wkvS_h, wkvS_l, H_,  2*H_, (size_t)H_*2*H_,  H_, (size_t)2*H_*H_,  DL);
    colwsum_kernel<<<dim3((2*H_+255)/256, DL), 256>>>(ln0_b, Wkv, H_, 2*H_, bkv,
                                                      H_, (size_t)H_*2*H_, 2*H_);
    run_tsplit_b(Wo,    nullptr, wo_h,   wo_l,   H_,  H_,   (size_t)H_*H_,    0,  (size_t)H_*H_,    DL);
    run_tsplit_b(ada_W, nullptr, wada_h, wada_l, H_,  4*H_, (size_t)H_*4*H_,  0,  (size_t)4*H_*H_,  DL);
    run_tsplit_b(Wff1,  nullptr, wff1_h, wff1_l, H_,  FF_,  (size_t)H_*FF_,   0,  (size_t)FF_*H_,   DL);
    run_tsplit_b(Wff2,  nullptr, wff2_h, wff2_l, FF_, H_,   (size_t)FF_*H_,   0,  (size_t)H_*FF_,   DL);
    run_tsplit_b(proj_out_W, nullptr, wpo_h, wpo_l, H_, O_, 0, 0, 0, 1);

    // ada mega-GEMM: all 4 layers at once. emb layout [B][DL*4H]; ada_b is
    // [DL][4H] = 20480 contiguous floats, wada [DL*4H][H] contiguous rows.
    run_mma(64, 128, tsh, tsl, wada_h, wada_l, emb, nullptr, nullptr, 0, 0,
            B_, DL*4*H_, H_, DL*4*H_, ada_b, nullptr, MODE_BIAS);

    for (int i = 0; i < DL; i++) {
        const float* embL = emb + (size_t)i * 4 * H_;

        ln_mod_kernel<<<ML, 256>>>(lat, ln1_g + i*H_, ln1_b + i*H_, embL,
                                   DL*4*H_, 0, H_, lmh, lml);

        run_mma(64, 128, lmh, lml, wq_h + (size_t)i*H_*H_, wq_l + (size_t)i*H_*H_,
                q, nullptr, nullptr, 0, 0, ML, H_, H_, H_, nullptr, nullptr, MODE_NONE);
        run_mma(128, 256, hnh, hnl, wkvS_h + (size_t)i*2*H_*H_, wkvS_l + (size_t)i*2*H_*H_,
                kv, nullptr, nullptr, 0, 2, MH, 2*H_, H_, 2*H_,
                bkv + i*2*H_, nullptr, MODE_BIAS);
        run_mma(64, 128, lmh, lml, wkv_h + (size_t)i*2*H_*H_, wkv_l + (size_t)i*2*H_*H_,
                kv, nullptr, nullptr, 0, 1, ML, 2*H_, H_, 2*H_,
                nullptr, nullptr, MODE_NONE);

        attn_kernel<<<B_*NH_, 256, SMEM_ATTN>>>(q, kv, atth, attl);

        run_mma(64, 128, atth, attl, wo_h + (size_t)i*H_*H_, wo_l + (size_t)i*H_*H_,
                lat, nullptr, nullptr, 0, 0, ML, H_, H_, H_, nullptr, lat, MODE_RES);

        ln_mod_kernel<<<ML, 256>>>(lat, lnada_g + i*H_, lnada_b + i*H_, embL,
                                   DL*4*H_, 2*H_, 3*H_, lmh, lml);
        run_mma(64, 128, lmh, lml, wff1_h + (size_t)i*FF_*H_, wff1_l + (size_t)i*FF_*H_,
                nullptr, ffh, ffl, 1, 0, ML, FF_, H_, FF_, nullptr, nullptr, MODE_GELU);
        run_mma(64, 128, ffh, ffl, wff2_h + (size_t)i*H_*FF_, wff2_l + (size_t)i*H_*FF_,
                lat, nullptr, nullptr, 0, 0, ML, H_, FF_, H_, nullptr, lat, MODE_RES);
    }

    run_split(lat, lmh, lml, (size_t)ML*H_);
    run_mma(64, 128, lmh, lml, wpo_h, wpo_l, obuf, nullptr, nullptr, 0, 0,
            ML, O_, H_, O_, proj_out_b, nullptr, MODE_BIAS);
    ln_out_kernel<<<ML, 256>>>(obuf, norm_out_g, norm_out_b, (float*)d_out);

    const int out0 = ML * O_;
    if (out_size >= out0 + B_*H_)
        copy_kernel<<<(B_*H_ + 255)/256, 256>>>(temb, (float*)d_out + out0, B_*H_);
}